// round 4
// baseline (speedup 1.0000x reference)
#include <cuda_runtime.h>

// PairwiseScore — fp32 baseline with algebraic decomposition + packed f32x2 FMA.
//
// pairs@W1 = i_g@W1a + j_g@W1b + (i_g*j_g)@W1c + phi@W1d
//   - AB[n]  : per-mention precompute of g_i[n]@W1a (cols 0..149) and g_i[n]@W1b (cols 160..309)
//   - Dt/Gt/St: tiny phi lookup tables (b1 folded into Dt)
//   - main kernel: bilinear GEMM per 64-pair tile + fused 2-layer MLP epilogue.

typedef unsigned long long ull;

#define GI   1220
#define HID  150
#define NMAX 50000
#define CPAD 160      // padded hidden width (cols 150..159 are zero)
#define ABS  320      // AB row stride in floats (A part @0, B part @160)
#define KC   16       // K-chunk

// -------- device scratch (no allocations allowed) --------
__device__ float d_AB[(size_t)NMAX * ABS];   // 64 MB
__device__ float d_Wab[GI * ABS];            // packed [W1a | pad | W1b | pad]
__device__ float d_Wc[GI * CPAD];            // W1c zero-padded to 160 cols
__device__ float d_Dt[9 * CPAD];             // dist table (+b1)
__device__ float d_Gt[8 * CPAD];             // genre table
__device__ float d_St[3 * CPAD];             // speaker table

// -------- packed f32x2 helpers --------
__device__ __forceinline__ void fma2(ull &d, ull a, ull b) {
    asm("fma.rn.f32x2 %0, %1, %2, %0;" : "+l"(d) : "l"(a), "l"(b));
}
__device__ __forceinline__ ull bcast2(float x) {
    ull r; asm("mov.b64 %0, {%1, %1};" : "=l"(r) : "f"(x)); return r;
}
__device__ __forceinline__ ull pk(float x, float y) {
    ull r; asm("mov.b64 %0, {%1, %2};" : "=l"(r) : "f"(x), "f"(y)); return r;
}
__device__ __forceinline__ float2 unpk(ull v) {
    float2 r; asm("mov.b64 {%0, %1}, %2;" : "=f"(r.x), "=f"(r.y) : "l"(v)); return r;
}

// ===================== weight prep =====================

__global__ void prep_weights(const float* __restrict__ W1) {
    int k = blockIdx.x;      // 0..GI-1
    int c = threadIdx.x;     // 0..319
    float v = 0.f;
    if (c < HID)                       v = W1[k * HID + c];
    else if (c >= CPAD && c < CPAD+HID) v = W1[(GI + k) * HID + (c - CPAD)];
    d_Wab[k * ABS + c] = v;
    if (c < CPAD)
        d_Wc[k * CPAD + c] = (c < HID) ? W1[(2 * GI + k) * HID + c] : 0.f;
}

__global__ void prep_tabs(const float* __restrict__ de, const float* __restrict__ ge,
                          const float* __restrict__ se, const float* __restrict__ W1,
                          const float* __restrict__ b1) {
    int c = threadIdx.x;     // 0..159
    for (int d = 0; d < 9; ++d) {
        float v = 0.f;
        if (c < HID) {
            v = b1[c];
            for (int t = 0; t < 20; ++t) v += de[d*20 + t] * W1[(3*GI + t) * HID + c];
        }
        d_Dt[d * CPAD + c] = v;
    }
    for (int g = 0; g < 8; ++g) {
        float v = 0.f;
        if (c < HID)
            for (int t = 0; t < 20; ++t) v += ge[g*20 + t] * W1[(3*GI + 20 + t) * HID + c];
        d_Gt[g * CPAD + c] = v;
    }
    for (int s = 0; s < 3; ++s) {
        float v = 0.f;
        if (c < HID)
            for (int t = 0; t < 20; ++t) v += se[s*20 + t] * W1[(3*GI + 40 + t) * HID + c];
        d_St[s * CPAD + c] = v;
    }
}

// ===================== AB precompute GEMM: [64 x 1220] @ [1220 x 320] =====================

__global__ __launch_bounds__(256) void gemm_ab(const float* __restrict__ g, int N) {
    __shared__ ull   Ws[KC * 160];   // 16 x 160 colpairs = 20 KB
    __shared__ float Qs[KC * 65];    // padded stride 65

    int t  = threadIdx.x;
    int tx = t & 15, ty = t >> 4;    // ty also serves as producer kk
    int ty4 = ty * 4;
    int n0 = blockIdx.x * 64;

    int pp = t >> 2, q = t & 3;
    int nrow = n0 + pp; if (nrow >= N) nrow = N - 1;
    const float* grow = g + (size_t)nrow * GI;

    ull acc[4][10];
    #pragma unroll
    for (int j = 0; j < 4; ++j)
        #pragma unroll
        for (int c = 0; c < 10; ++c) acc[j][c] = 0ull;

    const ull* Wab64 = (const ull*)d_Wab;   // row stride 160 colpairs

    for (int k0 = 0; k0 < GI; k0 += KC) {
        __syncthreads();
        // stage W chunk [16 x 320]
        {
            int k = k0 + ty;
            #pragma unroll
            for (int i = 0; i < 10; ++i) {
                ull w = 0ull;
                if (k < GI) w = Wab64[(size_t)k * 160 + tx + 16*i];
                Ws[ty * 160 + tx + 16*i] = w;
            }
        }
        // stage Q chunk [16 x 64] (transposed, stride 65)
        {
            int kb = k0 + 4*q;
            float4 v;
            if (kb + 3 < GI) v = *(const float4*)(grow + kb);
            else {
                v.x = (kb+0 < GI) ? grow[kb+0] : 0.f;
                v.y = (kb+1 < GI) ? grow[kb+1] : 0.f;
                v.z = (kb+2 < GI) ? grow[kb+2] : 0.f;
                v.w = (kb+3 < GI) ? grow[kb+3] : 0.f;
            }
            Qs[(4*q+0)*65 + pp] = v.x;
            Qs[(4*q+1)*65 + pp] = v.y;
            Qs[(4*q+2)*65 + pp] = v.z;
            Qs[(4*q+3)*65 + pp] = v.w;
        }
        __syncthreads();
        #pragma unroll
        for (int kk = 0; kk < KC; ++kk) {
            ull qq[4];
            #pragma unroll
            for (int j = 0; j < 4; ++j) qq[j] = bcast2(Qs[kk*65 + ty4 + j]);
            #pragma unroll
            for (int c = 0; c < 10; ++c) {
                ull w = Ws[kk*160 + tx + 16*c];
                #pragma unroll
                for (int j = 0; j < 4; ++j) fma2(acc[j][c], qq[j], w);
            }
        }
    }
    __syncthreads();

    ull* AB64 = (ull*)d_AB;   // row stride 160 colpairs
    #pragma unroll
    for (int j = 0; j < 4; ++j) {
        int n = n0 + ty4 + j;
        if (n < N) {
            #pragma unroll
            for (int c = 0; c < 10; ++c)
                AB64[(size_t)n * 160 + tx + 16*c] = acc[j][c];
        }
    }
}

// ===================== main: bilinear GEMM + fused MLP =====================

__global__ __launch_bounds__(256) void pair_main(
    const float* __restrict__ g,  const float* __restrict__ ms,
    const float* __restrict__ W2, const float* __restrict__ b2,
    const float* __restrict__ W3, const float* __restrict__ b3,
    const int* __restrict__ mid,  const int* __restrict__ aid,
    const int* __restrict__ did,  const int* __restrict__ gid,
    const int* __restrict__ sid,
    float* __restrict__ out, int P)
{
    extern __shared__ unsigned char smem_raw[];
    ull*   Ws   = (ull*)smem_raw;                                  // 16*80 ull = 10240 B
    float* QH   = (float*)(smem_raw + 10240);                      // Qs[16*65] then h1s[64*160]
    int*   sm_m = (int*)(smem_raw + 10240 + 64*CPAD*4);
    int*   sm_a = sm_m + 64;
    int*   sm_d = sm_a + 64;
    int*   sm_g = sm_d + 64;
    int*   sm_s = sm_g + 64;
    float* w3s  = (float*)(sm_s + 64);                             // [160]

    int t  = threadIdx.x;
    int tx = t & 15, ty = t >> 4;
    int ty4 = ty * 4;
    int p0 = blockIdx.x * 64;

    if (t < 64) {
        int p = p0 + t;
        int m = 0, a = 0, dd = 0, gg = 0, ss = 0;
        if (p < P) { m = mid[p]; a = aid[p]; dd = did[p]; gg = gid[p]; ss = sid[p]; }
        sm_m[t] = m; sm_a[t] = a; sm_d[t] = dd; sm_g[t] = gg; sm_s[t] = ss;
    }
    if (t < CPAD) w3s[t] = (t < HID) ? W3[t] : 0.f;
    __syncthreads();

    int pp = t >> 2, q = t & 3;
    const float* irow = g + (size_t)sm_m[pp] * GI;
    const float* jrow = g + (size_t)sm_a[pp] * GI;

    // ---- layer 1: bilinear (i*j) @ W1c over K=1220 ----
    ull acc[4][5];
    #pragma unroll
    for (int j = 0; j < 4; ++j)
        #pragma unroll
        for (int c = 0; c < 5; ++c) acc[j][c] = 0ull;

    const ull* Wc64 = (const ull*)d_Wc;   // row stride 80 colpairs

    for (int k0 = 0; k0 < GI; k0 += KC) {
        __syncthreads();
        {
            int k = k0 + ty;
            #pragma unroll
            for (int i = 0; i < 5; ++i) {
                ull w = 0ull;
                if (k < GI) w = Wc64[(size_t)k * 80 + tx + 16*i];
                Ws[ty * 80 + tx + 16*i] = w;
            }
        }
        {
            int kb = k0 + 4*q;
            float4 x, y;
            if (kb + 3 < GI) {
                x = *(const float4*)(irow + kb);
                y = *(const float4*)(jrow + kb);
            } else {
                x.x = (kb+0 < GI) ? irow[kb+0] : 0.f;  y.x = (kb+0 < GI) ? jrow[kb+0] : 0.f;
                x.y = (kb+1 < GI) ? irow[kb+1] : 0.f;  y.y = (kb+1 < GI) ? jrow[kb+1] : 0.f;
                x.z = (kb+2 < GI) ? irow[kb+2] : 0.f;  y.z = (kb+2 < GI) ? jrow[kb+2] : 0.f;
                x.w = (kb+3 < GI) ? irow[kb+3] : 0.f;  y.w = (kb+3 < GI) ? jrow[kb+3] : 0.f;
            }
            QH[(4*q+0)*65 + pp] = x.x * y.x;
            QH[(4*q+1)*65 + pp] = x.y * y.y;
            QH[(4*q+2)*65 + pp] = x.z * y.z;
            QH[(4*q+3)*65 + pp] = x.w * y.w;
        }
        __syncthreads();
        #pragma unroll
        for (int kk = 0; kk < KC; ++kk) {
            ull qq[4];
            #pragma unroll
            for (int j = 0; j < 4; ++j) qq[j] = bcast2(QH[kk*65 + ty4 + j]);
            #pragma unroll
            for (int c = 0; c < 5; ++c) {
                ull w = Ws[kk*80 + tx + 16*c];
                #pragma unroll
                for (int j = 0; j < 4; ++j) fma2(acc[j][c], qq[j], w);
            }
        }
    }
    __syncthreads();

    // ---- epilogue 1: h1 = relu(bilinear + AB[m] + AB[a] + Dt + Gt + St) -> SMEM ----
    {
        const float2* AB2 = (const float2*)d_AB;   // row stride 160 float2
        const float2* Dt2 = (const float2*)d_Dt;   // row stride 80 float2
        const float2* Gt2 = (const float2*)d_Gt;
        const float2* St2 = (const float2*)d_St;
        #pragma unroll
        for (int j = 0; j < 4; ++j) {
            int r = ty4 + j;
            const float2* am = AB2 + (size_t)sm_m[r] * 160;
            const float2* bm = AB2 + (size_t)sm_a[r] * 160 + 80;
            const float2* dp = Dt2 + sm_d[r] * 80;
            const float2* gp = Gt2 + sm_g[r] * 80;
            const float2* sp = St2 + sm_s[r] * 80;
            #pragma unroll
            for (int c = 0; c < 5; ++c) {
                int cp = tx + 16*c;
                float2 v  = unpk(acc[j][c]);
                float2 t1 = am[cp], t2 = bm[cp], t3 = dp[cp], t4 = gp[cp], t5 = sp[cp];
                v.x = fmaxf(v.x + t1.x + t2.x + t3.x + t4.x + t5.x, 0.f);
                v.y = fmaxf(v.y + t1.y + t2.y + t3.y + t4.y + t5.y, 0.f);
                *(float2*)(QH + r * CPAD + 2*cp) = v;
            }
        }
    }

    // ---- layer 2: h2pre = h1 @ W2 ----
    ull acc2[4][5];
    #pragma unroll
    for (int j = 0; j < 4; ++j)
        #pragma unroll
        for (int c = 0; c < 5; ++c) acc2[j][c] = 0ull;

    for (int k0 = 0; k0 < CPAD; k0 += KC) {   // 10 chunks (k>=150 is zero-padded)
        __syncthreads();
        {
            int k = k0 + ty;
            #pragma unroll
            for (int i = 0; i < 5; ++i) {
                int cp = tx + 16*i, c0 = 2*cp;
                ull w = 0ull;
                if (k < HID) {
                    float lo = (c0   < HID) ? W2[k*HID + c0    ] : 0.f;
                    float hi = (c0+1 < HID) ? W2[k*HID + c0 + 1] : 0.f;
                    w = pk(lo, hi);
                }
                Ws[ty * 80 + cp] = w;
            }
        }
        __syncthreads();
        #pragma unroll
        for (int kk = 0; kk < KC; ++kk) {
            ull qq[4];
            #pragma unroll
            for (int j = 0; j < 4; ++j) qq[j] = bcast2(QH[(ty4+j)*CPAD + k0 + kk]);
            #pragma unroll
            for (int c = 0; c < 5; ++c) {
                ull w = Ws[kk*80 + tx + 16*c];
                #pragma unroll
                for (int j = 0; j < 4; ++j) fma2(acc2[j][c], qq[j], w);
            }
        }
    }

    // ---- epilogue 2: relu(h2pre + b2) @ W3 + b3 + ms[m] + ms[a] ----
    float b3v = b3[0];
    float part[4] = {0.f, 0.f, 0.f, 0.f};
    #pragma unroll
    for (int c = 0; c < 5; ++c) {
        int c0 = 2 * (tx + 16*c);
        float w3a = w3s[c0], w3b = w3s[c0 + 1];
        float b2a = (c0   < HID) ? b2[c0    ] : 0.f;
        float b2b = (c0+1 < HID) ? b2[c0 + 1] : 0.f;
        #pragma unroll
        for (int j = 0; j < 4; ++j) {
            float2 v = unpk(acc2[j][c]);
            part[j] += fmaxf(v.x + b2a, 0.f) * w3a + fmaxf(v.y + b2b, 0.f) * w3b;
        }
    }
    #pragma unroll
    for (int j = 0; j < 4; ++j) {
        #pragma unroll
        for (int off = 8; off > 0; off >>= 1)
            part[j] += __shfl_xor_sync(0xffffffffu, part[j], off);
    }
    if (tx == 0) {
        #pragma unroll
        for (int j = 0; j < 4; ++j) {
            int p = p0 + ty4 + j;
            if (p < P)
                out[p] = part[j] + b3v + ms[sm_m[ty4 + j]] + ms[sm_a[ty4 + j]];
        }
    }
}

// ===================== launch =====================

extern "C" void kernel_launch(void* const* d_in, const int* in_sizes, int n_in,
                              void* d_out, int out_size)
{
    const float* g_i = (const float*)d_in[0];
    const float* ms  = (const float*)d_in[1];
    const float* de  = (const float*)d_in[2];
    const float* ge  = (const float*)d_in[3];
    const float* se  = (const float*)d_in[4];
    const float* W1  = (const float*)d_in[5];
    const float* b1  = (const float*)d_in[6];
    const float* W2  = (const float*)d_in[7];
    const float* b2  = (const float*)d_in[8];
    const float* W3  = (const float*)d_in[9];
    const float* b3  = (const float*)d_in[10];
    const int*   mid = (const int*)d_in[11];
    const int*   aid = (const int*)d_in[12];
    const int*   did = (const int*)d_in[13];
    const int*   gid = (const int*)d_in[14];
    const int*   sid = (const int*)d_in[15];

    int N = in_sizes[0] / GI;
    if (N > NMAX) N = NMAX;
    int P = in_sizes[11];
    float* out = (float*)d_out;

    prep_weights<<<GI, 320>>>(W1);
    prep_tabs<<<1, CPAD>>>(de, ge, se, W1, b1);
    gemm_ab<<<(N + 63) / 64, 256>>>(g_i, N);

    int smem = 10240 + 64*CPAD*4 + 5*64*4 + CPAD*4;   // 53120 B
    cudaFuncSetAttribute(pair_main, cudaFuncAttributeMaxDynamicSharedMemorySize, smem);
    pair_main<<<(P + 63) / 64, 256, smem>>>(g_i, ms, W2, b2, W3, b3,
                                            mid, aid, did, gid, sid, out, P);
}

// round 6
// speedup vs baseline: 1.5027x; 1.5027x over previous
#include <cuda_runtime.h>
#include <cuda_bf16.h>
#include <cstdint>

typedef unsigned long long ull;

#define GI   1220
#define HID  150
#define NMAX 50000
#define PMAX 100000
#define CPAD 160
#define ABS  320
#define NCH  20        // K chunks of 64 (padded to 1280)

// ===================== device scratch (no allocations allowed) =====================
__device__ float d_AB[(size_t)NMAX * ABS];     // 64 MB: per-mention  g@[W1a|W1b]
__device__ float d_bil[(size_t)PMAX * CPAD];   // 64 MB: per-pair bilinear (i*j)@W1c
__device__ uint4 d_WcTh[NCH * 20480 / 16];     // W1c^T bf16-hi tiles [160 x 64] per chunk
__device__ uint4 d_WcTl[NCH * 20480 / 16];     // bf16-lo
__device__ uint4 d_WabTh[NCH * 40960 / 16];    // [W1a|pad|W1b|pad]^T tiles [320 x 64] per chunk
__device__ uint4 d_WabTl[NCH * 40960 / 16];
__device__ float d_Dt[9 * CPAD];               // dist table (+b1)
__device__ float d_Gt[8 * CPAD];
__device__ float d_St[3 * CPAD];

// ===================== helpers =====================

// mma.sync (sm_80 baseline feature -> compiles for plain sm_103 target, HMMA on Blackwell)
__device__ __forceinline__ void mma16816(float c[4],
                                         uint32_t a0, uint32_t a1, uint32_t a2, uint32_t a3,
                                         uint32_t b0, uint32_t b1) {
    asm volatile(
        "mma.sync.aligned.m16n8k16.row.col.f32.bf16.bf16.f32 "
        "{%0,%1,%2,%3}, {%4,%5,%6,%7}, {%8,%9}, {%0,%1,%2,%3};"
        : "+f"(c[0]), "+f"(c[1]), "+f"(c[2]), "+f"(c[3])
        : "r"(a0), "r"(a1), "r"(a2), "r"(a3), "r"(b0), "r"(b1));
}

union BPack { __nv_bfloat16 v[4]; ull u; };
__device__ __forceinline__ void split4(float4 x, ull& hu, ull& lu) {
    BPack H, L;
    float p[4] = {x.x, x.y, x.z, x.w};
    #pragma unroll
    for (int i = 0; i < 4; ++i) {
        __nv_bfloat16 h = __float2bfloat16(p[i]);
        H.v[i] = h;
        L.v[i] = __float2bfloat16(p[i] - __bfloat162float(h));
    }
    hu = H.u; lu = L.u;
}

// packed f32x2 helpers (scalar tail)
__device__ __forceinline__ void fma2(ull& d, ull a, ull b) {
    asm("fma.rn.f32x2 %0, %1, %2, %0;" : "+l"(d) : "l"(a), "l"(b));
}
__device__ __forceinline__ ull bcast2(float x) {
    ull r; asm("mov.b64 %0, {%1, %1};" : "=l"(r) : "f"(x)); return r;
}
__device__ __forceinline__ ull pk(float x, float y) {
    ull r; asm("mov.b64 %0, {%1, %2};" : "=l"(r) : "f"(x), "f"(y)); return r;
}
__device__ __forceinline__ float2 unpk(ull v) {
    float2 r; asm("mov.b64 {%0, %1}, %2;" : "=f"(r.x), "=f"(r.y) : "l"(v)); return r;
}

// ===================== weight prep: transpose + bf16 split (plain [n][64] tiles) =====================

__global__ void prep_wtiles(const float* __restrict__ W1) {
    int q = blockIdx.x;   // K-chunk
    int t = threadIdx.x;
    __nv_bfloat16* ch = (__nv_bfloat16*)d_WcTh;
    __nv_bfloat16* cl = (__nv_bfloat16*)d_WcTl;
    for (int idx = t; idx < 160 * 64; idx += 256) {
        int n = idx >> 6, kk = idx & 63, k = q * 64 + kk;
        float v = (k < GI && n < HID) ? W1[(2 * GI + k) * HID + n] : 0.f;
        __nv_bfloat16 h = __float2bfloat16(v);
        float l = v - __bfloat162float(h);
        size_t e = (size_t)q * 10240 + (size_t)n * 64 + kk;
        ch[e] = h; cl[e] = __float2bfloat16(l);
    }
    __nv_bfloat16* ah = (__nv_bfloat16*)d_WabTh;
    __nv_bfloat16* al = (__nv_bfloat16*)d_WabTl;
    for (int idx = t; idx < 320 * 64; idx += 256) {
        int n = idx >> 6, kk = idx & 63, k = q * 64 + kk;
        float v = 0.f;
        if (k < GI) {
            if (n < HID)                        v = W1[k * HID + n];
            else if (n >= 160 && n < 160 + HID) v = W1[(GI + k) * HID + (n - 160)];
        }
        __nv_bfloat16 h = __float2bfloat16(v);
        float l = v - __bfloat162float(h);
        size_t e = (size_t)q * 20480 + (size_t)n * 64 + kk;
        ah[e] = h; al[e] = __float2bfloat16(l);
    }
}

__global__ void prep_tabs(const float* __restrict__ de, const float* __restrict__ ge,
                          const float* __restrict__ se, const float* __restrict__ W1,
                          const float* __restrict__ b1) {
    int c = threadIdx.x;     // 0..159
    for (int d = 0; d < 9; ++d) {
        float v = 0.f;
        if (c < HID) {
            v = b1[c];
            for (int t = 0; t < 20; ++t) v += de[d*20 + t] * W1[(3*GI + t) * HID + c];
        }
        d_Dt[d * CPAD + c] = v;
    }
    for (int g = 0; g < 8; ++g) {
        float v = 0.f;
        if (c < HID)
            for (int t = 0; t < 20; ++t) v += ge[g*20 + t] * W1[(3*GI + 20 + t) * HID + c];
        d_Gt[g * CPAD + c] = v;
    }
    for (int s = 0; s < 3; ++s) {
        float v = 0.f;
        if (c < HID)
            for (int t = 0; t < 20; ++t) v += se[s*20 + t] * W1[(3*GI + 40 + t) * HID + c];
        d_St[s * CPAD + c] = v;
    }
}

// SMEM row stride for bf16 tiles: 72 bf16 = 144 bytes -> conflict-free frag loads
#define RS 144

// ===================== T1: AB = g @ [W1a|W1b]  (64 rows x 320 cols / CTA, mma) =====================
// smem: Ah @0 (64*144=9216), Al @9216, Bh @18432 (320*144=46080), Bl @64512 ; total 110592
#define T1_AH 0
#define T1_AL 9216
#define T1_BH 18432
#define T1_BL 64512
#define T1_SMEM 110592

__global__ __launch_bounds__(256) void gemm_ab_tc(const float* __restrict__ g, int N) {
    extern __shared__ unsigned char sm[];
    unsigned char* Ah = sm + T1_AH;
    unsigned char* Al = sm + T1_AL;
    unsigned char* Bh = sm + T1_BH;
    unsigned char* Bl = sm + T1_BL;

    int t = threadIdx.x, wid = t >> 5, lane = t & 31;
    int n0 = blockIdx.x * 64;
    int g4 = lane >> 2, tq = lane & 3;
    int wr = wid >> 2, wc = wid & 3;              // 2 x 4 warp grid

    int r = t >> 2, qd = t & 3;                   // A staging: 64 rows, 16 cols/thread
    int row = n0 + r; if (row >= N) row = N - 1;
    const float4* grow = (const float4*)(g + (size_t)row * GI);

    float acc[2][10][4];
    #pragma unroll
    for (int mi = 0; mi < 2; ++mi)
        #pragma unroll
        for (int f = 0; f < 10; ++f)
            #pragma unroll
            for (int e = 0; e < 4; ++e) acc[mi][f][e] = 0.f;

    for (int q = 0; q < NCH; ++q) {
        int k0 = q * 64;
        __syncthreads();
        // B copy: pre-split tiles [320 x 64] bf16 -> stride-144 smem
        {
            const uint4* sH = d_WabTh + (size_t)q * 2560;
            const uint4* sL = d_WabTl + (size_t)q * 2560;
            #pragma unroll
            for (int i = 0; i < 10; ++i) {
                int idx = t + 256 * i;
                int n = idx >> 3, ii = idx & 7;
                *(uint4*)(Bh + n * RS + 16 * ii) = sH[idx];
                *(uint4*)(Bl + n * RS + 16 * ii) = sL[idx];
            }
        }
        // A stage: split g slice
        #pragma unroll
        for (int gi2 = 0; gi2 < 4; ++gi2) {
            int kb = k0 + 16 * qd + 4 * gi2;
            float4 x = (kb < GI) ? grow[kb >> 2] : make_float4(0.f, 0.f, 0.f, 0.f);
            ull hu, lu; split4(x, hu, lu);
            uint32_t off = (uint32_t)(r * RS + (16 * qd + 4 * gi2) * 2);
            *(ull*)(Ah + off) = hu;
            *(ull*)(Al + off) = lu;
        }
        __syncthreads();
        // compute: 4 k16-steps
        #pragma unroll
        for (int s = 0; s < 4; ++s) {
            int kb2 = s * 32;   // byte offset of k-step
            uint32_t ah[2][4], al[2][4];
            #pragma unroll
            for (int mi = 0; mi < 2; ++mi) {
                int row0 = wr * 32 + mi * 16 + g4;
                const unsigned char* pa = Ah + row0 * RS + kb2 + 4 * tq;
                ah[mi][0] = *(const uint32_t*)pa;
                ah[mi][1] = *(const uint32_t*)(pa + 8 * RS);
                ah[mi][2] = *(const uint32_t*)(pa + 16);
                ah[mi][3] = *(const uint32_t*)(pa + 8 * RS + 16);
                const unsigned char* pl = Al + row0 * RS + kb2 + 4 * tq;
                al[mi][0] = *(const uint32_t*)pl;
                al[mi][1] = *(const uint32_t*)(pl + 8 * RS);
                al[mi][2] = *(const uint32_t*)(pl + 16);
                al[mi][3] = *(const uint32_t*)(pl + 8 * RS + 16);
            }
            #pragma unroll
            for (int f = 0; f < 10; ++f) {
                int nrow = wc * 80 + f * 8 + g4;
                const unsigned char* pb = Bh + nrow * RS + kb2 + 4 * tq;
                uint32_t bh0 = *(const uint32_t*)pb;
                uint32_t bh1 = *(const uint32_t*)(pb + 16);
                const unsigned char* pc = Bl + nrow * RS + kb2 + 4 * tq;
                uint32_t bl0 = *(const uint32_t*)pc;
                uint32_t bl1 = *(const uint32_t*)(pc + 16);
                #pragma unroll
                for (int mi = 0; mi < 2; ++mi) {
                    mma16816(acc[mi][f], ah[mi][0], ah[mi][1], ah[mi][2], ah[mi][3], bh0, bh1);
                    mma16816(acc[mi][f], al[mi][0], al[mi][1], al[mi][2], al[mi][3], bh0, bh1);
                    mma16816(acc[mi][f], ah[mi][0], ah[mi][1], ah[mi][2], ah[mi][3], bl0, bl1);
                }
            }
        }
    }

    // store to d_AB
    #pragma unroll
    for (int mi = 0; mi < 2; ++mi) {
        #pragma unroll
        for (int f = 0; f < 10; ++f) {
            int rr = wr * 32 + mi * 16 + g4;
            int col = wc * 80 + f * 8 + 2 * tq;
            int n = n0 + rr;
            if (n < N)
                *(float2*)(d_AB + (size_t)n * ABS + col) = make_float2(acc[mi][f][0], acc[mi][f][1]);
            n = n0 + rr + 8;
            if (n < N)
                *(float2*)(d_AB + (size_t)n * ABS + col) = make_float2(acc[mi][f][2], acc[mi][f][3]);
        }
    }
}

// ===================== T2: bilinear = (i_g * j_g) @ W1c  (128 pairs x 160 / CTA, mma) =====================
// smem: sm_m @0 (512), sm_a @512, Ah @1024 (128*144=18432), Al @19456, Bh @37888 (160*144=23040), Bl @60928 ; total 83968
#define T2_AH 1024
#define T2_AL 19456
#define T2_BH 37888
#define T2_BL 60928
#define T2_SMEM 83968

__global__ __launch_bounds__(256) void bilinear_tc(const float* __restrict__ g,
                                                   const int* __restrict__ mid,
                                                   const int* __restrict__ aid, int P) {
    extern __shared__ unsigned char sm[];
    int* sm_m = (int*)sm;
    int* sm_a = (int*)(sm + 512);
    unsigned char* Ah = sm + T2_AH;
    unsigned char* Al = sm + T2_AL;
    unsigned char* Bh = sm + T2_BH;
    unsigned char* Bl = sm + T2_BL;

    int t = threadIdx.x, wid = t >> 5, lane = t & 31;
    int p0 = blockIdx.x * 128;
    int g4 = lane >> 2, tq = lane & 3;
    int wr = wid >> 1, wc = wid & 1;              // 4 x 2 warp grid

    if (t < 128) {
        int p = p0 + t; if (p >= P) p = P - 1;
        sm_m[t] = mid[p]; sm_a[t] = aid[p];
    }
    __syncthreads();

    int r = t >> 1, half = t & 1;                 // A staging: 128 rows, 32 cols/thread
    const float4* ir = (const float4*)(g + (size_t)sm_m[r] * GI);
    const float4* jr = (const float4*)(g + (size_t)sm_a[r] * GI);

    float acc[2][10][4];
    #pragma unroll
    for (int mi = 0; mi < 2; ++mi)
        #pragma unroll
        for (int f = 0; f < 10; ++f)
            #pragma unroll
            for (int e = 0; e < 4; ++e) acc[mi][f][e] = 0.f;

    for (int q = 0; q < NCH; ++q) {
        int k0 = q * 64;
        __syncthreads();
        {
            const uint4* sH = d_WcTh + (size_t)q * 1280;
            const uint4* sL = d_WcTl + (size_t)q * 1280;
            #pragma unroll
            for (int i = 0; i < 5; ++i) {
                int idx = t + 256 * i;
                int n = idx >> 3, ii = idx & 7;
                *(uint4*)(Bh + n * RS + 16 * ii) = sH[idx];
                *(uint4*)(Bl + n * RS + 16 * ii) = sL[idx];
            }
        }
        #pragma unroll
        for (int gi2 = 0; gi2 < 8; ++gi2) {
            int kb = k0 + 32 * half + 4 * gi2;
            float4 p4 = make_float4(0.f, 0.f, 0.f, 0.f);
            if (kb < GI) {
                float4 x = ir[kb >> 2], y = jr[kb >> 2];
                p4 = make_float4(x.x * y.x, x.y * y.y, x.z * y.z, x.w * y.w);
            }
            ull hu, lu; split4(p4, hu, lu);
            uint32_t off = (uint32_t)(r * RS + (32 * half + 4 * gi2) * 2);
            *(ull*)(Ah + off) = hu;
            *(ull*)(Al + off) = lu;
        }
        __syncthreads();
        #pragma unroll
        for (int s = 0; s < 4; ++s) {
            int kb2 = s * 32;
            uint32_t ah[2][4], al[2][4];
            #pragma unroll
            for (int mi = 0; mi < 2; ++mi) {
                int row0 = wr * 32 + mi * 16 + g4;
                const unsigned char* pa = Ah + row0 * RS + kb2 + 4 * tq;
                ah[mi][0] = *(const uint32_t*)pa;
                ah[mi][1] = *(const uint32_t*)(pa + 8 * RS);
                ah[mi][2] = *(const uint32_t*)(pa + 16);
                ah[mi][3] = *(const uint32_t*)(pa + 8 * RS + 16);
                const unsigned char* pl = Al + row0 * RS + kb2 + 4 * tq;
                al[mi][0] = *(const uint32_t*)pl;
                al[mi][1] = *(const uint32_t*)(pl + 8 * RS);
                al[mi][2] = *(const uint32_t*)(pl + 16);
                al[mi][3] = *(const uint32_t*)(pl + 8 * RS + 16);
            }
            #pragma unroll
            for (int f = 0; f < 10; ++f) {
                int nrow = wc * 80 + f * 8 + g4;
                const unsigned char* pb = Bh + nrow * RS + kb2 + 4 * tq;
                uint32_t bh0 = *(const uint32_t*)pb;
                uint32_t bh1 = *(const uint32_t*)(pb + 16);
                const unsigned char* pc = Bl + nrow * RS + kb2 + 4 * tq;
                uint32_t bl0 = *(const uint32_t*)pc;
                uint32_t bl1 = *(const uint32_t*)(pc + 16);
                #pragma unroll
                for (int mi = 0; mi < 2; ++mi) {
                    mma16816(acc[mi][f], ah[mi][0], ah[mi][1], ah[mi][2], ah[mi][3], bh0, bh1);
                    mma16816(acc[mi][f], al[mi][0], al[mi][1], al[mi][2], al[mi][3], bh0, bh1);
                    mma16816(acc[mi][f], ah[mi][0], ah[mi][1], ah[mi][2], ah[mi][3], bl0, bl1);
                }
            }
        }
    }

    #pragma unroll
    for (int mi = 0; mi < 2; ++mi) {
        #pragma unroll
        for (int f = 0; f < 10; ++f) {
            int rr = wr * 32 + mi * 16 + g4;
            int col = wc * 80 + f * 8 + 2 * tq;
            int p = p0 + rr;
            if (p < P)
                *(float2*)(d_bil + (size_t)p * CPAD + col) = make_float2(acc[mi][f][0], acc[mi][f][1]);
            p = p0 + rr + 8;
            if (p < P)
                *(float2*)(d_bil + (size_t)p * CPAD + col) = make_float2(acc[mi][f][2], acc[mi][f][3]);
        }
    }
}

// ===================== T3: h1 = relu(bil + AB[m] + AB[a] + tabs); layers 2-3 (scalar f32x2) =====================

#define KC 16

__global__ __launch_bounds__(256) void mlp_tail(
    const float* __restrict__ ms,
    const float* __restrict__ W2, const float* __restrict__ b2,
    const float* __restrict__ W3, const float* __restrict__ b3,
    const int* __restrict__ mid,  const int* __restrict__ aid,
    const int* __restrict__ did,  const int* __restrict__ gid,
    const int* __restrict__ sid,
    float* __restrict__ out, int P)
{
    extern __shared__ unsigned char smem_raw[];
    ull*   Ws   = (ull*)smem_raw;                                  // 16*80 ull = 10240 B
    float* QH   = (float*)(smem_raw + 10240);                      // h1 tile [64 x 160]
    int*   sm_m = (int*)(smem_raw + 10240 + 64*CPAD*4);
    int*   sm_a = sm_m + 64;
    int*   sm_d = sm_a + 64;
    int*   sm_g = sm_d + 64;
    int*   sm_s = sm_g + 64;
    float* w3s  = (float*)(sm_s + 64);                             // [160]

    int t  = threadIdx.x;
    int tx = t & 15, ty = t >> 4;
    int ty4 = ty * 4;
    int p0 = blockIdx.x * 64;

    if (t < 64) {
        int p = p0 + t; if (p >= P) p = P - 1;
        sm_m[t] = mid[p]; sm_a[t] = aid[p]; sm_d[t] = did[p]; sm_g[t] = gid[p]; sm_s[t] = sid[p];
    }
    if (t < CPAD) w3s[t] = (t < HID) ? W3[t] : 0.f;
    __syncthreads();

    // stage bilinear tile [64 x 160] (coalesced)
    #pragma unroll
    for (int k = 0; k < 10; ++k) {
        int idx = t + 256 * k;               // 0..2559 float4s
        int rr = idx / 40, cc = (idx % 40) * 4;
        int p = p0 + rr; if (p >= P) p = P - 1;
        *(float4*)(QH + rr * CPAD + cc) = *(const float4*)(d_bil + (size_t)p * CPAD + cc);
    }
    __syncthreads();

    // epilogue 1: h1 = relu(bil + AB[m] + AB[a]+160 + Dt + Gt + St), in place
    {
        const float2* AB2 = (const float2*)d_AB;   // row stride 160 float2
        const float2* Dt2 = (const float2*)d_Dt;
        const float2* Gt2 = (const float2*)d_Gt;
        const float2* St2 = (const float2*)d_St;
        #pragma unroll
        for (int j = 0; j < 4; ++j) {
            int rr = ty4 + j;
            const float2* am = AB2 + (size_t)sm_m[rr] * 160;
            const float2* bm = AB2 + (size_t)sm_a[rr] * 160 + 80;
            const float2* dp = Dt2 + sm_d[rr] * 80;
            const float2* gp = Gt2 + sm_g[rr] * 80;
            const float2* sp = St2 + sm_s[rr] * 80;
            #pragma unroll
            for (int c = 0; c < 5; ++c) {
                int cp = tx + 16*c;
                float2 v  = *(float2*)(QH + rr * CPAD + 2*cp);
                float2 t1 = am[cp], t2 = bm[cp], t3 = dp[cp], t4 = gp[cp], t5 = sp[cp];
                v.x = fmaxf(v.x + t1.x + t2.x + t3.x + t4.x + t5.x, 0.f);
                v.y = fmaxf(v.y + t1.y + t2.y + t3.y + t4.y + t5.y, 0.f);
                *(float2*)(QH + rr * CPAD + 2*cp) = v;
            }
        }
    }

    // layer 2: h2pre = h1 @ W2
    ull acc2[4][5];
    #pragma unroll
    for (int j = 0; j < 4; ++j)
        #pragma unroll
        for (int c = 0; c < 5; ++c) acc2[j][c] = 0ull;

    for (int k0 = 0; k0 < CPAD; k0 += KC) {
        __syncthreads();
        {
            int k = k0 + ty;
            #pragma unroll
            for (int i = 0; i < 5; ++i) {
                int cp = tx + 16*i, c0 = 2*cp;
                ull w = 0ull;
                if (k < HID) {
                    float lo = (c0   < HID) ? W2[k*HID + c0    ] : 0.f;
                    float hi = (c0+1 < HID) ? W2[k*HID + c0 + 1] : 0.f;
                    w = pk(lo, hi);
                }
                Ws[ty * 80 + cp] = w;
            }
        }
        __syncthreads();
        #pragma unroll
        for (int kk = 0; kk < KC; ++kk) {
            ull qq[4];
            #pragma unroll
            for (int j = 0; j < 4; ++j) qq[j] = bcast2(QH[(ty4+j)*CPAD + k0 + kk]);
            #pragma unroll
            for (int c = 0; c < 5; ++c) {
                ull w = Ws[kk*80 + tx + 16*c];
                #pragma unroll
                for (int j = 0; j < 4; ++j) fma2(acc2[j][c], qq[j], w);
            }
        }
    }

    // epilogue 2: relu(h2pre + b2) @ W3 + b3 + ms[m] + ms[a]
    float b3v = b3[0];
    float part[4] = {0.f, 0.f, 0.f, 0.f};
    #pragma unroll
    for (int c = 0; c < 5; ++c) {
        int c0 = 2 * (tx + 16*c);
        float w3a = w3s[c0], w3b = w3s[c0 + 1];
        float b2a = (c0   < HID) ? b2[c0    ] : 0.f;
        float b2b = (c0+1 < HID) ? b2[c0 + 1] : 0.f;
        #pragma unroll
        for (int j = 0; j < 4; ++j) {
            float2 v = unpk(acc2[j][c]);
            part[j] += fmaxf(v.x + b2a, 0.f) * w3a + fmaxf(v.y + b2b, 0.f) * w3b;
        }
    }
    #pragma unroll
    for (int j = 0; j < 4; ++j) {
        #pragma unroll
        for (int off = 8; off > 0; off >>= 1)
            part[j] += __shfl_xor_sync(0xffffffffu, part[j], off);
    }
    if (tx == 0) {
        #pragma unroll
        for (int j = 0; j < 4; ++j) {
            int p = p0 + ty4 + j;
            if (p < P)
                out[p] = part[j] + b3v + ms[sm_m[ty4 + j]] + ms[sm_a[ty4 + j]];
        }
    }
}

// ===================== launch =====================

extern "C" void kernel_launch(void* const* d_in, const int* in_sizes, int n_in,
                              void* d_out, int out_size)
{
    const float* g_i = (const float*)d_in[0];
    const float* ms  = (const float*)d_in[1];
    const float* de  = (const float*)d_in[2];
    const float* ge  = (const float*)d_in[3];
    const float* se  = (const float*)d_in[4];
    const float* W1  = (const float*)d_in[5];
    const float* b1  = (const float*)d_in[6];
    const float* W2  = (const float*)d_in[7];
    const float* b2  = (const float*)d_in[8];
    const float* W3  = (const float*)d_in[9];
    const float* b3  = (const float*)d_in[10];
    const int*   mid = (const int*)d_in[11];
    const int*   aid = (const int*)d_in[12];
    const int*   did = (const int*)d_in[13];
    const int*   gid = (const int*)d_in[14];
    const int*   sid = (const int*)d_in[15];

    int N = in_sizes[0] / GI;
    if (N > NMAX) N = NMAX;
    int P = in_sizes[11];
    if (P > PMAX) P = PMAX;
    float* out = (float*)d_out;

    prep_wtiles<<<NCH, 256>>>(W1);
    prep_tabs<<<1, CPAD>>>(de, ge, se, W1, b1);

    cudaFuncSetAttribute(gemm_ab_tc, cudaFuncAttributeMaxDynamicSharedMemorySize, T1_SMEM);
    gemm_ab_tc<<<(N + 63) / 64, 256, T1_SMEM>>>(g_i, N);

    cudaFuncSetAttribute(bilinear_tc, cudaFuncAttributeMaxDynamicSharedMemorySize, T2_SMEM);
    bilinear_tc<<<(P + 127) / 128, 256, T2_SMEM>>>(g_i, mid, aid, P);

    int smem3 = 10240 + 64*CPAD*4 + 5*64*4 + CPAD*4;   // 53120 B
    cudaFuncSetAttribute(mlp_tail, cudaFuncAttributeMaxDynamicSharedMemorySize, smem3);
    mlp_tail<<<(P + 63) / 64, 256, smem3>>>(ms, W2, b2, W3, b3,
                                            mid, aid, did, gid, sid, out, P);
}

// round 7
// speedup vs baseline: 1.5731x; 1.0469x over previous
#include <cuda_runtime.h>
#include <cuda_bf16.h>
#include <cstdint>

typedef unsigned long long ull;

#define GI   1220
#define HID  150
#define NMAX 50000
#define PMAX 100000
#define CPAD 160
#define ABS  320
#define NCH  20        // K chunks of 64 (padded to 1280)
#define RS   144       // smem row stride (bytes) for bf16 tiles -> conflict-free frag LDS

// ===================== device scratch (no allocations allowed) =====================
__device__ float d_AB[(size_t)NMAX * ABS];     // 64 MB: per-mention  g@[W1a|W1b]
__device__ uint4 d_WcTh[NCH * 20480 / 16];     // W1c^T bf16-hi tiles [160 x 64] per chunk
__device__ uint4 d_WcTl[NCH * 20480 / 16];     // bf16-lo
__device__ uint4 d_WabTh[NCH * 40960 / 16];    // [W1a|pad|W1b|pad]^T tiles [320 x 64] per chunk
__device__ uint4 d_WabTl[NCH * 40960 / 16];
__device__ float d_Dt[9 * CPAD];               // dist table (+b1)
__device__ float d_Gt[8 * CPAD];
__device__ float d_St[3 * CPAD];

// ===================== helpers =====================
__device__ __forceinline__ uint32_t smem_to_u32(const void* p) {
    uint32_t a;
    asm("{ .reg .u64 t; cvta.to.shared.u64 t, %1; cvt.u32.u64 %0, t; }" : "=r"(a) : "l"(p));
    return a;
}

__device__ __forceinline__ void mma16816(float c[4],
                                         uint32_t a0, uint32_t a1, uint32_t a2, uint32_t a3,
                                         uint32_t b0, uint32_t b1) {
    asm volatile(
        "mma.sync.aligned.m16n8k16.row.col.f32.bf16.bf16.f32 "
        "{%0,%1,%2,%3}, {%4,%5,%6,%7}, {%8,%9}, {%0,%1,%2,%3};"
        : "+f"(c[0]), "+f"(c[1]), "+f"(c[2]), "+f"(c[3])
        : "r"(a0), "r"(a1), "r"(a2), "r"(a3), "r"(b0), "r"(b1));
}

__device__ __forceinline__ void cp16(uint32_t dst, const void* src) {
    asm volatile("cp.async.cg.shared.global [%0], [%1], 16;" :: "r"(dst), "l"(src));
}
#define CP_COMMIT() asm volatile("cp.async.commit_group;" ::: "memory")
#define CP_WAIT0()  asm volatile("cp.async.wait_group 0;" ::: "memory")

union BPack { __nv_bfloat16 v[4]; ull u; };
__device__ __forceinline__ void split4(float4 x, ull& hu, ull& lu) {
    BPack H, L;
    float p[4] = {x.x, x.y, x.z, x.w};
    #pragma unroll
    for (int i = 0; i < 4; ++i) {
        __nv_bfloat16 h = __float2bfloat16(p[i]);
        H.v[i] = h;
        L.v[i] = __float2bfloat16(p[i] - __bfloat162float(h));
    }
    hu = H.u; lu = L.u;
}

// packed f32x2 helpers (scalar tail)
__device__ __forceinline__ void fma2(ull& d, ull a, ull b) {
    asm("fma.rn.f32x2 %0, %1, %2, %0;" : "+l"(d) : "l"(a), "l"(b));
}
__device__ __forceinline__ ull bcast2(float x) {
    ull r; asm("mov.b64 %0, {%1, %1};" : "=l"(r) : "f"(x)); return r;
}
__device__ __forceinline__ ull pk(float x, float y) {
    ull r; asm("mov.b64 %0, {%1, %2};" : "=l"(r) : "f"(x), "f"(y)); return r;
}
__device__ __forceinline__ float2 unpk(ull v) {
    float2 r; asm("mov.b64 {%0, %1}, %2;" : "=f"(r.x), "=f"(r.y) : "l"(v)); return r;
}

// shared MMA inner step: 4B frags from stride-144 smem, 3 split passes, 10 n-frags x 2 m-frags
__device__ __forceinline__ void mma_chunk(float (*acc)[10][4],
        const unsigned char* __restrict__ Ah, const unsigned char* __restrict__ Al,
        const unsigned char* __restrict__ Bh, const unsigned char* __restrict__ Bl,
        int s, int rowbase, int colbase, int g4, int tq) {
    int kb2 = s * 32;
    uint32_t ah[2][4], al[2][4];
    #pragma unroll
    for (int mi = 0; mi < 2; ++mi) {
        int row0 = rowbase + mi * 16 + g4;
        const unsigned char* pa = Ah + row0 * RS + kb2 + 4 * tq;
        ah[mi][0] = *(const uint32_t*)pa;
        ah[mi][1] = *(const uint32_t*)(pa + 8 * RS);
        ah[mi][2] = *(const uint32_t*)(pa + 16);
        ah[mi][3] = *(const uint32_t*)(pa + 8 * RS + 16);
        const unsigned char* pl = Al + row0 * RS + kb2 + 4 * tq;
        al[mi][0] = *(const uint32_t*)pl;
        al[mi][1] = *(const uint32_t*)(pl + 8 * RS);
        al[mi][2] = *(const uint32_t*)(pl + 16);
        al[mi][3] = *(const uint32_t*)(pl + 8 * RS + 16);
    }
    #pragma unroll
    for (int f = 0; f < 10; ++f) {
        int nrow = colbase + f * 8 + g4;
        const unsigned char* pb = Bh + nrow * RS + kb2 + 4 * tq;
        uint32_t bh0 = *(const uint32_t*)pb;
        uint32_t bh1 = *(const uint32_t*)(pb + 16);
        const unsigned char* pc = Bl + nrow * RS + kb2 + 4 * tq;
        uint32_t bl0 = *(const uint32_t*)pc;
        uint32_t bl1 = *(const uint32_t*)(pc + 16);
        #pragma unroll
        for (int mi = 0; mi < 2; ++mi) {
            mma16816(acc[mi][f], ah[mi][0], ah[mi][1], ah[mi][2], ah[mi][3], bh0, bh1);
            mma16816(acc[mi][f], al[mi][0], al[mi][1], al[mi][2], al[mi][3], bh0, bh1);
            mma16816(acc[mi][f], ah[mi][0], ah[mi][1], ah[mi][2], ah[mi][3], bl0, bl1);
        }
    }
}

// ===================== weight prep: transpose + bf16 split =====================

__global__ void prep_wtiles(const float* __restrict__ W1) {
    int q = blockIdx.x;   // K-chunk
    int t = threadIdx.x;
    __nv_bfloat16* ch = (__nv_bfloat16*)d_WcTh;
    __nv_bfloat16* cl = (__nv_bfloat16*)d_WcTl;
    for (int idx = t; idx < 160 * 64; idx += 256) {
        int n = idx >> 6, kk = idx & 63, k = q * 64 + kk;
        float v = (k < GI && n < HID) ? W1[(2 * GI + k) * HID + n] : 0.f;
        __nv_bfloat16 h = __float2bfloat16(v);
        float l = v - __bfloat162float(h);
        size_t e = (size_t)q * 10240 + (size_t)n * 64 + kk;
        ch[e] = h; cl[e] = __float2bfloat16(l);
    }
    __nv_bfloat16* ah = (__nv_bfloat16*)d_WabTh;
    __nv_bfloat16* al = (__nv_bfloat16*)d_WabTl;
    for (int idx = t; idx < 320 * 64; idx += 256) {
        int n = idx >> 6, kk = idx & 63, k = q * 64 + kk;
        float v = 0.f;
        if (k < GI) {
            if (n < HID)                        v = W1[k * HID + n];
            else if (n >= 160 && n < 160 + HID) v = W1[(GI + k) * HID + (n - 160)];
        }
        __nv_bfloat16 h = __float2bfloat16(v);
        float l = v - __bfloat162float(h);
        size_t e = (size_t)q * 20480 + (size_t)n * 64 + kk;
        ah[e] = h; al[e] = __float2bfloat16(l);
    }
}

__global__ void prep_tabs(const float* __restrict__ de, const float* __restrict__ ge,
                          const float* __restrict__ se, const float* __restrict__ W1,
                          const float* __restrict__ b1) {
    int c = threadIdx.x;     // 0..159
    for (int d = 0; d < 9; ++d) {
        float v = 0.f;
        if (c < HID) {
            v = b1[c];
            for (int t = 0; t < 20; ++t) v += de[d*20 + t] * W1[(3*GI + t) * HID + c];
        }
        d_Dt[d * CPAD + c] = v;
    }
    for (int g = 0; g < 8; ++g) {
        float v = 0.f;
        if (c < HID)
            for (int t = 0; t < 20; ++t) v += ge[g*20 + t] * W1[(3*GI + 20 + t) * HID + c];
        d_Gt[g * CPAD + c] = v;
    }
    for (int s = 0; s < 3; ++s) {
        float v = 0.f;
        if (c < HID)
            for (int t = 0; t < 20; ++t) v += se[s*20 + t] * W1[(3*GI + 40 + t) * HID + c];
        d_St[s * CPAD + c] = v;
    }
}

// ===================== T1: AB = g @ [W1a|W1b]  (64 x 320 / CTA, pipelined mma) =====================
// smem: A bufs @0 (2 x 18432: h 9216 + l 9216), B bufs @36864 (2 x 92160: h 46080 + l 46080)
#define T1_B    36864
#define T1_SMEM 221184

__device__ __forceinline__ void cpB_T1(uint32_t bh, uint32_t bl, int q, int t) {
    const uint4* sH = d_WabTh + (size_t)q * 2560;
    const uint4* sL = d_WabTl + (size_t)q * 2560;
    #pragma unroll
    for (int i = 0; i < 10; ++i) {
        int idx = t + 256 * i, n = idx >> 3, seg = idx & 7;
        uint32_t o = n * RS + seg * 16;
        cp16(bh + o, sH + idx);
        cp16(bl + o, sL + idx);
    }
}

__device__ __forceinline__ void ldgRow(const float4* grow, int kb0, float4 x[2]) {
    #pragma unroll
    for (int u = 0; u < 2; ++u) {
        int kb = kb0 + 4 * u;
        x[u] = (kb < GI) ? grow[kb >> 2] : make_float4(0.f, 0.f, 0.f, 0.f);
    }
}
__device__ __forceinline__ void stsRow(unsigned char* Ah, unsigned char* Al,
                                       int r, int koff, const float4 x[2]) {
    #pragma unroll
    for (int u = 0; u < 2; ++u) {
        ull hu, lu; split4(x[u], hu, lu);
        uint32_t off = (uint32_t)(r * RS + (koff + 4 * u) * 2);
        *(ull*)(Ah + off) = hu;
        *(ull*)(Al + off) = lu;
    }
}

__global__ __launch_bounds__(256) void gemm_ab_pipe(const float* __restrict__ g, int N) {
    extern __shared__ unsigned char sm[];
    uint32_t sb = smem_to_u32(sm);
    int t = threadIdx.x, wid = t >> 5, lane = t & 31;
    int g4 = lane >> 2, tq = lane & 3;
    int wr = wid >> 2, wc = wid & 3;
    int rowbase = wr * 32, colbase = wc * 80;
    int n0 = blockIdx.x * 64;
    int r = t >> 2, qd = t & 3, kth = 16 * qd;
    int row = n0 + r; if (row >= N) row = N - 1;
    const float4* grow = (const float4*)(g + (size_t)row * GI);

    float acc[2][10][4];
    #pragma unroll
    for (int mi = 0; mi < 2; ++mi)
        #pragma unroll
        for (int f = 0; f < 10; ++f)
            #pragma unroll
            for (int e = 0; e < 4; ++e) acc[mi][f][e] = 0.f;

    // prologue: stage chunk 0
    {
        float4 x[2];
        ldgRow(grow, kth, x);      stsRow(sm, sm + 9216, r, kth, x);
        ldgRow(grow, kth + 8, x);  stsRow(sm, sm + 9216, r, kth + 8, x);
        cpB_T1(sb + T1_B, sb + T1_B + 46080, 0, t);
        CP_COMMIT(); CP_WAIT0();
    }
    __syncthreads();

    for (int q = 0; q < NCH; ++q) {
        int cb = q & 1, nb = cb ^ 1;
        unsigned char* Ah = sm + cb * 18432;
        unsigned char* Al = Ah + 9216;
        unsigned char* Bh = sm + T1_B + cb * 92160;
        unsigned char* Bl = Bh + 46080;
        unsigned char* nAh = sm + nb * 18432;
        unsigned char* nAl = nAh + 9216;
        bool more = (q + 1 < NCH);
        if (more) { cpB_T1(sb + T1_B + nb * 92160, sb + T1_B + nb * 92160 + 46080, q + 1, t); CP_COMMIT(); }
        float4 x0[2], x1[2];
        int kn = (q + 1) * 64 + kth;
        if (more) ldgRow(grow, kn, x0);
        mma_chunk(acc, Ah, Al, Bh, Bl, 0, rowbase, colbase, g4, tq);
        mma_chunk(acc, Ah, Al, Bh, Bl, 1, rowbase, colbase, g4, tq);
        if (more) { stsRow(nAh, nAl, r, kth, x0); ldgRow(grow, kn + 8, x1); }
        mma_chunk(acc, Ah, Al, Bh, Bl, 2, rowbase, colbase, g4, tq);
        mma_chunk(acc, Ah, Al, Bh, Bl, 3, rowbase, colbase, g4, tq);
        if (more) { stsRow(nAh, nAl, r, kth + 8, x1); CP_WAIT0(); }
        __syncthreads();
    }

    #pragma unroll
    for (int mi = 0; mi < 2; ++mi) {
        #pragma unroll
        for (int f = 0; f < 10; ++f) {
            int rr = rowbase + mi * 16 + g4;
            int col = colbase + f * 8 + 2 * tq;
            int n = n0 + rr;
            if (n < N)
                *(float2*)(d_AB + (size_t)n * ABS + col) = make_float2(acc[mi][f][0], acc[mi][f][1]);
            n = n0 + rr + 8;
            if (n < N)
                *(float2*)(d_AB + (size_t)n * ABS + col) = make_float2(acc[mi][f][2], acc[mi][f][3]);
        }
    }
}

// ===================== T2 fused: bilinear MMA + epilogue + layers 2-3 =====================
// smem layout:
//   [0, 2560)         indices m/a/d/g/s (5 x 512)
//   [2560, 3200)      w3s
//   [4096, 77824)     A bufs (2 x 36864: h 18432 + l 18432)
//   [77824, 169984)   B bufs (2 x 46080: h 23040 + l 23040)
//   stage (reuse A/B): [4096, 90112)  128 rows x 168 floats
//   Ws (layer2 W2):    [90112, 100352)
#define F_W3   2560
#define F_A    4096
#define F_B    77824
#define F_STG  4096
#define F_WS   90112
#define F_SMEM 169984
#define SSTR   168

__device__ __forceinline__ void cpB_T2(uint32_t bh, uint32_t bl, int q, int t) {
    const uint4* sH = d_WcTh + (size_t)q * 1280;
    const uint4* sL = d_WcTl + (size_t)q * 1280;
    #pragma unroll
    for (int i = 0; i < 5; ++i) {
        int idx = t + 256 * i, n = idx >> 3, seg = idx & 7;
        uint32_t o = n * RS + seg * 16;
        cp16(bh + o, sH + idx);
        cp16(bl + o, sL + idx);
    }
}

__device__ __forceinline__ void ldgPair(const float4* ir, const float4* jr, int kb0,
                                        float4 xi[4], float4 xj[4]) {
    #pragma unroll
    for (int u = 0; u < 4; ++u) {
        int kb = kb0 + 4 * u;
        if (kb < GI) { xi[u] = ir[kb >> 2]; xj[u] = jr[kb >> 2]; }
        else { xi[u] = make_float4(0.f, 0.f, 0.f, 0.f); xj[u] = make_float4(0.f, 0.f, 0.f, 0.f); }
    }
}
__device__ __forceinline__ void stsPair(unsigned char* Ah, unsigned char* Al,
                                        int r, int koff, const float4 xi[4], const float4 xj[4]) {
    #pragma unroll
    for (int u = 0; u < 4; ++u) {
        float4 p4 = make_float4(xi[u].x * xj[u].x, xi[u].y * xj[u].y,
                                xi[u].z * xj[u].z, xi[u].w * xj[u].w);
        ull hu, lu; split4(p4, hu, lu);
        uint32_t off = (uint32_t)(r * RS + (koff + 4 * u) * 2);
        *(ull*)(Ah + off) = hu;
        *(ull*)(Al + off) = lu;
    }
}

__global__ __launch_bounds__(256) void bilinear_fused(
    const float* __restrict__ g,  const float* __restrict__ ms,
    const float* __restrict__ W2, const float* __restrict__ b2,
    const float* __restrict__ W3, const float* __restrict__ b3,
    const int* __restrict__ mid,  const int* __restrict__ aid,
    const int* __restrict__ did,  const int* __restrict__ gid,
    const int* __restrict__ sid,
    float* __restrict__ out, int P)
{
    extern __shared__ unsigned char sm[];
    uint32_t sb = smem_to_u32(sm);
    int t = threadIdx.x, wid = t >> 5, lane = t & 31;
    int g4 = lane >> 2, tq = lane & 3;
    int wr = wid >> 1, wc = wid & 1;
    int rowbase = wr * 32, colbase = wc * 80;
    int p0 = blockIdx.x * 128;
    int* sm_m = (int*)sm;
    int* sm_a = (int*)(sm + 512);
    int* sm_d = (int*)(sm + 1024);
    int* sm_g = (int*)(sm + 1536);
    int* sm_s = (int*)(sm + 2048);
    float* w3s = (float*)(sm + F_W3);

    if (t < 128) {
        int p = p0 + t; if (p >= P) p = P - 1;
        sm_m[t] = mid[p]; sm_a[t] = aid[p]; sm_d[t] = did[p]; sm_g[t] = gid[p]; sm_s[t] = sid[p];
    }
    if (t < CPAD) w3s[t] = (t < HID) ? W3[t] : 0.f;
    __syncthreads();

    int r = t >> 1, kth = 32 * (t & 1);
    const float4* ir = (const float4*)(g + (size_t)sm_m[r] * GI);
    const float4* jr = (const float4*)(g + (size_t)sm_a[r] * GI);

    float acc[2][10][4];
    #pragma unroll
    for (int mi = 0; mi < 2; ++mi)
        #pragma unroll
        for (int f = 0; f < 10; ++f)
            #pragma unroll
            for (int e = 0; e < 4; ++e) acc[mi][f][e] = 0.f;

    // prologue: stage chunk 0
    {
        float4 xi[4], xj[4];
        ldgPair(ir, jr, kth, xi, xj);
        stsPair(sm + F_A, sm + F_A + 18432, r, kth, xi, xj);
        ldgPair(ir, jr, kth + 16, xi, xj);
        stsPair(sm + F_A, sm + F_A + 18432, r, kth + 16, xi, xj);
        cpB_T2(sb + F_B, sb + F_B + 23040, 0, t);
        CP_COMMIT(); CP_WAIT0();
    }
    __syncthreads();

    for (int q = 0; q < NCH; ++q) {
        int cb = q & 1, nb = cb ^ 1;
        unsigned char* Ah = sm + F_A + cb * 36864;
        unsigned char* Al = Ah + 18432;
        unsigned char* Bh = sm + F_B + cb * 46080;
        unsigned char* Bl = Bh + 23040;
        unsigned char* nAh = sm + F_A + nb * 36864;
        unsigned char* nAl = nAh + 18432;
        bool more = (q + 1 < NCH);
        if (more) { cpB_T2(sb + F_B + nb * 46080, sb + F_B + nb * 46080 + 23040, q + 1, t); CP_COMMIT(); }
        float4 xi[4], xj[4];
        int kn = (q + 1) * 64 + kth;
        if (more) ldgPair(ir, jr, kn, xi, xj);
        mma_chunk(acc, Ah, Al, Bh, Bl, 0, rowbase, colbase, g4, tq);
        mma_chunk(acc, Ah, Al, Bh, Bl, 1, rowbase, colbase, g4, tq);
        if (more) { stsPair(nAh, nAl, r, kth, xi, xj); ldgPair(ir, jr, kn + 16, xi, xj); }
        mma_chunk(acc, Ah, Al, Bh, Bl, 2, rowbase, colbase, g4, tq);
        mma_chunk(acc, Ah, Al, Bh, Bl, 3, rowbase, colbase, g4, tq);
        if (more) { stsPair(nAh, nAl, r, kth + 16, xi, xj); CP_WAIT0(); }
        __syncthreads();
    }

    // ---- stage acc -> smem [128 x 168] ----
    float* stg = (float*)(sm + F_STG);
    #pragma unroll
    for (int mi = 0; mi < 2; ++mi) {
        #pragma unroll
        for (int f = 0; f < 10; ++f) {
            int rr = rowbase + mi * 16 + g4;
            int col = colbase + f * 8 + 2 * tq;
            *(float2*)(stg + rr * SSTR + col) = make_float2(acc[mi][f][0], acc[mi][f][1]);
            *(float2*)(stg + (rr + 8) * SSTR + col) = make_float2(acc[mi][f][2], acc[mi][f][3]);
        }
    }
    __syncthreads();

    // ---- epilogue 1: h1 = relu(bil + AB[m] + AB[a]+160 + Dt + Gt + St), in place ----
    int tx = t & 15, ty = t >> 4;
    {
        const float2* AB2 = (const float2*)d_AB;   // row stride 160 float2
        const float2* Dt2 = (const float2*)d_Dt;
        const float2* Gt2 = (const float2*)d_Gt;
        const float2* St2 = (const float2*)d_St;
        #pragma unroll
        for (int j = 0; j < 8; ++j) {
            int rr = ty * 8 + j;
            const float2* am = AB2 + (size_t)sm_m[rr] * 160;
            const float2* bm = AB2 + (size_t)sm_a[rr] * 160 + 80;
            const float2* dp = Dt2 + sm_d[rr] * 80;
            const float2* gp = Gt2 + sm_g[rr] * 80;
            const float2* sp = St2 + sm_s[rr] * 80;
            #pragma unroll
            for (int c = 0; c < 5; ++c) {
                int cp = tx + 16 * c;
                float2 v  = *(float2*)(stg + rr * SSTR + 2 * cp);
                float2 t1 = am[cp], t2 = bm[cp], t3 = dp[cp], t4 = gp[cp], t5 = sp[cp];
                v.x = fmaxf(v.x + t1.x + t2.x + t3.x + t4.x + t5.x, 0.f);
                v.y = fmaxf(v.y + t1.y + t2.y + t3.y + t4.y + t5.y, 0.f);
                *(float2*)(stg + rr * SSTR + 2 * cp) = v;
            }
        }
    }

    // ---- layer 2: h2pre = h1 @ W2 (scalar f32x2) ----
    ull* Ws = (ull*)(sm + F_WS);
    ull acc2[8][5];
    #pragma unroll
    for (int j = 0; j < 8; ++j)
        #pragma unroll
        for (int c = 0; c < 5; ++c) acc2[j][c] = 0ull;

    for (int k0 = 0; k0 < CPAD; k0 += 16) {
        __syncthreads();
        {
            int k = k0 + ty;
            #pragma unroll
            for (int i = 0; i < 5; ++i) {
                int cp = tx + 16 * i, c0 = 2 * cp;
                ull w = 0ull;
                if (k < HID) {
                    float lo = (c0     < HID) ? W2[k * HID + c0    ] : 0.f;
                    float hi = (c0 + 1 < HID) ? W2[k * HID + c0 + 1] : 0.f;
                    w = pk(lo, hi);
                }
                Ws[ty * 80 + cp] = w;
            }
        }
        __syncthreads();
        #pragma unroll
        for (int kk = 0; kk < 16; ++kk) {
            ull qq[8];
            #pragma unroll
            for (int j = 0; j < 8; ++j) qq[j] = bcast2(stg[(ty * 8 + j) * SSTR + k0 + kk]);
            #pragma unroll
            for (int c = 0; c < 5; ++c) {
                ull w = Ws[kk * 80 + tx + 16 * c];
                #pragma unroll
                for (int j = 0; j < 8; ++j) fma2(acc2[j][c], qq[j], w);
            }
        }
    }

    // ---- epilogue 2: relu(h2pre + b2) @ W3 + b3 + ms[m] + ms[a] ----
    float b3v = b3[0];
    float part[8] = {0.f, 0.f, 0.f, 0.f, 0.f, 0.f, 0.f, 0.f};
    #pragma unroll
    for (int c = 0; c < 5; ++c) {
        int c0 = 2 * (tx + 16 * c);
        float w3a = w3s[c0], w3b = w3s[c0 + 1];
        float b2a = (c0     < HID) ? b2[c0    ] : 0.f;
        float b2b = (c0 + 1 < HID) ? b2[c0 + 1] : 0.f;
        #pragma unroll
        for (int j = 0; j < 8; ++j) {
            float2 v = unpk(acc2[j][c]);
            part[j] += fmaxf(v.x + b2a, 0.f) * w3a + fmaxf(v.y + b2b, 0.f) * w3b;
        }
    }
    #pragma unroll
    for (int j = 0; j < 8; ++j) {
        #pragma unroll
        for (int off = 8; off > 0; off >>= 1)
            part[j] += __shfl_xor_sync(0xffffffffu, part[j], off);
    }
    if (tx == 0) {
        #pragma unroll
        for (int j = 0; j < 8; ++j) {
            int rr = ty * 8 + j;
            int p = p0 + rr;
            if (p < P)
                out[p] = part[j] + b3v + ms[sm_m[rr]] + ms[sm_a[rr]];
        }
    }
}

// ===================== launch =====================

extern "C" void kernel_launch(void* const* d_in, const int* in_sizes, int n_in,
                              void* d_out, int out_size)
{
    const float* g_i = (const float*)d_in[0];
    const float* ms  = (const float*)d_in[1];
    const float* de  = (const float*)d_in[2];
    const float* ge  = (const float*)d_in[3];
    const float* se  = (const float*)d_in[4];
    const float* W1  = (const float*)d_in[5];
    const float* b1  = (const float*)d_in[6];
    const float* W2  = (const float*)d_in[7];
    const float* b2  = (const float*)d_in[8];
    const float* W3  = (const float*)d_in[9];
    const float* b3  = (const float*)d_in[10];
    const int*   mid = (const int*)d_in[11];
    const int*   aid = (const int*)d_in[12];
    const int*   did = (const int*)d_in[13];
    const int*   gid = (const int*)d_in[14];
    const int*   sid = (const int*)d_in[15];

    int N = in_sizes[0] / GI;
    if (N > NMAX) N = NMAX;
    int P = in_sizes[11];
    if (P > PMAX) P = PMAX;
    float* out = (float*)d_out;

    prep_wtiles<<<NCH, 256>>>(W1);
    prep_tabs<<<1, CPAD>>>(de, ge, se, W1, b1);

    cudaFuncSetAttribute(gemm_ab_pipe, cudaFuncAttributeMaxDynamicSharedMemorySize, T1_SMEM);
    gemm_ab_pipe<<<(N + 63) / 64, 256, T1_SMEM>>>(g_i, N);

    cudaFuncSetAttribute(bilinear_fused, cudaFuncAttributeMaxDynamicSharedMemorySize, F_SMEM);
    bilinear_fused<<<(P + 127) / 128, 256, F_SMEM>>>(g_i, ms, W2, b2, W3, b3,
                                                     mid, aid, did, gid, sid, out, P);
}

// round 8
// speedup vs baseline: 1.6654x; 1.0587x over previous
#include <cuda_runtime.h>
#include <cuda_bf16.h>
#include <cstdint>

typedef unsigned long long ull;

#define GI   1220
#define HID  150
#define NMAX 50000
#define PMAX 100000
#define CPAD 160
#define ABS  320
#define NCH  20        // K chunks of 64 (padded to 1280)
#define RS   144       // smem row stride (bytes) for bf16 tiles -> conflict-free LDSM

// ===================== device scratch (no allocations allowed) =====================
__device__ float d_AB[(size_t)NMAX * ABS];     // 64 MB: per-mention  g@[W1a|W1b]
__device__ uint4 d_WcTh[NCH * 20480 / 16];     // W1c^T bf16-hi tiles [160 x 64] per chunk
__device__ uint4 d_WcTl[NCH * 20480 / 16];     // bf16-lo
__device__ uint4 d_WabTh[NCH * 40960 / 16];    // [W1a|pad|W1b|pad]^T tiles [320 x 64] per chunk
__device__ uint4 d_WabTl[NCH * 40960 / 16];
__device__ float d_Dt[9 * CPAD];               // dist table (+b1)
__device__ float d_Gt[8 * CPAD];
__device__ float d_St[3 * CPAD];

// ===================== helpers =====================
__device__ __forceinline__ uint32_t smem_to_u32(const void* p) {
    uint32_t a;
    asm("{ .reg .u64 t; cvta.to.shared.u64 t, %1; cvt.u32.u64 %0, t; }" : "=r"(a) : "l"(p));
    return a;
}

__device__ __forceinline__ void mma16816(float c[4],
                                         uint32_t a0, uint32_t a1, uint32_t a2, uint32_t a3,
                                         uint32_t b0, uint32_t b1) {
    asm volatile(
        "mma.sync.aligned.m16n8k16.row.col.f32.bf16.bf16.f32 "
        "{%0,%1,%2,%3}, {%4,%5,%6,%7}, {%8,%9}, {%0,%1,%2,%3};"
        : "+f"(c[0]), "+f"(c[1]), "+f"(c[2]), "+f"(c[3])
        : "r"(a0), "r"(a1), "r"(a2), "r"(a3), "r"(b0), "r"(b1));
}

__device__ __forceinline__ void ldsm4(uint32_t r[4], uint32_t addr) {
    asm volatile("ldmatrix.sync.aligned.m8n8.x4.shared.b16 {%0,%1,%2,%3}, [%4];"
        : "=r"(r[0]), "=r"(r[1]), "=r"(r[2]), "=r"(r[3]) : "r"(addr));
}

__device__ __forceinline__ void cp16(uint32_t dst, const void* src) {
    asm volatile("cp.async.cg.shared.global [%0], [%1], 16;" :: "r"(dst), "l"(src));
}
#define CP_COMMIT() asm volatile("cp.async.commit_group;" ::: "memory")
#define CP_WAIT0()  asm volatile("cp.async.wait_group 0;" ::: "memory")

union BPack { __nv_bfloat16 v[4]; ull u; };
__device__ __forceinline__ void split4(float4 x, ull& hu, ull& lu) {
    BPack H, L;
    float p[4] = {x.x, x.y, x.z, x.w};
    #pragma unroll
    for (int i = 0; i < 4; ++i) {
        __nv_bfloat16 h = __float2bfloat16(p[i]);
        H.v[i] = h;
        L.v[i] = __float2bfloat16(p[i] - __bfloat162float(h));
    }
    hu = H.u; lu = L.u;
}

// packed f32x2 helpers (scalar tail)
__device__ __forceinline__ void fma2(ull& d, ull a, ull b) {
    asm("fma.rn.f32x2 %0, %1, %2, %0;" : "+l"(d) : "l"(a), "l"(b));
}
__device__ __forceinline__ ull bcast2(float x) {
    ull r; asm("mov.b64 %0, {%1, %1};" : "=l"(r) : "f"(x)); return r;
}
__device__ __forceinline__ ull pk(float x, float y) {
    ull r; asm("mov.b64 %0, {%1, %2};" : "=l"(r) : "f"(x), "f"(y)); return r;
}
__device__ __forceinline__ float2 unpk(ull v) {
    float2 r; asm("mov.b64 {%0, %1}, %2;" : "=f"(r.x), "=f"(r.y) : "l"(v)); return r;
}

// MMA inner step with ldmatrix.x4 frag loads (addresses are shared-space u32)
// Lane mapping for A: matrices {rows+0..7 @k, rows+8..15 @k, rows+0..7 @k+8, rows+8..15 @k+8}
// Lane mapping for B: matrices {f rows @k, f rows @k+8, f+1 rows @k, f+1 rows @k+8}
__device__ __forceinline__ void mma_chunk(float (*acc)[10][4],
        uint32_t Ah, uint32_t Al, uint32_t Bh, uint32_t Bl,
        int s, int rowbase, int colbase, int lane) {
    int kb2 = s * 32;
    int l7 = lane & 7, g = lane >> 3;
    uint32_t aoff = (uint32_t)((rowbase + (g & 1) * 8 + l7) * RS + kb2 + (g >> 1) * 16);
    uint32_t ah[2][4], al[2][4];
    ldsm4(ah[0], Ah + aoff);
    ldsm4(ah[1], Ah + aoff + 16 * RS);
    ldsm4(al[0], Al + aoff);
    ldsm4(al[1], Al + aoff + 16 * RS);
    uint32_t boff = (uint32_t)((colbase + (g >> 1) * 8 + l7) * RS + kb2 + (g & 1) * 16);
    #pragma unroll
    for (int fp = 0; fp < 5; ++fp) {
        uint32_t bh[4], bl[4];
        ldsm4(bh, Bh + boff + fp * 16 * RS);
        ldsm4(bl, Bl + boff + fp * 16 * RS);
        #pragma unroll
        for (int half = 0; half < 2; ++half) {
            int f = fp * 2 + half;
            uint32_t b0h = bh[half * 2], b1h = bh[half * 2 + 1];
            uint32_t b0l = bl[half * 2], b1l = bl[half * 2 + 1];
            #pragma unroll
            for (int mi = 0; mi < 2; ++mi) {
                mma16816(acc[mi][f], ah[mi][0], ah[mi][1], ah[mi][2], ah[mi][3], b0h, b1h);
                mma16816(acc[mi][f], al[mi][0], al[mi][1], al[mi][2], al[mi][3], b0h, b1h);
                mma16816(acc[mi][f], ah[mi][0], ah[mi][1], ah[mi][2], ah[mi][3], b0l, b1l);
            }
        }
    }
}

// ===================== weight prep: transpose + bf16 split =====================

__global__ void prep_wtiles(const float* __restrict__ W1) {
    int q = blockIdx.x;   // K-chunk
    int t = threadIdx.x;
    __nv_bfloat16* ch = (__nv_bfloat16*)d_WcTh;
    __nv_bfloat16* cl = (__nv_bfloat16*)d_WcTl;
    for (int idx = t; idx < 160 * 64; idx += 256) {
        int n = idx >> 6, kk = idx & 63, k = q * 64 + kk;
        float v = (k < GI && n < HID) ? W1[(2 * GI + k) * HID + n] : 0.f;
        __nv_bfloat16 h = __float2bfloat16(v);
        float l = v - __bfloat162float(h);
        size_t e = (size_t)q * 10240 + (size_t)n * 64 + kk;
        ch[e] = h; cl[e] = __float2bfloat16(l);
    }
    __nv_bfloat16* ah = (__nv_bfloat16*)d_WabTh;
    __nv_bfloat16* al = (__nv_bfloat16*)d_WabTl;
    for (int idx = t; idx < 320 * 64; idx += 256) {
        int n = idx >> 6, kk = idx & 63, k = q * 64 + kk;
        float v = 0.f;
        if (k < GI) {
            if (n < HID)                        v = W1[k * HID + n];
            else if (n >= 160 && n < 160 + HID) v = W1[(GI + k) * HID + (n - 160)];
        }
        __nv_bfloat16 h = __float2bfloat16(v);
        float l = v - __bfloat162float(h);
        size_t e = (size_t)q * 20480 + (size_t)n * 64 + kk;
        ah[e] = h; al[e] = __float2bfloat16(l);
    }
}

__global__ void prep_tabs(const float* __restrict__ de, const float* __restrict__ ge,
                          const float* __restrict__ se, const float* __restrict__ W1,
                          const float* __restrict__ b1) {
    int c = threadIdx.x;     // 0..159
    for (int d = 0; d < 9; ++d) {
        float v = 0.f;
        if (c < HID) {
            v = b1[c];
            for (int t = 0; t < 20; ++t) v += de[d*20 + t] * W1[(3*GI + t) * HID + c];
        }
        d_Dt[d * CPAD + c] = v;
    }
    for (int g = 0; g < 8; ++g) {
        float v = 0.f;
        if (c < HID)
            for (int t = 0; t < 20; ++t) v += ge[g*20 + t] * W1[(3*GI + 20 + t) * HID + c];
        d_Gt[g * CPAD + c] = v;
    }
    for (int s = 0; s < 3; ++s) {
        float v = 0.f;
        if (c < HID)
            for (int t = 0; t < 20; ++t) v += se[s*20 + t] * W1[(3*GI + 40 + t) * HID + c];
        d_St[s * CPAD + c] = v;
    }
}

// ===================== T1: AB = g @ [W1a|W1b]  (64 x 320 / CTA, pipelined mma) =====================
// smem: A bufs @0 (2 x 18432: h 9216 + l 9216), B bufs @36864 (2 x 92160: h 46080 + l 46080)
#define T1_B    36864
#define T1_SMEM 221184

__device__ __forceinline__ void cpB_T1(uint32_t bh, uint32_t bl, int q, int t) {
    const uint4* sH = d_WabTh + (size_t)q * 2560;
    const uint4* sL = d_WabTl + (size_t)q * 2560;
    #pragma unroll
    for (int i = 0; i < 10; ++i) {
        int idx = t + 256 * i, n = idx >> 3, seg = idx & 7;
        uint32_t o = n * RS + seg * 16;
        cp16(bh + o, sH + idx);
        cp16(bl + o, sL + idx);
    }
}

__device__ __forceinline__ void ldgRow(const float4* grow, int kb0, float4 x[2]) {
    #pragma unroll
    for (int u = 0; u < 2; ++u) {
        int kb = kb0 + 4 * u;
        x[u] = (kb < GI) ? grow[kb >> 2] : make_float4(0.f, 0.f, 0.f, 0.f);
    }
}
__device__ __forceinline__ void stsRow(unsigned char* Ah, unsigned char* Al,
                                       int r, int koff, const float4 x[2]) {
    #pragma unroll
    for (int u = 0; u < 2; ++u) {
        ull hu, lu; split4(x[u], hu, lu);
        uint32_t off = (uint32_t)(r * RS + (koff + 4 * u) * 2);
        *(ull*)(Ah + off) = hu;
        *(ull*)(Al + off) = lu;
    }
}

__global__ __launch_bounds__(256) void gemm_ab_pipe(const float* __restrict__ g, int N) {
    extern __shared__ unsigned char sm[];
    uint32_t sb = smem_to_u32(sm);
    int t = threadIdx.x, wid = t >> 5, lane = t & 31;
    int g4 = lane >> 2, tq = lane & 3;
    int wr = wid >> 2, wc = wid & 3;
    int rowbase = wr * 32, colbase = wc * 80;
    int n0 = blockIdx.x * 64;
    int r = t >> 2, qd = t & 3, kth = 16 * qd;
    int row = n0 + r; if (row >= N) row = N - 1;
    const float4* grow = (const float4*)(g + (size_t)row * GI);

    float acc[2][10][4];
    #pragma unroll
    for (int mi = 0; mi < 2; ++mi)
        #pragma unroll
        for (int f = 0; f < 10; ++f)
            #pragma unroll
            for (int e = 0; e < 4; ++e) acc[mi][f][e] = 0.f;

    // prologue: stage chunk 0
    {
        float4 x[2];
        ldgRow(grow, kth, x);      stsRow(sm, sm + 9216, r, kth, x);
        ldgRow(grow, kth + 8, x);  stsRow(sm, sm + 9216, r, kth + 8, x);
        cpB_T1(sb + T1_B, sb + T1_B + 46080, 0, t);
        CP_COMMIT(); CP_WAIT0();
    }
    __syncthreads();

    for (int q = 0; q < NCH; ++q) {
        int cb = q & 1, nb = cb ^ 1;
        uint32_t Ah = sb + cb * 18432;
        uint32_t Al = Ah + 9216;
        uint32_t Bh = sb + T1_B + cb * 92160;
        uint32_t Bl = Bh + 46080;
        unsigned char* nAh = sm + nb * 18432;
        unsigned char* nAl = nAh + 9216;
        bool more = (q + 1 < NCH);
        if (more) { cpB_T1(sb + T1_B + nb * 92160, sb + T1_B + nb * 92160 + 46080, q + 1, t); CP_COMMIT(); }
        float4 x0[2], x1[2];
        int kn = (q + 1) * 64 + kth;
        if (more) ldgRow(grow, kn, x0);
        mma_chunk(acc, Ah, Al, Bh, Bl, 0, rowbase, colbase, lane);
        mma_chunk(acc, Ah, Al, Bh, Bl, 1, rowbase, colbase, lane);
        if (more) { stsRow(nAh, nAl, r, kth, x0); ldgRow(grow, kn + 8, x1); }
        mma_chunk(acc, Ah, Al, Bh, Bl, 2, rowbase, colbase, lane);
        mma_chunk(acc, Ah, Al, Bh, Bl, 3, rowbase, colbase, lane);
        if (more) { stsRow(nAh, nAl, r, kth + 8, x1); CP_WAIT0(); }
        __syncthreads();
    }

    #pragma unroll
    for (int mi = 0; mi < 2; ++mi) {
        #pragma unroll
        for (int f = 0; f < 10; ++f) {
            int rr = rowbase + mi * 16 + g4;
            int col = colbase + f * 8 + 2 * tq;
            int n = n0 + rr;
            if (n < N)
                *(float2*)(d_AB + (size_t)n * ABS + col) = make_float2(acc[mi][f][0], acc[mi][f][1]);
            n = n0 + rr + 8;
            if (n < N)
                *(float2*)(d_AB + (size_t)n * ABS + col) = make_float2(acc[mi][f][2], acc[mi][f][3]);
        }
    }
}

// ===================== T2 fused: bilinear MMA + epilogue + layers 2-3 =====================
#define F_W3   2560
#define F_A    4096
#define F_B    77824
#define F_STG  4096
#define F_WS   90112
#define F_SMEM 169984
#define SSTR   168

__device__ __forceinline__ void cpB_T2(uint32_t bh, uint32_t bl, int q, int t) {
    const uint4* sH = d_WcTh + (size_t)q * 1280;
    const uint4* sL = d_WcTl + (size_t)q * 1280;
    #pragma unroll
    for (int i = 0; i < 5; ++i) {
        int idx = t + 256 * i, n = idx >> 3, seg = idx & 7;
        uint32_t o = n * RS + seg * 16;
        cp16(bh + o, sH + idx);
        cp16(bl + o, sL + idx);
    }
}

__device__ __forceinline__ void ldgPair(const float4* ir, const float4* jr, int kb0,
                                        float4 xi[4], float4 xj[4]) {
    #pragma unroll
    for (int u = 0; u < 4; ++u) {
        int kb = kb0 + 4 * u;
        if (kb < GI) { xi[u] = ir[kb >> 2]; xj[u] = jr[kb >> 2]; }
        else { xi[u] = make_float4(0.f, 0.f, 0.f, 0.f); xj[u] = make_float4(0.f, 0.f, 0.f, 0.f); }
    }
}
__device__ __forceinline__ void stsPair(unsigned char* Ah, unsigned char* Al,
                                        int r, int koff, const float4 xi[4], const float4 xj[4]) {
    #pragma unroll
    for (int u = 0; u < 4; ++u) {
        float4 p4 = make_float4(xi[u].x * xj[u].x, xi[u].y * xj[u].y,
                                xi[u].z * xj[u].z, xi[u].w * xj[u].w);
        ull hu, lu; split4(p4, hu, lu);
        uint32_t off = (uint32_t)(r * RS + (koff + 4 * u) * 2);
        *(ull*)(Ah + off) = hu;
        *(ull*)(Al + off) = lu;
    }
}

__global__ __launch_bounds__(256) void bilinear_fused(
    const float* __restrict__ g,  const float* __restrict__ ms,
    const float* __restrict__ W2, const float* __restrict__ b2,
    const float* __restrict__ W3, const float* __restrict__ b3,
    const int* __restrict__ mid,  const int* __restrict__ aid,
    const int* __restrict__ did,  const int* __restrict__ gid,
    const int* __restrict__ sid,
    float* __restrict__ out, int P)
{
    extern __shared__ unsigned char sm[];
    uint32_t sb = smem_to_u32(sm);
    int t = threadIdx.x, wid = t >> 5, lane = t & 31;
    int g4 = lane >> 2, tq = lane & 3;
    int wr = wid >> 1, wc = wid & 1;
    int rowbase = wr * 32, colbase = wc * 80;
    int p0 = blockIdx.x * 128;
    int* sm_m = (int*)sm;
    int* sm_a = (int*)(sm + 512);
    int* sm_d = (int*)(sm + 1024);
    int* sm_g = (int*)(sm + 1536);
    int* sm_s = (int*)(sm + 2048);
    float* w3s = (float*)(sm + F_W3);

    if (t < 128) {
        int p = p0 + t; if (p >= P) p = P - 1;
        sm_m[t] = mid[p]; sm_a[t] = aid[p]; sm_d[t] = did[p]; sm_g[t] = gid[p]; sm_s[t] = sid[p];
    }
    if (t < CPAD) w3s[t] = (t < HID) ? W3[t] : 0.f;
    __syncthreads();

    int r = t >> 1, kth = 32 * (t & 1);
    const float4* ir = (const float4*)(g + (size_t)sm_m[r] * GI);
    const float4* jr = (const float4*)(g + (size_t)sm_a[r] * GI);

    float acc[2][10][4];
    #pragma unroll
    for (int mi = 0; mi < 2; ++mi)
        #pragma unroll
        for (int f = 0; f < 10; ++f)
            #pragma unroll
            for (int e = 0; e < 4; ++e) acc[mi][f][e] = 0.f;

    // prologue: stage chunk 0
    {
        float4 xi[4], xj[4];
        ldgPair(ir, jr, kth, xi, xj);
        stsPair(sm + F_A, sm + F_A + 18432, r, kth, xi, xj);
        ldgPair(ir, jr, kth + 16, xi, xj);
        stsPair(sm + F_A, sm + F_A + 18432, r, kth + 16, xi, xj);
        cpB_T2(sb + F_B, sb + F_B + 23040, 0, t);
        CP_COMMIT(); CP_WAIT0();
    }
    __syncthreads();

    for (int q = 0; q < NCH; ++q) {
        int cb = q & 1, nb = cb ^ 1;
        uint32_t Ah = sb + F_A + cb * 36864;
        uint32_t Al = Ah + 18432;
        uint32_t Bh = sb + F_B + cb * 46080;
        uint32_t Bl = Bh + 23040;
        unsigned char* nAh = sm + F_A + nb * 36864;
        unsigned char* nAl = nAh + 18432;
        bool more = (q + 1 < NCH);
        if (more) { cpB_T2(sb + F_B + nb * 46080, sb + F_B + nb * 46080 + 23040, q + 1, t); CP_COMMIT(); }
        float4 xi[4], xj[4];
        int kn = (q + 1) * 64 + kth;
        if (more) ldgPair(ir, jr, kn, xi, xj);
        mma_chunk(acc, Ah, Al, Bh, Bl, 0, rowbase, colbase, lane);
        mma_chunk(acc, Ah, Al, Bh, Bl, 1, rowbase, colbase, lane);
        if (more) { stsPair(nAh, nAl, r, kth, xi, xj); ldgPair(ir, jr, kn + 16, xi, xj); }
        mma_chunk(acc, Ah, Al, Bh, Bl, 2, rowbase, colbase, lane);
        mma_chunk(acc, Ah, Al, Bh, Bl, 3, rowbase, colbase, lane);
        if (more) { stsPair(nAh, nAl, r, kth + 16, xi, xj); CP_WAIT0(); }
        __syncthreads();
    }

    // ---- stage acc -> smem [128 x 168] ----
    float* stg = (float*)(sm + F_STG);
    #pragma unroll
    for (int mi = 0; mi < 2; ++mi) {
        #pragma unroll
        for (int f = 0; f < 10; ++f) {
            int rr = rowbase + mi * 16 + g4;
            int col = colbase + f * 8 + 2 * tq;
            *(float2*)(stg + rr * SSTR + col) = make_float2(acc[mi][f][0], acc[mi][f][1]);
            *(float2*)(stg + (rr + 8) * SSTR + col) = make_float2(acc[mi][f][2], acc[mi][f][3]);
        }
    }
    __syncthreads();

    // ---- epilogue 1: h1 = relu(bil + AB[m] + AB[a]+160 + Dt + Gt + St), in place ----
    int tx = t & 15, ty = t >> 4;
    {
        const float2* AB2 = (const float2*)d_AB;   // row stride 160 float2
        const float2* Dt2 = (const float2*)d_Dt;
        const float2* Gt2 = (const float2*)d_Gt;
        const float2* St2 = (const float2*)d_St;
        #pragma unroll
        for (int j = 0; j < 8; ++j) {
            int rr = ty * 8 + j;
            const float2* am = AB2 + (size_t)sm_m[rr] * 160;
            const float2* bm = AB2 + (size_t)sm_a[rr] * 160 + 80;
            const float2* dp = Dt2 + sm_d[rr] * 80;
            const float2* gp = Gt2 + sm_g[rr] * 80;
            const float2* sp = St2 + sm_s[rr] * 80;
            #pragma unroll
            for (int c = 0; c < 5; ++c) {
                int cp = tx + 16 * c;
                float2 v  = *(float2*)(stg + rr * SSTR + 2 * cp);
                float2 t1 = am[cp], t2 = bm[cp], t3 = dp[cp], t4 = gp[cp], t5 = sp[cp];
                v.x = fmaxf(v.x + t1.x + t2.x + t3.x + t4.x + t5.x, 0.f);
                v.y = fmaxf(v.y + t1.y + t2.y + t3.y + t4.y + t5.y, 0.f);
                *(float2*)(stg + rr * SSTR + 2 * cp) = v;
            }
        }
    }

    // ---- layer 2: h2pre = h1 @ W2 (scalar f32x2) ----
    ull* Ws = (ull*)(sm + F_WS);
    ull acc2[8][5];
    #pragma unroll
    for (int j = 0; j < 8; ++j)
        #pragma unroll
        for (int c = 0; c < 5; ++c) acc2[j][c] = 0ull;

    for (int k0 = 0; k0 < CPAD; k0 += 16) {
        __syncthreads();
        {
            int k = k0 + ty;
            #pragma unroll
            for (int i = 0; i < 5; ++i) {
                int cp = tx + 16 * i, c0 = 2 * cp;
                ull w = 0ull;
                if (k < HID) {
                    float lo = (c0     < HID) ? W2[k * HID + c0    ] : 0.f;
                    float hi = (c0 + 1 < HID) ? W2[k * HID + c0 + 1] : 0.f;
                    w = pk(lo, hi);
                }
                Ws[ty * 80 + cp] = w;
            }
        }
        __syncthreads();
        #pragma unroll
        for (int kk = 0; kk < 16; ++kk) {
            ull qq[8];
            #pragma unroll
            for (int j = 0; j < 8; ++j) qq[j] = bcast2(stg[(ty * 8 + j) * SSTR + k0 + kk]);
            #pragma unroll
            for (int c = 0; c < 5; ++c) {
                ull w = Ws[kk * 80 + tx + 16 * c];
                #pragma unroll
                for (int j = 0; j < 8; ++j) fma2(acc2[j][c], qq[j], w);
            }
        }
    }

    // ---- epilogue 2: relu(h2pre + b2) @ W3 + b3 + ms[m] + ms[a] ----
    float b3v = b3[0];
    float part[8] = {0.f, 0.f, 0.f, 0.f, 0.f, 0.f, 0.f, 0.f};
    #pragma unroll
    for (int c = 0; c < 5; ++c) {
        int c0 = 2 * (tx + 16 * c);
        float w3a = w3s[c0], w3b = w3s[c0 + 1];
        float b2a = (c0     < HID) ? b2[c0    ] : 0.f;
        float b2b = (c0 + 1 < HID) ? b2[c0 + 1] : 0.f;
        #pragma unroll
        for (int j = 0; j < 8; ++j) {
            float2 v = unpk(acc2[j][c]);
            part[j] += fmaxf(v.x + b2a, 0.f) * w3a + fmaxf(v.y + b2b, 0.f) * w3b;
        }
    }
    #pragma unroll
    for (int j = 0; j < 8; ++j) {
        #pragma unroll
        for (int off = 8; off > 0; off >>= 1)
            part[j] += __shfl_xor_sync(0xffffffffu, part[j], off);
    }
    if (tx == 0) {
        #pragma unroll
        for (int j = 0; j < 8; ++j) {
            int rr = ty * 8 + j;
            int p = p0 + rr;
            if (p < P)
                out[p] = part[j] + b3v + ms[sm_m[rr]] + ms[sm_a[rr]];
        }
    }
}

// ===================== launch =====================

extern "C" void kernel_launch(void* const* d_in, const int* in_sizes, int n_in,
                              void* d_out, int out_size)
{
    const float* g_i = (const float*)d_in[0];
    const float* ms  = (const float*)d_in[1];
    const float* de  = (const float*)d_in[2];
    const float* ge  = (const float*)d_in[3];
    const float* se  = (const float*)d_in[4];
    const float* W1  = (const float*)d_in[5];
    const float* b1  = (const float*)d_in[6];
    const float* W2  = (const float*)d_in[7];
    const float* b2  = (const float*)d_in[8];
    const float* W3  = (const float*)d_in[9];
    const float* b3  = (const float*)d_in[10];
    const int*   mid = (const int*)d_in[11];
    const int*   aid = (const int*)d_in[12];
    const int*   did = (const int*)d_in[13];
    const int*   gid = (const int*)d_in[14];
    const int*   sid = (const int*)d_in[15];

    int N = in_sizes[0] / GI;
    if (N > NMAX) N = NMAX;
    int P = in_sizes[11];
    if (P > PMAX) P = PMAX;
    float* out = (float*)d_out;

    prep_wtiles<<<NCH, 256>>>(W1);
    prep_tabs<<<1, CPAD>>>(de, ge, se, W1, b1);

    cudaFuncSetAttribute(gemm_ab_pipe, cudaFuncAttributeMaxDynamicSharedMemorySize, T1_SMEM);
    gemm_ab_pipe<<<(N + 63) / 64, 256, T1_SMEM>>>(g_i, N);

    cudaFuncSetAttribute(bilinear_fused, cudaFuncAttributeMaxDynamicSharedMemorySize, F_SMEM);
    bilinear_fused<<<(P + 127) / 128, 256, F_SMEM>>>(g_i, ms, W2, b2, W3, b3,
                                                     mid, aid, did, gid, sid, out, P);
}

// round 9
// speedup vs baseline: 1.7667x; 1.0608x over previous
#include <cuda_runtime.h>
#include <cuda_bf16.h>
#include <cstdint>

typedef unsigned long long ull;

#define GI   1220
#define HID  150
#define NMAX 50000
#define PMAX 100000
#define CPAD 160
#define ABS  320
#define NCH  20        // K chunks of 64 (padded to 1280)
#define RS   144       // smem row stride (bytes) for bf16 tiles -> conflict-free LDSM

// ===================== device scratch (no allocations allowed) =====================
__device__ float d_AB[(size_t)NMAX * ABS];     // 64 MB: per-mention  g@[W1a|W1b]
__device__ uint4 d_WcTh[NCH * 20480 / 16];     // W1c^T bf16-hi tiles [160 x 64] per chunk
__device__ uint4 d_WcTl[NCH * 20480 / 16];     // bf16-lo
__device__ uint4 d_WabTh[NCH * 40960 / 16];    // [W1a|pad|W1b|pad]^T tiles [320 x 64] per chunk
__device__ uint4 d_WabTl[NCH * 40960 / 16];
__device__ float d_Dt[9 * CPAD];               // dist table (+b1)
__device__ float d_Gt[8 * CPAD];
__device__ float d_St[3 * CPAD];

// ===================== helpers =====================
__device__ __forceinline__ uint32_t smem_to_u32(const void* p) {
    uint32_t a;
    asm("{ .reg .u64 t; cvta.to.shared.u64 t, %1; cvt.u32.u64 %0, t; }" : "=r"(a) : "l"(p));
    return a;
}

__device__ __forceinline__ void mma16816(float c[4],
                                         uint32_t a0, uint32_t a1, uint32_t a2, uint32_t a3,
                                         uint32_t b0, uint32_t b1) {
    asm volatile(
        "mma.sync.aligned.m16n8k16.row.col.f32.bf16.bf16.f32 "
        "{%0,%1,%2,%3}, {%4,%5,%6,%7}, {%8,%9}, {%0,%1,%2,%3};"
        : "+f"(c[0]), "+f"(c[1]), "+f"(c[2]), "+f"(c[3])
        : "r"(a0), "r"(a1), "r"(a2), "r"(a3), "r"(b0), "r"(b1));
}

__device__ __forceinline__ void ldsm4(uint32_t r[4], uint32_t addr) {
    asm volatile("ldmatrix.sync.aligned.m8n8.x4.shared.b16 {%0,%1,%2,%3}, [%4];"
        : "=r"(r[0]), "=r"(r[1]), "=r"(r[2]), "=r"(r[3]) : "r"(addr));
}
__device__ __forceinline__ void ldsm2(uint32_t r[2], uint32_t addr) {
    asm volatile("ldmatrix.sync.aligned.m8n8.x2.shared.b16 {%0,%1}, [%2];"
        : "=r"(r[0]), "=r"(r[1]) : "r"(addr));
}

__device__ __forceinline__ void cp16(uint32_t dst, const void* src) {
    asm volatile("cp.async.cg.shared.global [%0], [%1], 16;" :: "r"(dst), "l"(src));
}
#define CP_COMMIT() asm volatile("cp.async.commit_group;" ::: "memory")
#define CP_WAIT0()  asm volatile("cp.async.wait_group 0;" ::: "memory")

union BPack { __nv_bfloat16 v[4]; ull u; };
__device__ __forceinline__ void split4(float4 x, ull& hu, ull& lu) {
    BPack H, L;
    float p[4] = {x.x, x.y, x.z, x.w};
    #pragma unroll
    for (int i = 0; i < 4; ++i) {
        __nv_bfloat16 h = __float2bfloat16(p[i]);
        H.v[i] = h;
        L.v[i] = __float2bfloat16(p[i] - __bfloat162float(h));
    }
    hu = H.u; lu = L.u;
}

// packed f32x2 helpers (scalar tail)
__device__ __forceinline__ void fma2(ull& d, ull a, ull b) {
    asm("fma.rn.f32x2 %0, %1, %2, %0;" : "+l"(d) : "l"(a), "l"(b));
}
__device__ __forceinline__ ull bcast2(float x) {
    ull r; asm("mov.b64 %0, {%1, %1};" : "=l"(r) : "f"(x)); return r;
}
__device__ __forceinline__ ull pk(float x, float y) {
    ull r; asm("mov.b64 %0, {%1, %2};" : "=l"(r) : "f"(x), "f"(y)); return r;
}
__device__ __forceinline__ float2 unpk(ull v) {
    float2 r; asm("mov.b64 {%0, %1}, %2;" : "=f"(r.x), "=f"(r.y) : "l"(v)); return r;
}

// MMA inner step, 32-row x 40-col warp tile: 2 m-frags x 5 n-frags, 3 split passes.
__device__ __forceinline__ void mma_chunk5(float (*acc)[5][4],
        uint32_t Ah, uint32_t Al, uint32_t Bh, uint32_t Bl,
        int s, int rowbase, int colbase, int lane) {
    int kb2 = s * 32;
    int l7 = lane & 7, g = lane >> 3;
    uint32_t aoff = (uint32_t)((rowbase + (g & 1) * 8 + l7) * RS + kb2 + (g >> 1) * 16);
    uint32_t ah[2][4], al[2][4];
    ldsm4(ah[0], Ah + aoff);
    ldsm4(ah[1], Ah + aoff + 16 * RS);
    ldsm4(al[0], Al + aoff);
    ldsm4(al[1], Al + aoff + 16 * RS);
    uint32_t boff = (uint32_t)((colbase + (g >> 1) * 8 + l7) * RS + kb2 + (g & 1) * 16);
    #pragma unroll
    for (int fp = 0; fp < 2; ++fp) {
        uint32_t bh[4], bl[4];
        ldsm4(bh, Bh + boff + fp * 16 * RS);
        ldsm4(bl, Bl + boff + fp * 16 * RS);
        #pragma unroll
        for (int half = 0; half < 2; ++half) {
            int f = fp * 2 + half;
            uint32_t b0h = bh[half * 2], b1h = bh[half * 2 + 1];
            uint32_t b0l = bl[half * 2], b1l = bl[half * 2 + 1];
            #pragma unroll
            for (int mi = 0; mi < 2; ++mi) {
                mma16816(acc[mi][f], ah[mi][0], ah[mi][1], ah[mi][2], ah[mi][3], b0h, b1h);
                mma16816(acc[mi][f], al[mi][0], al[mi][1], al[mi][2], al[mi][3], b0h, b1h);
                mma16816(acc[mi][f], ah[mi][0], ah[mi][1], ah[mi][2], ah[mi][3], b0l, b1l);
            }
        }
    }
    // n-frag 4 via ldmatrix.x2
    uint32_t boff2 = (uint32_t)((colbase + 32 + l7) * RS + kb2 + ((lane >> 3) & 1) * 16);
    uint32_t bh2[2], bl2[2];
    ldsm2(bh2, Bh + boff2);
    ldsm2(bl2, Bl + boff2);
    #pragma unroll
    for (int mi = 0; mi < 2; ++mi) {
        mma16816(acc[mi][4], ah[mi][0], ah[mi][1], ah[mi][2], ah[mi][3], bh2[0], bh2[1]);
        mma16816(acc[mi][4], al[mi][0], al[mi][1], al[mi][2], al[mi][3], bh2[0], bh2[1]);
        mma16816(acc[mi][4], ah[mi][0], ah[mi][1], ah[mi][2], ah[mi][3], bl2[0], bl2[1]);
    }
}

// ===================== weight prep: transpose + bf16 split =====================

__global__ void prep_wtiles(const float* __restrict__ W1) {
    int q = blockIdx.x;   // K-chunk
    int t = threadIdx.x;
    __nv_bfloat16* ch = (__nv_bfloat16*)d_WcTh;
    __nv_bfloat16* cl = (__nv_bfloat16*)d_WcTl;
    for (int idx = t; idx < 160 * 64; idx += 256) {
        int n = idx >> 6, kk = idx & 63, k = q * 64 + kk;
        float v = (k < GI && n < HID) ? W1[(2 * GI + k) * HID + n] : 0.f;
        __nv_bfloat16 h = __float2bfloat16(v);
        float l = v - __bfloat162float(h);
        size_t e = (size_t)q * 10240 + (size_t)n * 64 + kk;
        ch[e] = h; cl[e] = __float2bfloat16(l);
    }
    __nv_bfloat16* ah = (__nv_bfloat16*)d_WabTh;
    __nv_bfloat16* al = (__nv_bfloat16*)d_WabTl;
    for (int idx = t; idx < 320 * 64; idx += 256) {
        int n = idx >> 6, kk = idx & 63, k = q * 64 + kk;
        float v = 0.f;
        if (k < GI) {
            if (n < HID)                        v = W1[k * HID + n];
            else if (n >= 160 && n < 160 + HID) v = W1[(GI + k) * HID + (n - 160)];
        }
        __nv_bfloat16 h = __float2bfloat16(v);
        float l = v - __bfloat162float(h);
        size_t e = (size_t)q * 20480 + (size_t)n * 64 + kk;
        ah[e] = h; al[e] = __float2bfloat16(l);
    }
}

__global__ void prep_tabs(const float* __restrict__ de, const float* __restrict__ ge,
                          const float* __restrict__ se, const float* __restrict__ W1,
                          const float* __restrict__ b1) {
    int c = threadIdx.x;     // 0..159
    for (int d = 0; d < 9; ++d) {
        float v = 0.f;
        if (c < HID) {
            v = b1[c];
            for (int t = 0; t < 20; ++t) v += de[d*20 + t] * W1[(3*GI + t) * HID + c];
        }
        d_Dt[d * CPAD + c] = v;
    }
    for (int g = 0; g < 8; ++g) {
        float v = 0.f;
        if (c < HID)
            for (int t = 0; t < 20; ++t) v += ge[g*20 + t] * W1[(3*GI + 20 + t) * HID + c];
        d_Gt[g * CPAD + c] = v;
    }
    for (int s = 0; s < 3; ++s) {
        float v = 0.f;
        if (c < HID)
            for (int t = 0; t < 20; ++t) v += se[s*20 + t] * W1[(3*GI + 40 + t) * HID + c];
        d_St[s * CPAD + c] = v;
    }
}

// ===================== T1: AB = g @ [W1a|W1b]  (64 x 320 / CTA, 512 threads) =====================
// smem: A bufs @0 (2 x 18432: h 9216 + l 9216), B bufs @36864 (2 x 92160: h 46080 + l 46080)
#define T1_B    36864
#define T1_SMEM 221184

__device__ __forceinline__ void cpB_T1(uint32_t bh, uint32_t bl, int q, int t) {
    const uint4* sH = d_WabTh + (size_t)q * 2560;
    const uint4* sL = d_WabTl + (size_t)q * 2560;
    #pragma unroll
    for (int i = 0; i < 5; ++i) {
        int idx = t + 512 * i, n = idx >> 3, seg = idx & 7;
        uint32_t o = n * RS + seg * 16;
        cp16(bh + o, sH + idx);
        cp16(bl + o, sL + idx);
    }
}

__device__ __forceinline__ void ldgRow(const float4* grow, int kb0, float4 x[2]) {
    #pragma unroll
    for (int u = 0; u < 2; ++u) {
        int kb = kb0 + 4 * u;
        x[u] = (kb < GI) ? grow[kb >> 2] : make_float4(0.f, 0.f, 0.f, 0.f);
    }
}
__device__ __forceinline__ void stsRow(unsigned char* Ah, unsigned char* Al,
                                       int r, int koff, const float4 x[2]) {
    #pragma unroll
    for (int u = 0; u < 2; ++u) {
        ull hu, lu; split4(x[u], hu, lu);
        uint32_t off = (uint32_t)(r * RS + (koff + 4 * u) * 2);
        *(ull*)(Ah + off) = hu;
        *(ull*)(Al + off) = lu;
    }
}

__global__ __launch_bounds__(512, 1) void gemm_ab_pipe(const float* __restrict__ g, int N) {
    extern __shared__ unsigned char sm[];
    uint32_t sb = smem_to_u32(sm);
    int t = threadIdx.x, wid = t >> 5, lane = t & 31;
    int g4 = lane >> 2, tq = lane & 3;
    int wr = wid & 1, wc = wid >> 1;              // 2 x 8 warp grid (32 x 40 tiles)
    int rowbase = wr * 32, colbase = wc * 40;
    int n0 = blockIdx.x * 64;
    int r = t >> 3, q8 = t & 7, kth = 8 * q8;     // A staging: 64 rows, 8 floats/thread
    int row = n0 + r; if (row >= N) row = N - 1;
    const float4* grow = (const float4*)(g + (size_t)row * GI);

    float acc[2][5][4];
    #pragma unroll
    for (int mi = 0; mi < 2; ++mi)
        #pragma unroll
        for (int f = 0; f < 5; ++f)
            #pragma unroll
            for (int e = 0; e < 4; ++e) acc[mi][f][e] = 0.f;

    // prologue: stage chunk 0
    {
        float4 x[2];
        ldgRow(grow, kth, x);
        stsRow(sm, sm + 9216, r, kth, x);
        cpB_T1(sb + T1_B, sb + T1_B + 46080, 0, t);
        CP_COMMIT(); CP_WAIT0();
    }
    __syncthreads();

    for (int q = 0; q < NCH; ++q) {
        int cb = q & 1, nb = cb ^ 1;
        uint32_t Ah = sb + cb * 18432;
        uint32_t Al = Ah + 9216;
        uint32_t Bh = sb + T1_B + cb * 92160;
        uint32_t Bl = Bh + 46080;
        unsigned char* nAh = sm + nb * 18432;
        unsigned char* nAl = nAh + 9216;
        bool more = (q + 1 < NCH);
        if (more) { cpB_T1(sb + T1_B + nb * 92160, sb + T1_B + nb * 92160 + 46080, q + 1, t); CP_COMMIT(); }
        float4 x0[2];
        int kn = (q + 1) * 64 + kth;
        if (more) ldgRow(grow, kn, x0);
        mma_chunk5(acc, Ah, Al, Bh, Bl, 0, rowbase, colbase, lane);
        mma_chunk5(acc, Ah, Al, Bh, Bl, 1, rowbase, colbase, lane);
        mma_chunk5(acc, Ah, Al, Bh, Bl, 2, rowbase, colbase, lane);
        mma_chunk5(acc, Ah, Al, Bh, Bl, 3, rowbase, colbase, lane);
        if (more) { stsRow(nAh, nAl, r, kth, x0); CP_WAIT0(); }
        __syncthreads();
    }

    #pragma unroll
    for (int mi = 0; mi < 2; ++mi) {
        #pragma unroll
        for (int f = 0; f < 5; ++f) {
            int rr = rowbase + mi * 16 + g4;
            int col = colbase + f * 8 + 2 * tq;
            int n = n0 + rr;
            if (n < N)
                *(float2*)(d_AB + (size_t)n * ABS + col) = make_float2(acc[mi][f][0], acc[mi][f][1]);
            n = n0 + rr + 8;
            if (n < N)
                *(float2*)(d_AB + (size_t)n * ABS + col) = make_float2(acc[mi][f][2], acc[mi][f][3]);
        }
    }
}

// ===================== T2 fused: bilinear MMA + epilogue + layers 2-3 (512 threads) =====================
#define F_W3   2560
#define F_A    4096
#define F_B    77824
#define F_STG  4096
#define F_WS   90112
#define F_SMEM 169984
#define SSTR   168

__device__ __forceinline__ void cpB_T2(uint32_t bh, uint32_t bl, int q, int t) {
    const uint4* sH = d_WcTh + (size_t)q * 1280;
    const uint4* sL = d_WcTl + (size_t)q * 1280;
    #pragma unroll
    for (int i = 0; i < 3; ++i) {
        int idx = t + 512 * i;
        if (idx < 1280) {
            int n = idx >> 3, seg = idx & 7;
            uint32_t o = n * RS + seg * 16;
            cp16(bh + o, sH + idx);
            cp16(bl + o, sL + idx);
        }
    }
}

__device__ __forceinline__ void ldgPair(const float4* ir, const float4* jr, int kb0,
                                        float4 xi[2], float4 xj[2]) {
    #pragma unroll
    for (int u = 0; u < 2; ++u) {
        int kb = kb0 + 4 * u;
        if (kb < GI) { xi[u] = ir[kb >> 2]; xj[u] = jr[kb >> 2]; }
        else { xi[u] = make_float4(0.f, 0.f, 0.f, 0.f); xj[u] = make_float4(0.f, 0.f, 0.f, 0.f); }
    }
}
__device__ __forceinline__ void stsPair(unsigned char* Ah, unsigned char* Al,
                                        int r, int koff, const float4 xi[2], const float4 xj[2]) {
    #pragma unroll
    for (int u = 0; u < 2; ++u) {
        float4 p4 = make_float4(xi[u].x * xj[u].x, xi[u].y * xj[u].y,
                                xi[u].z * xj[u].z, xi[u].w * xj[u].w);
        ull hu, lu; split4(p4, hu, lu);
        uint32_t off = (uint32_t)(r * RS + (koff + 4 * u) * 2);
        *(ull*)(Ah + off) = hu;
        *(ull*)(Al + off) = lu;
    }
}

__global__ __launch_bounds__(512, 1) void bilinear_fused(
    const float* __restrict__ g,  const float* __restrict__ ms,
    const float* __restrict__ W2, const float* __restrict__ b2,
    const float* __restrict__ W3, const float* __restrict__ b3,
    const int* __restrict__ mid,  const int* __restrict__ aid,
    const int* __restrict__ did,  const int* __restrict__ gid,
    const int* __restrict__ sid,
    float* __restrict__ out, int P)
{
    extern __shared__ unsigned char sm[];
    uint32_t sb = smem_to_u32(sm);
    int t = threadIdx.x, wid = t >> 5, lane = t & 31;
    int g4 = lane >> 2, tq = lane & 3;
    int wr = wid >> 2, wc = wid & 3;              // 4 x 4 warp grid (32 x 40 tiles)
    int rowbase = wr * 32, colbase = wc * 40;
    int p0 = blockIdx.x * 128;
    int* sm_m = (int*)sm;
    int* sm_a = (int*)(sm + 512);
    int* sm_d = (int*)(sm + 1024);
    int* sm_g = (int*)(sm + 1536);
    int* sm_s = (int*)(sm + 2048);
    float* w3s = (float*)(sm + F_W3);

    if (t < 128) {
        int p = p0 + t; if (p >= P) p = P - 1;
        sm_m[t] = mid[p]; sm_a[t] = aid[p]; sm_d[t] = did[p]; sm_g[t] = gid[p]; sm_s[t] = sid[p];
    }
    if (t < CPAD) w3s[t] = (t < HID) ? W3[t] : 0.f;
    __syncthreads();

    int r = t >> 2, q4 = t & 3, kth = 16 * q4;    // A staging: 128 rows, 16 floats/thread
    const float4* ir = (const float4*)(g + (size_t)sm_m[r] * GI);
    const float4* jr = (const float4*)(g + (size_t)sm_a[r] * GI);

    float acc[2][5][4];
    #pragma unroll
    for (int mi = 0; mi < 2; ++mi)
        #pragma unroll
        for (int f = 0; f < 5; ++f)
            #pragma unroll
            for (int e = 0; e < 4; ++e) acc[mi][f][e] = 0.f;

    // prologue: stage chunk 0
    {
        float4 xi[2], xj[2];
        ldgPair(ir, jr, kth, xi, xj);
        stsPair(sm + F_A, sm + F_A + 18432, r, kth, xi, xj);
        ldgPair(ir, jr, kth + 8, xi, xj);
        stsPair(sm + F_A, sm + F_A + 18432, r, kth + 8, xi, xj);
        cpB_T2(sb + F_B, sb + F_B + 23040, 0, t);
        CP_COMMIT(); CP_WAIT0();
    }
    __syncthreads();

    for (int q = 0; q < NCH; ++q) {
        int cb = q & 1, nb = cb ^ 1;
        uint32_t Ah = sb + F_A + cb * 36864;
        uint32_t Al = Ah + 18432;
        uint32_t Bh = sb + F_B + cb * 46080;
        uint32_t Bl = Bh + 23040;
        unsigned char* nAh = sm + F_A + nb * 36864;
        unsigned char* nAl = nAh + 18432;
        bool more = (q + 1 < NCH);
        if (more) { cpB_T2(sb + F_B + nb * 46080, sb + F_B + nb * 46080 + 23040, q + 1, t); CP_COMMIT(); }
        float4 xi[2], xj[2], yi[2], yj[2];
        int kn = (q + 1) * 64 + kth;
        if (more) ldgPair(ir, jr, kn, xi, xj);
        mma_chunk5(acc, Ah, Al, Bh, Bl, 0, rowbase, colbase, lane);
        mma_chunk5(acc, Ah, Al, Bh, Bl, 1, rowbase, colbase, lane);
        if (more) { stsPair(nAh, nAl, r, kth, xi, xj); ldgPair(ir, jr, kn + 8, yi, yj); }
        mma_chunk5(acc, Ah, Al, Bh, Bl, 2, rowbase, colbase, lane);
        mma_chunk5(acc, Ah, Al, Bh, Bl, 3, rowbase, colbase, lane);
        if (more) { stsPair(nAh, nAl, r, kth + 8, yi, yj); CP_WAIT0(); }
        __syncthreads();
    }

    // ---- stage acc -> smem [128 x 168] ----
    float* stg = (float*)(sm + F_STG);
    #pragma unroll
    for (int mi = 0; mi < 2; ++mi) {
        #pragma unroll
        for (int f = 0; f < 5; ++f) {
            int rr = rowbase + mi * 16 + g4;
            int col = colbase + f * 8 + 2 * tq;
            *(float2*)(stg + rr * SSTR + col) = make_float2(acc[mi][f][0], acc[mi][f][1]);
            *(float2*)(stg + (rr + 8) * SSTR + col) = make_float2(acc[mi][f][2], acc[mi][f][3]);
        }
    }
    __syncthreads();

    // ---- epilogue 1: h1 = relu(bil + AB[m] + AB[a]+160 + Dt + Gt + St), in place ----
    int tx = t & 15, ty = t >> 4;                 // ty 0..31: 4 rows each
    {
        const float2* AB2 = (const float2*)d_AB;   // row stride 160 float2
        const float2* Dt2 = (const float2*)d_Dt;
        const float2* Gt2 = (const float2*)d_Gt;
        const float2* St2 = (const float2*)d_St;
        #pragma unroll
        for (int j = 0; j < 4; ++j) {
            int rr = ty * 4 + j;
            const float2* am = AB2 + (size_t)sm_m[rr] * 160;
            const float2* bm = AB2 + (size_t)sm_a[rr] * 160 + 80;
            const float2* dp = Dt2 + sm_d[rr] * 80;
            const float2* gp = Gt2 + sm_g[rr] * 80;
            const float2* sp = St2 + sm_s[rr] * 80;
            #pragma unroll
            for (int c = 0; c < 5; ++c) {
                int cp = tx + 16 * c;
                float2 v  = *(float2*)(stg + rr * SSTR + 2 * cp);
                float2 t1 = am[cp], t2 = bm[cp], t3 = dp[cp], t4 = gp[cp], t5 = sp[cp];
                v.x = fmaxf(v.x + t1.x + t2.x + t3.x + t4.x + t5.x, 0.f);
                v.y = fmaxf(v.y + t1.y + t2.y + t3.y + t4.y + t5.y, 0.f);
                *(float2*)(stg + rr * SSTR + 2 * cp) = v;
            }
        }
    }

    // ---- layer 2: h2pre = h1 @ W2 (scalar f32x2) ----
    ull* Ws = (ull*)(sm + F_WS);
    ull acc2[4][5];
    #pragma unroll
    for (int j = 0; j < 4; ++j)
        #pragma unroll
        for (int c = 0; c < 5; ++c) acc2[j][c] = 0ull;

    for (int k0 = 0; k0 < CPAD; k0 += 16) {
        __syncthreads();
        for (int i = t; i < 1280; i += 512) {
            int k = i / 80, cp = i % 80, c0 = 2 * cp;
            int kk = k0 + k;
            ull w = 0ull;
            if (kk < HID) {
                float lo = (c0     < HID) ? W2[kk * HID + c0    ] : 0.f;
                float hi = (c0 + 1 < HID) ? W2[kk * HID + c0 + 1] : 0.f;
                w = pk(lo, hi);
            }
            Ws[k * 80 + cp] = w;
        }
        __syncthreads();
        #pragma unroll
        for (int kk = 0; kk < 16; ++kk) {
            ull qq[4];
            #pragma unroll
            for (int j = 0; j < 4; ++j) qq[j] = bcast2(stg[(ty * 4 + j) * SSTR + k0 + kk]);
            #pragma unroll
            for (int c = 0; c < 5; ++c) {
                ull w = Ws[kk * 80 + tx + 16 * c];
                #pragma unroll
                for (int j = 0; j < 4; ++j) fma2(acc2[j][c], qq[j], w);
            }
        }
    }

    // ---- epilogue 2: relu(h2pre + b2) @ W3 + b3 + ms[m] + ms[a] ----
    float b3v = b3[0];
    float part[4] = {0.f, 0.f, 0.f, 0.f};
    #pragma unroll
    for (int c = 0; c < 5; ++c) {
        int c0 = 2 * (tx + 16 * c);
        float w3a = w3s[c0], w3b = w3s[c0 + 1];
        float b2a = (c0     < HID) ? b2[c0    ] : 0.f;
        float b2b = (c0 + 1 < HID) ? b2[c0 + 1] : 0.f;
        #pragma unroll
        for (int j = 0; j < 4; ++j) {
            float2 v = unpk(acc2[j][c]);
            part[j] += fmaxf(v.x + b2a, 0.f) * w3a + fmaxf(v.y + b2b, 0.f) * w3b;
        }
    }
    #pragma unroll
    for (int j = 0; j < 4; ++j) {
        #pragma unroll
        for (int off = 8; off > 0; off >>= 1)
            part[j] += __shfl_xor_sync(0xffffffffu, part[j], off);
    }
    if (tx == 0) {
        #pragma unroll
        for (int j = 0; j < 4; ++j) {
            int rr = ty * 4 + j;
            int p = p0 + rr;
            if (p < P)
                out[p] = part[j] + b3v + ms[sm_m[rr]] + ms[sm_a[rr]];
        }
    }
}

// ===================== launch =====================

extern "C" void kernel_launch(void* const* d_in, const int* in_sizes, int n_in,
                              void* d_out, int out_size)
{
    const float* g_i = (const float*)d_in[0];
    const float* ms  = (const float*)d_in[1];
    const float* de  = (const float*)d_in[2];
    const float* ge  = (const float*)d_in[3];
    const float* se  = (const float*)d_in[4];
    const float* W1  = (const float*)d_in[5];
    const float* b1  = (const float*)d_in[6];
    const float* W2  = (const float*)d_in[7];
    const float* b2  = (const float*)d_in[8];
    const float* W3  = (const float*)d_in[9];
    const float* b3  = (const float*)d_in[10];
    const int*   mid = (const int*)d_in[11];
    const int*   aid = (const int*)d_in[12];
    const int*   did = (const int*)d_in[13];
    const int*   gid = (const int*)d_in[14];
    const int*   sid = (const int*)d_in[15];

    int N = in_sizes[0] / GI;
    if (N > NMAX) N = NMAX;
    int P = in_sizes[11];
    if (P > PMAX) P = PMAX;
    float* out = (float*)d_out;

    prep_wtiles<<<NCH, 256>>>(W1);
    prep_tabs<<<1, CPAD>>>(de, ge, se, W1, b1);

    cudaFuncSetAttribute(gemm_ab_pipe, cudaFuncAttributeMaxDynamicSharedMemorySize, T1_SMEM);
    gemm_ab_pipe<<<(N + 63) / 64, 512, T1_SMEM>>>(g_i, N);

    cudaFuncSetAttribute(bilinear_fused, cudaFuncAttributeMaxDynamicSharedMemorySize, F_SMEM);
    bilinear_fused<<<(P + 127) / 128, 512, F_SMEM>>>(g_i, ms, W2, b2, W3, b3,
                                                     mid, aid, did, gid, sid, out, P);
}

// round 10
// speedup vs baseline: 2.2487x; 1.2728x over previous
#include <cuda_runtime.h>
#include <cuda_fp16.h>
#include <cstdint>

typedef unsigned long long ull;

#define GI   1220
#define HID  150
#define NMAX 50000
#define PMAX 100000
#define CPAD 160
#define ABS  320
#define NCH  20        // K chunks of 64 (padded to 1280)
#define RS   144       // smem row stride (bytes) for fp16 tiles -> conflict-free LDSM

// ===================== device scratch (no allocations allowed) =====================
__device__ float d_AB[(size_t)NMAX * ABS];     // 64 MB: per-mention  g@[W1a|W1b]
__device__ uint4 d_WcTh[NCH * 20480 / 16];     // W1c^T fp16 tiles [160 x 64] per chunk
__device__ uint4 d_WabTh[NCH * 40960 / 16];    // [W1a|pad|W1b|pad]^T fp16 tiles [320 x 64] per chunk
__device__ float d_Dt[9 * CPAD];               // dist table (+b1)
__device__ float d_Gt[8 * CPAD];
__device__ float d_St[3 * CPAD];

// ===================== helpers =====================
__device__ __forceinline__ uint32_t smem_to_u32(const void* p) {
    uint32_t a;
    asm("{ .reg .u64 t; cvta.to.shared.u64 t, %1; cvt.u32.u64 %0, t; }" : "=r"(a) : "l"(p));
    return a;
}

__device__ __forceinline__ void mma16816(float c[4],
                                         uint32_t a0, uint32_t a1, uint32_t a2, uint32_t a3,
                                         uint32_t b0, uint32_t b1) {
    asm volatile(
        "mma.sync.aligned.m16n8k16.row.col.f32.f16.f16.f32 "
        "{%0,%1,%2,%3}, {%4,%5,%6,%7}, {%8,%9}, {%0,%1,%2,%3};"
        : "+f"(c[0]), "+f"(c[1]), "+f"(c[2]), "+f"(c[3])
        : "r"(a0), "r"(a1), "r"(a2), "r"(a3), "r"(b0), "r"(b1));
}

__device__ __forceinline__ void ldsm4(uint32_t r[4], uint32_t addr) {
    asm volatile("ldmatrix.sync.aligned.m8n8.x4.shared.b16 {%0,%1,%2,%3}, [%4];"
        : "=r"(r[0]), "=r"(r[1]), "=r"(r[2]), "=r"(r[3]) : "r"(addr));
}
__device__ __forceinline__ void ldsm2(uint32_t r[2], uint32_t addr) {
    asm volatile("ldmatrix.sync.aligned.m8n8.x2.shared.b16 {%0,%1}, [%2];"
        : "=r"(r[0]), "=r"(r[1]) : "r"(addr));
}

__device__ __forceinline__ void cp16(uint32_t dst, const void* src) {
    asm volatile("cp.async.cg.shared.global [%0], [%1], 16;" :: "r"(dst), "l"(src));
}
#define CP_COMMIT() asm volatile("cp.async.commit_group;" ::: "memory")
#define CP_WAIT0()  asm volatile("cp.async.wait_group 0;" ::: "memory")

union HPack { __half v[4]; ull u; };
// fp16 hi/lo split: x = hi + lo with |x-hi-lo| <= 2^-22 |x|
__device__ __forceinline__ void split4h(float4 x, ull& hu, ull& lu) {
    HPack H, L;
    float p[4] = {x.x, x.y, x.z, x.w};
    #pragma unroll
    for (int i = 0; i < 4; ++i) {
        __half h = __float2half_rn(p[i]);
        H.v[i] = h;
        L.v[i] = __float2half_rn(p[i] - __half2float(h));
    }
    hu = H.u; lu = L.u;
}

// packed f32x2 helpers (scalar tail)
__device__ __forceinline__ void fma2(ull& d, ull a, ull b) {
    asm("fma.rn.f32x2 %0, %1, %2, %0;" : "+l"(d) : "l"(a), "l"(b));
}
__device__ __forceinline__ ull bcast2(float x) {
    ull r; asm("mov.b64 %0, {%1, %1};" : "=l"(r) : "f"(x)); return r;
}
__device__ __forceinline__ ull pk(float x, float y) {
    ull r; asm("mov.b64 %0, {%1, %2};" : "=l"(r) : "f"(x), "f"(y)); return r;
}
__device__ __forceinline__ float2 unpk(ull v) {
    float2 r; asm("mov.b64 {%0, %1}, %2;" : "=f"(r.x), "=f"(r.y) : "l"(v)); return r;
}

// MMA inner step, 32-row x 40-col warp tile: 2 m-frags x 5 n-frags, 2 split passes (A hi+lo, B hi).
__device__ __forceinline__ void mma_chunk5(float (*acc)[5][4],
        uint32_t Ah, uint32_t Al, uint32_t Bh,
        int s, int rowbase, int colbase, int lane) {
    int kb2 = s * 32;
    int l7 = lane & 7, g = lane >> 3;
    uint32_t aoff = (uint32_t)((rowbase + (g & 1) * 8 + l7) * RS + kb2 + (g >> 1) * 16);
    uint32_t ah[2][4], al[2][4];
    ldsm4(ah[0], Ah + aoff);
    ldsm4(ah[1], Ah + aoff + 16 * RS);
    ldsm4(al[0], Al + aoff);
    ldsm4(al[1], Al + aoff + 16 * RS);
    uint32_t boff = (uint32_t)((colbase + (g >> 1) * 8 + l7) * RS + kb2 + (g & 1) * 16);
    #pragma unroll
    for (int fp = 0; fp < 2; ++fp) {
        uint32_t bh[4];
        ldsm4(bh, Bh + boff + fp * 16 * RS);
        #pragma unroll
        for (int half = 0; half < 2; ++half) {
            int f = fp * 2 + half;
            uint32_t b0h = bh[half * 2], b1h = bh[half * 2 + 1];
            #pragma unroll
            for (int mi = 0; mi < 2; ++mi) {
                mma16816(acc[mi][f], ah[mi][0], ah[mi][1], ah[mi][2], ah[mi][3], b0h, b1h);
                mma16816(acc[mi][f], al[mi][0], al[mi][1], al[mi][2], al[mi][3], b0h, b1h);
            }
        }
    }
    // n-frag 4 via ldmatrix.x2
    uint32_t boff2 = (uint32_t)((colbase + 32 + l7) * RS + kb2 + ((lane >> 3) & 1) * 16);
    uint32_t bh2[2];
    ldsm2(bh2, Bh + boff2);
    #pragma unroll
    for (int mi = 0; mi < 2; ++mi) {
        mma16816(acc[mi][4], ah[mi][0], ah[mi][1], ah[mi][2], ah[mi][3], bh2[0], bh2[1]);
        mma16816(acc[mi][4], al[mi][0], al[mi][1], al[mi][2], al[mi][3], bh2[0], bh2[1]);
    }
}

// ===================== weight prep: transpose + fp16 =====================

__global__ void prep_wtiles(const float* __restrict__ W1) {
    int q = blockIdx.x;   // K-chunk
    int t = threadIdx.x;
    __half* ch = (__half*)d_WcTh;
    for (int idx = t; idx < 160 * 64; idx += 256) {
        int n = idx >> 6, kk = idx & 63, k = q * 64 + kk;
        float v = (k < GI && n < HID) ? W1[(2 * GI + k) * HID + n] : 0.f;
        ch[(size_t)q * 10240 + (size_t)n * 64 + kk] = __float2half_rn(v);
    }
    __half* ah = (__half*)d_WabTh;
    for (int idx = t; idx < 320 * 64; idx += 256) {
        int n = idx >> 6, kk = idx & 63, k = q * 64 + kk;
        float v = 0.f;
        if (k < GI) {
            if (n < HID)                        v = W1[k * HID + n];
            else if (n >= 160 && n < 160 + HID) v = W1[(GI + k) * HID + (n - 160)];
        }
        ah[(size_t)q * 20480 + (size_t)n * 64 + kk] = __float2half_rn(v);
    }
}

__global__ void prep_tabs(const float* __restrict__ de, const float* __restrict__ ge,
                          const float* __restrict__ se, const float* __restrict__ W1,
                          const float* __restrict__ b1) {
    int c = threadIdx.x;     // 0..159
    for (int d = 0; d < 9; ++d) {
        float v = 0.f;
        if (c < HID) {
            v = b1[c];
            for (int t = 0; t < 20; ++t) v += de[d*20 + t] * W1[(3*GI + t) * HID + c];
        }
        d_Dt[d * CPAD + c] = v;
    }
    for (int g = 0; g < 8; ++g) {
        float v = 0.f;
        if (c < HID)
            for (int t = 0; t < 20; ++t) v += ge[g*20 + t] * W1[(3*GI + 20 + t) * HID + c];
        d_Gt[g * CPAD + c] = v;
    }
    for (int s = 0; s < 3; ++s) {
        float v = 0.f;
        if (c < HID)
            for (int t = 0; t < 20; ++t) v += se[s*20 + t] * W1[(3*GI + 40 + t) * HID + c];
        d_St[s * CPAD + c] = v;
    }
}

// ===================== T1: AB = g @ [W1a|W1b]  (64 x 320 / CTA, 512 threads) =====================
// smem: A bufs @0 (2 x 18432: h 9216 + l 9216), B bufs @36864 (2 x 46080, hi only)
#define T1_B    36864
#define T1_SMEM 129024

__device__ __forceinline__ void cpB_T1(uint32_t bh, int q, int t) {
    const uint4* sH = d_WabTh + (size_t)q * 2560;
    #pragma unroll
    for (int i = 0; i < 5; ++i) {
        int idx = t + 512 * i, n = idx >> 3, seg = idx & 7;
        cp16(bh + n * RS + seg * 16, sH + idx);
    }
}

__device__ __forceinline__ void ldgRow(const float4* grow, int kb0, float4 x[2]) {
    #pragma unroll
    for (int u = 0; u < 2; ++u) {
        int kb = kb0 + 4 * u;
        x[u] = (kb < GI) ? grow[kb >> 2] : make_float4(0.f, 0.f, 0.f, 0.f);
    }
}
__device__ __forceinline__ void stsRow(unsigned char* Ah, unsigned char* Al,
                                       int r, int koff, const float4 x[2]) {
    #pragma unroll
    for (int u = 0; u < 2; ++u) {
        ull hu, lu; split4h(x[u], hu, lu);
        uint32_t off = (uint32_t)(r * RS + (koff + 4 * u) * 2);
        *(ull*)(Ah + off) = hu;
        *(ull*)(Al + off) = lu;
    }
}

__global__ __launch_bounds__(512, 1) void gemm_ab_pipe(const float* __restrict__ g, int N) {
    extern __shared__ unsigned char sm[];
    uint32_t sb = smem_to_u32(sm);
    int t = threadIdx.x, wid = t >> 5, lane = t & 31;
    int g4 = lane >> 2, tq = lane & 3;
    int wr = wid & 1, wc = wid >> 1;              // 2 x 8 warp grid (32 x 40 tiles)
    int rowbase = wr * 32, colbase = wc * 40;
    int n0 = blockIdx.x * 64;
    int r = t >> 3, q8 = t & 7, kth = 8 * q8;     // A staging: 64 rows, 8 floats/thread
    int row = n0 + r; if (row >= N) row = N - 1;
    const float4* grow = (const float4*)(g + (size_t)row * GI);

    float acc[2][5][4];
    #pragma unroll
    for (int mi = 0; mi < 2; ++mi)
        #pragma unroll
        for (int f = 0; f < 5; ++f)
            #pragma unroll
            for (int e = 0; e < 4; ++e) acc[mi][f][e] = 0.f;

    // prologue: stage chunk 0
    {
        float4 x[2];
        ldgRow(grow, kth, x);
        stsRow(sm, sm + 9216, r, kth, x);
        cpB_T1(sb + T1_B, 0, t);
        CP_COMMIT(); CP_WAIT0();
    }
    __syncthreads();

    for (int q = 0; q < NCH; ++q) {
        int cb = q & 1, nb = cb ^ 1;
        uint32_t Ah = sb + cb * 18432;
        uint32_t Al = Ah + 9216;
        uint32_t Bh = sb + T1_B + cb * 46080;
        unsigned char* nAh = sm + nb * 18432;
        unsigned char* nAl = nAh + 9216;
        bool more = (q + 1 < NCH);
        if (more) { cpB_T1(sb + T1_B + nb * 46080, q + 1, t); CP_COMMIT(); }
        float4 x0[2];
        int kn = (q + 1) * 64 + kth;
        if (more) ldgRow(grow, kn, x0);
        mma_chunk5(acc, Ah, Al, Bh, 0, rowbase, colbase, lane);
        mma_chunk5(acc, Ah, Al, Bh, 1, rowbase, colbase, lane);
        mma_chunk5(acc, Ah, Al, Bh, 2, rowbase, colbase, lane);
        mma_chunk5(acc, Ah, Al, Bh, 3, rowbase, colbase, lane);
        if (more) { stsRow(nAh, nAl, r, kth, x0); CP_WAIT0(); }
        __syncthreads();
    }

    #pragma unroll
    for (int mi = 0; mi < 2; ++mi) {
        #pragma unroll
        for (int f = 0; f < 5; ++f) {
            int rr = rowbase + mi * 16 + g4;
            int col = colbase + f * 8 + 2 * tq;
            int n = n0 + rr;
            if (n < N)
                *(float2*)(d_AB + (size_t)n * ABS + col) = make_float2(acc[mi][f][0], acc[mi][f][1]);
            n = n0 + rr + 8;
            if (n < N)
                *(float2*)(d_AB + (size_t)n * ABS + col) = make_float2(acc[mi][f][2], acc[mi][f][3]);
        }
    }
}

// ===================== T2 fused: bilinear MMA + epilogue + layers 2-3 (512 threads) =====================
#define F_W3   2560
#define F_A    4096
#define F_B    77824
#define F_STG  4096
#define F_WS   90112
#define F_SMEM 123904
#define SSTR   168

__device__ __forceinline__ void cpB_T2(uint32_t bh, int q, int t) {
    const uint4* sH = d_WcTh + (size_t)q * 1280;
    #pragma unroll
    for (int i = 0; i < 3; ++i) {
        int idx = t + 512 * i;
        if (idx < 1280) {
            int n = idx >> 3, seg = idx & 7;
            cp16(bh + n * RS + seg * 16, sH + idx);
        }
    }
}

__device__ __forceinline__ void ldgPair(const float4* ir, const float4* jr, int kb0,
                                        float4 xi[2], float4 xj[2]) {
    #pragma unroll
    for (int u = 0; u < 2; ++u) {
        int kb = kb0 + 4 * u;
        if (kb < GI) { xi[u] = ir[kb >> 2]; xj[u] = jr[kb >> 2]; }
        else { xi[u] = make_float4(0.f, 0.f, 0.f, 0.f); xj[u] = make_float4(0.f, 0.f, 0.f, 0.f); }
    }
}
__device__ __forceinline__ void stsPair(unsigned char* Ah, unsigned char* Al,
                                        int r, int koff, const float4 xi[2], const float4 xj[2]) {
    #pragma unroll
    for (int u = 0; u < 2; ++u) {
        float4 p4 = make_float4(xi[u].x * xj[u].x, xi[u].y * xj[u].y,
                                xi[u].z * xj[u].z, xi[u].w * xj[u].w);
        ull hu, lu; split4h(p4, hu, lu);
        uint32_t off = (uint32_t)(r * RS + (koff + 4 * u) * 2);
        *(ull*)(Ah + off) = hu;
        *(ull*)(Al + off) = lu;
    }
}

__global__ __launch_bounds__(512, 1) void bilinear_fused(
    const float* __restrict__ g,  const float* __restrict__ ms,
    const float* __restrict__ W2, const float* __restrict__ b2,
    const float* __restrict__ W3, const float* __restrict__ b3,
    const int* __restrict__ mid,  const int* __restrict__ aid,
    const int* __restrict__ did,  const int* __restrict__ gid,
    const int* __restrict__ sid,
    float* __restrict__ out, int P)
{
    extern __shared__ unsigned char sm[];
    uint32_t sb = smem_to_u32(sm);
    int t = threadIdx.x, wid = t >> 5, lane = t & 31;
    int g4 = lane >> 2, tq = lane & 3;
    int wr = wid >> 2, wc = wid & 3;              // 4 x 4 warp grid (32 x 40 tiles)
    int rowbase = wr * 32, colbase = wc * 40;
    int p0 = blockIdx.x * 128;
    int* sm_m = (int*)sm;
    int* sm_a = (int*)(sm + 512);
    int* sm_d = (int*)(sm + 1024);
    int* sm_g = (int*)(sm + 1536);
    int* sm_s = (int*)(sm + 2048);
    float* w3s = (float*)(sm + F_W3);

    if (t < 128) {
        int p = p0 + t; if (p >= P) p = P - 1;
        sm_m[t] = mid[p]; sm_a[t] = aid[p]; sm_d[t] = did[p]; sm_g[t] = gid[p]; sm_s[t] = sid[p];
    }
    if (t < CPAD) w3s[t] = (t < HID) ? W3[t] : 0.f;
    __syncthreads();

    int r = t >> 2, q4 = t & 3, kth = 16 * q4;    // A staging: 128 rows, 16 floats/thread
    const float4* ir = (const float4*)(g + (size_t)sm_m[r] * GI);
    const float4* jr = (const float4*)(g + (size_t)sm_a[r] * GI);

    float acc[2][5][4];
    #pragma unroll
    for (int mi = 0; mi < 2; ++mi)
        #pragma unroll
        for (int f = 0; f < 5; ++f)
            #pragma unroll
            for (int e = 0; e < 4; ++e) acc[mi][f][e] = 0.f;

    // prologue: stage chunk 0
    {
        float4 xi[2], xj[2];
        ldgPair(ir, jr, kth, xi, xj);
        stsPair(sm + F_A, sm + F_A + 18432, r, kth, xi, xj);
        ldgPair(ir, jr, kth + 8, xi, xj);
        stsPair(sm + F_A, sm + F_A + 18432, r, kth + 8, xi, xj);
        cpB_T2(sb + F_B, 0, t);
        CP_COMMIT(); CP_WAIT0();
    }
    __syncthreads();

    for (int q = 0; q < NCH; ++q) {
        int cb = q & 1, nb = cb ^ 1;
        uint32_t Ah = sb + F_A + cb * 36864;
        uint32_t Al = Ah + 18432;
        uint32_t Bh = sb + F_B + cb * 23040;
        unsigned char* nAh = sm + F_A + nb * 36864;
        unsigned char* nAl = nAh + 18432;
        bool more = (q + 1 < NCH);
        if (more) { cpB_T2(sb + F_B + nb * 23040, q + 1, t); CP_COMMIT(); }
        float4 xi[2], xj[2], yi[2], yj[2];
        int kn = (q + 1) * 64 + kth;
        if (more) ldgPair(ir, jr, kn, xi, xj);
        mma_chunk5(acc, Ah, Al, Bh, 0, rowbase, colbase, lane);
        mma_chunk5(acc, Ah, Al, Bh, 1, rowbase, colbase, lane);
        if (more) { stsPair(nAh, nAl, r, kth, xi, xj); ldgPair(ir, jr, kn + 8, yi, yj); }
        mma_chunk5(acc, Ah, Al, Bh, 2, rowbase, colbase, lane);
        mma_chunk5(acc, Ah, Al, Bh, 3, rowbase, colbase, lane);
        if (more) { stsPair(nAh, nAl, r, kth + 8, yi, yj); CP_WAIT0(); }
        __syncthreads();
    }

    // ---- stage acc -> smem [128 x 168] ----
    float* stg = (float*)(sm + F_STG);
    #pragma unroll
    for (int mi = 0; mi < 2; ++mi) {
        #pragma unroll
        for (int f = 0; f < 5; ++f) {
            int rr = rowbase + mi * 16 + g4;
            int col = colbase + f * 8 + 2 * tq;
            *(float2*)(stg + rr * SSTR + col) = make_float2(acc[mi][f][0], acc[mi][f][1]);
            *(float2*)(stg + (rr + 8) * SSTR + col) = make_float2(acc[mi][f][2], acc[mi][f][3]);
        }
    }
    __syncthreads();

    // ---- epilogue 1: h1 = relu(bil + AB[m] + AB[a]+160 + Dt + Gt + St), in place ----
    int tx = t & 15, ty = t >> 4;                 // ty 0..31: 4 rows each
    {
        const float2* AB2 = (const float2*)d_AB;   // row stride 160 float2
        const float2* Dt2 = (const float2*)d_Dt;
        const float2* Gt2 = (const float2*)d_Gt;
        const float2* St2 = (const float2*)d_St;
        #pragma unroll
        for (int j = 0; j < 4; ++j) {
            int rr = ty * 4 + j;
            const float2* am = AB2 + (size_t)sm_m[rr] * 160;
            const float2* bm = AB2 + (size_t)sm_a[rr] * 160 + 80;
            const float2* dp = Dt2 + sm_d[rr] * 80;
            const float2* gp = Gt2 + sm_g[rr] * 80;
            const float2* sp = St2 + sm_s[rr] * 80;
            #pragma unroll
            for (int c = 0; c < 5; ++c) {
                int cp = tx + 16 * c;
                float2 v  = *(float2*)(stg + rr * SSTR + 2 * cp);
                float2 t1 = am[cp], t2 = bm[cp], t3 = dp[cp], t4 = gp[cp], t5 = sp[cp];
                v.x = fmaxf(v.x + t1.x + t2.x + t3.x + t4.x + t5.x, 0.f);
                v.y = fmaxf(v.y + t1.y + t2.y + t3.y + t4.y + t5.y, 0.f);
                *(float2*)(stg + rr * SSTR + 2 * cp) = v;
            }
        }
    }

    // ---- layer 2: h2pre = h1 @ W2 (scalar f32x2) ----
    ull* Ws = (ull*)(sm + F_WS);
    ull acc2[4][5];
    #pragma unroll
    for (int j = 0; j < 4; ++j)
        #pragma unroll
        for (int c = 0; c < 5; ++c) acc2[j][c] = 0ull;

    for (int k0 = 0; k0 < CPAD; k0 += 16) {
        __syncthreads();
        for (int i = t; i < 1280; i += 512) {
            int k = i / 80, cp = i % 80, c0 = 2 * cp;
            int kk = k0 + k;
            ull w = 0ull;
            if (kk < HID) {
                float lo = (c0     < HID) ? W2[kk * HID + c0    ] : 0.f;
                float hi = (c0 + 1 < HID) ? W2[kk * HID + c0 + 1] : 0.f;
                w = pk(lo, hi);
            }
            Ws[k * 80 + cp] = w;
        }
        __syncthreads();
        #pragma unroll
        for (int kk = 0; kk < 16; ++kk) {
            ull qq[4];
            #pragma unroll
            for (int j = 0; j < 4; ++j) qq[j] = bcast2(stg[(ty * 4 + j) * SSTR + k0 + kk]);
            #pragma unroll
            for (int c = 0; c < 5; ++c) {
                ull w = Ws[kk * 80 + tx + 16 * c];
                #pragma unroll
                for (int j = 0; j < 4; ++j) fma2(acc2[j][c], qq[j], w);
            }
        }
    }

    // ---- epilogue 2: relu(h2pre + b2) @ W3 + b3 + ms[m] + ms[a] ----
    float b3v = b3[0];
    float part[4] = {0.f, 0.f, 0.f, 0.f};
    #pragma unroll
    for (int c = 0; c < 5; ++c) {
        int c0 = 2 * (tx + 16 * c);
        float w3a = w3s[c0], w3b = w3s[c0 + 1];
        float b2a = (c0     < HID) ? b2[c0    ] : 0.f;
        float b2b = (c0 + 1 < HID) ? b2[c0 + 1] : 0.f;
        #pragma unroll
        for (int j = 0; j < 4; ++j) {
            float2 v = unpk(acc2[j][c]);
            part[j] += fmaxf(v.x + b2a, 0.f) * w3a + fmaxf(v.y + b2b, 0.f) * w3b;
        }
    }
    #pragma unroll
    for (int j = 0; j < 4; ++j) {
        #pragma unroll
        for (int off = 8; off > 0; off >>= 1)
            part[j] += __shfl_xor_sync(0xffffffffu, part[j], off);
    }
    if (tx == 0) {
        #pragma unroll
        for (int j = 0; j < 4; ++j) {
            int rr = ty * 4 + j;
            int p = p0 + rr;
            if (p < P)
                out[p] = part[j] + b3v + ms[sm_m[rr]] + ms[sm_a[rr]];
        }
    }
}

// ===================== launch =====================

extern "C" void kernel_launch(void* const* d_in, const int* in_sizes, int n_in,
                              void* d_out, int out_size)
{
    const float* g_i = (const float*)d_in[0];
    const float* ms  = (const float*)d_in[1];
    const float* de  = (const float*)d_in[2];
    const float* ge  = (const float*)d_in[3];
    const float* se  = (const float*)d_in[4];
    const float* W1  = (const float*)d_in[5];
    const float* b1  = (const float*)d_in[6];
    const float* W2  = (const float*)d_in[7];
    const float* b2  = (const float*)d_in[8];
    const float* W3  = (const float*)d_in[9];
    const float* b3  = (const float*)d_in[10];
    const int*   mid = (const int*)d_in[11];
    const int*   aid = (const int*)d_in[12];
    const int*   did = (const int*)d_in[13];
    const int*   gid = (const int*)d_in[14];
    const int*   sid = (const int*)d_in[15];

    int N = in_sizes[0] / GI;
    if (N > NMAX) N = NMAX;
    int P = in_sizes[11];
    if (P > PMAX) P = PMAX;
    float* out = (float*)d_out;

    prep_wtiles<<<NCH, 256>>>(W1);
    prep_tabs<<<1, CPAD>>>(de, ge, se, W1, b1);

    cudaFuncSetAttribute(gemm_ab_pipe, cudaFuncAttributeMaxDynamicSharedMemorySize, T1_SMEM);
    gemm_ab_pipe<<<(N + 63) / 64, 512, T1_SMEM>>>(g_i, N);

    cudaFuncSetAttribute(bilinear_fused, cudaFuncAttributeMaxDynamicSharedMemorySize, F_SMEM);
    bilinear_fused<<<(P + 127) / 128, 512, F_SMEM>>>(g_i, ms, W2, b2, W3, b3,
                                                     mid, aid, did, gid, sid, out, P);
}

// round 11
// speedup vs baseline: 2.4608x; 1.0943x over previous
#include <cuda_runtime.h>
#include <cuda_fp16.h>
#include <cstdint>

typedef unsigned long long ull;

#define GI   1220
#define HID  150
#define NMAX 50000
#define PMAX 100000
#define CPAD 160
#define ABS  320
#define NCH  20        // K chunks of 64 (padded to 1280)
#define RS   144       // smem row stride (bytes) for fp16 tiles -> conflict-free LDSM

// ===================== device scratch (no allocations allowed) =====================
__device__ float d_AB[(size_t)NMAX * ABS];     // 64 MB: per-mention  g@[W1a|W1b]
__device__ uint4 d_WcTh[NCH * 20480 / 16];     // W1c^T fp16 tiles [160 x 64] per chunk
__device__ uint4 d_WabTh[NCH * 40960 / 16];    // [W1a|pad|W1b|pad]^T fp16 tiles [320 x 64] per chunk
__device__ float d_Dt[9 * CPAD];               // dist table (+b1)
__device__ float d_Gt[8 * CPAD];
__device__ float d_St[3 * CPAD];

// ===================== helpers =====================
__device__ __forceinline__ uint32_t smem_to_u32(const void* p) {
    uint32_t a;
    asm("{ .reg .u64 t; cvta.to.shared.u64 t, %1; cvt.u32.u64 %0, t; }" : "=r"(a) : "l"(p));
    return a;
}

__device__ __forceinline__ void mma16816(float c[4],
                                         uint32_t a0, uint32_t a1, uint32_t a2, uint32_t a3,
                                         uint32_t b0, uint32_t b1) {
    asm volatile(
        "mma.sync.aligned.m16n8k16.row.col.f32.f16.f16.f32 "
        "{%0,%1,%2,%3}, {%4,%5,%6,%7}, {%8,%9}, {%0,%1,%2,%3};"
        : "+f"(c[0]), "+f"(c[1]), "+f"(c[2]), "+f"(c[3])
        : "r"(a0), "r"(a1), "r"(a2), "r"(a3), "r"(b0), "r"(b1));
}

__device__ __forceinline__ void ldsm4(uint32_t r[4], uint32_t addr) {
    asm volatile("ldmatrix.sync.aligned.m8n8.x4.shared.b16 {%0,%1,%2,%3}, [%4];"
        : "=r"(r[0]), "=r"(r[1]), "=r"(r[2]), "=r"(r[3]) : "r"(addr));
}
__device__ __forceinline__ void ldsm2(uint32_t r[2], uint32_t addr) {
    asm volatile("ldmatrix.sync.aligned.m8n8.x2.shared.b16 {%0,%1}, [%2];"
        : "=r"(r[0]), "=r"(r[1]) : "r"(addr));
}

__device__ __forceinline__ void cp16(uint32_t dst, const void* src) {
    asm volatile("cp.async.cg.shared.global [%0], [%1], 16;" :: "r"(dst), "l"(src));
}
#define CP_COMMIT() asm volatile("cp.async.commit_group;" ::: "memory")
#define CP_WAIT0()  asm volatile("cp.async.wait_group 0;" ::: "memory")

union HPack { __half v[4]; ull u; };
// fp16 hi/lo split: x = hi + lo with |x-hi-lo| <= 2^-22 |x|
__device__ __forceinline__ void split4h(float4 x, ull& hu, ull& lu) {
    HPack H, L;
    float p[4] = {x.x, x.y, x.z, x.w};
    #pragma unroll
    for (int i = 0; i < 4; ++i) {
        __half h = __float2half_rn(p[i]);
        H.v[i] = h;
        L.v[i] = __float2half_rn(p[i] - __half2float(h));
    }
    hu = H.u; lu = L.u;
}

// packed f32x2 helpers (scalar tail)
__device__ __forceinline__ void fma2(ull& d, ull a, ull b) {
    asm("fma.rn.f32x2 %0, %1, %2, %0;" : "+l"(d) : "l"(a), "l"(b));
}
__device__ __forceinline__ ull bcast2(float x) {
    ull r; asm("mov.b64 %0, {%1, %1};" : "=l"(r) : "f"(x)); return r;
}
__device__ __forceinline__ ull pk(float x, float y) {
    ull r; asm("mov.b64 %0, {%1, %2};" : "=l"(r) : "f"(x), "f"(y)); return r;
}
__device__ __forceinline__ float2 unpk(ull v) {
    float2 r; asm("mov.b64 {%0, %1}, %2;" : "=f"(r.x), "=f"(r.y) : "l"(v)); return r;
}

// MMA inner step, 32-row x 40-col warp tile: 2 m-frags x 5 n-frags, 2 split passes (A hi+lo, B hi).
__device__ __forceinline__ void mma_chunk5(float (*acc)[5][4],
        uint32_t Ah, uint32_t Al, uint32_t Bh,
        int s, int rowbase, int colbase, int lane) {
    int kb2 = s * 32;
    int l7 = lane & 7, g = lane >> 3;
    uint32_t aoff = (uint32_t)((rowbase + (g & 1) * 8 + l7) * RS + kb2 + (g >> 1) * 16);
    uint32_t ah[2][4], al[2][4];
    ldsm4(ah[0], Ah + aoff);
    ldsm4(ah[1], Ah + aoff + 16 * RS);
    ldsm4(al[0], Al + aoff);
    ldsm4(al[1], Al + aoff + 16 * RS);
    uint32_t boff = (uint32_t)((colbase + (g >> 1) * 8 + l7) * RS + kb2 + (g & 1) * 16);
    #pragma unroll
    for (int fp = 0; fp < 2; ++fp) {
        uint32_t bh[4];
        ldsm4(bh, Bh + boff + fp * 16 * RS);
        #pragma unroll
        for (int half = 0; half < 2; ++half) {
            int f = fp * 2 + half;
            uint32_t b0h = bh[half * 2], b1h = bh[half * 2 + 1];
            #pragma unroll
            for (int mi = 0; mi < 2; ++mi) {
                mma16816(acc[mi][f], ah[mi][0], ah[mi][1], ah[mi][2], ah[mi][3], b0h, b1h);
                mma16816(acc[mi][f], al[mi][0], al[mi][1], al[mi][2], al[mi][3], b0h, b1h);
            }
        }
    }
    // n-frag 4 via ldmatrix.x2
    uint32_t boff2 = (uint32_t)((colbase + 32 + l7) * RS + kb2 + ((lane >> 3) & 1) * 16);
    uint32_t bh2[2];
    ldsm2(bh2, Bh + boff2);
    #pragma unroll
    for (int mi = 0; mi < 2; ++mi) {
        mma16816(acc[mi][4], ah[mi][0], ah[mi][1], ah[mi][2], ah[mi][3], bh2[0], bh2[1]);
        mma16816(acc[mi][4], al[mi][0], al[mi][1], al[mi][2], al[mi][3], bh2[0], bh2[1]);
    }
}

// ===================== weight prep: transpose + fp16 =====================

__global__ void prep_wtiles(const float* __restrict__ W1) {
    int q = blockIdx.x;   // K-chunk
    int t = threadIdx.x;
    __half* ch = (__half*)d_WcTh;
    for (int idx = t; idx < 160 * 64; idx += 256) {
        int n = idx >> 6, kk = idx & 63, k = q * 64 + kk;
        float v = (k < GI && n < HID) ? W1[(2 * GI + k) * HID + n] : 0.f;
        ch[(size_t)q * 10240 + (size_t)n * 64 + kk] = __float2half_rn(v);
    }
    __half* ah = (__half*)d_WabTh;
    for (int idx = t; idx < 320 * 64; idx += 256) {
        int n = idx >> 6, kk = idx & 63, k = q * 64 + kk;
        float v = 0.f;
        if (k < GI) {
            if (n < HID)                        v = W1[k * HID + n];
            else if (n >= 160 && n < 160 + HID) v = W1[(GI + k) * HID + (n - 160)];
        }
        ah[(size_t)q * 20480 + (size_t)n * 64 + kk] = __float2half_rn(v);
    }
}

__global__ void prep_tabs(const float* __restrict__ de, const float* __restrict__ ge,
                          const float* __restrict__ se, const float* __restrict__ W1,
                          const float* __restrict__ b1) {
    int c = threadIdx.x;     // 0..159
    for (int d = 0; d < 9; ++d) {
        float v = 0.f;
        if (c < HID) {
            v = b1[c];
            for (int t = 0; t < 20; ++t) v += de[d*20 + t] * W1[(3*GI + t) * HID + c];
        }
        d_Dt[d * CPAD + c] = v;
    }
    for (int g = 0; g < 8; ++g) {
        float v = 0.f;
        if (c < HID)
            for (int t = 0; t < 20; ++t) v += ge[g*20 + t] * W1[(3*GI + 20 + t) * HID + c];
        d_Gt[g * CPAD + c] = v;
    }
    for (int s = 0; s < 3; ++s) {
        float v = 0.f;
        if (c < HID)
            for (int t = 0; t < 20; ++t) v += se[s*20 + t] * W1[(3*GI + 40 + t) * HID + c];
        d_St[s * CPAD + c] = v;
    }
}

// ===================== T1: AB = g @ W1-half  (64 x 160 / CTA, 256 thr, 2 CTA/SM) =====================
// smem: A bufs @0 (2 x 18432: h 9216 + l 9216), B bufs @36864 (2 x 23040, hi only)
#define T1_B    36864
#define T1_SMEM 82944

__device__ __forceinline__ void cpB_T1(uint32_t bh, int q, int by, int t) {
    const uint4* sH = d_WabTh + (size_t)q * 2560 + (size_t)by * 1280;
    #pragma unroll
    for (int i = 0; i < 5; ++i) {
        int idx = t + 256 * i, n = idx >> 3, seg = idx & 7;
        cp16(bh + n * RS + seg * 16, sH + idx);
    }
}

__device__ __forceinline__ void ldgRow4(const float4* grow, int kb0, float4 x[4]) {
    #pragma unroll
    for (int u = 0; u < 4; ++u) {
        int kb = kb0 + 4 * u;
        x[u] = (kb < GI) ? grow[kb >> 2] : make_float4(0.f, 0.f, 0.f, 0.f);
    }
}
__device__ __forceinline__ void stsRow4(unsigned char* Ah, unsigned char* Al,
                                        int r, int koff, const float4 x[4]) {
    #pragma unroll
    for (int u = 0; u < 4; ++u) {
        ull hu, lu; split4h(x[u], hu, lu);
        uint32_t off = (uint32_t)(r * RS + (koff + 4 * u) * 2);
        *(ull*)(Ah + off) = hu;
        *(ull*)(Al + off) = lu;
    }
}

__global__ __launch_bounds__(256, 2) void gemm_ab_pipe(const float* __restrict__ g, int N) {
    extern __shared__ unsigned char sm[];
    uint32_t sb = smem_to_u32(sm);
    int t = threadIdx.x, wid = t >> 5, lane = t & 31;
    int g4 = lane >> 2, tq = lane & 3;
    int wr = wid & 1, wc = wid >> 1;              // 2 x 4 warp grid (32 x 40 tiles)
    int rowbase = wr * 32, colbase = wc * 40;
    int n0 = blockIdx.x * 64;
    int by = blockIdx.y;                          // which 160-col half of [W1a|W1b]
    int r = t >> 2, q4 = t & 3, kth = 16 * q4;    // A staging: 64 rows, 16 floats/thread
    int row = n0 + r; if (row >= N) row = N - 1;
    const float4* grow = (const float4*)(g + (size_t)row * GI);

    float acc[2][5][4];
    #pragma unroll
    for (int mi = 0; mi < 2; ++mi)
        #pragma unroll
        for (int f = 0; f < 5; ++f)
            #pragma unroll
            for (int e = 0; e < 4; ++e) acc[mi][f][e] = 0.f;

    // prologue: stage chunk 0
    {
        float4 x[4];
        ldgRow4(grow, kth, x);
        stsRow4(sm, sm + 9216, r, kth, x);
        cpB_T1(sb + T1_B, 0, by, t);
        CP_COMMIT(); CP_WAIT0();
    }
    __syncthreads();

    for (int q = 0; q < NCH; ++q) {
        int cb = q & 1, nb = cb ^ 1;
        uint32_t Ah = sb + cb * 18432;
        uint32_t Al = Ah + 9216;
        uint32_t Bh = sb + T1_B + cb * 23040;
        unsigned char* nAh = sm + nb * 18432;
        unsigned char* nAl = nAh + 9216;
        bool more = (q + 1 < NCH);
        if (more) { cpB_T1(sb + T1_B + nb * 23040, q + 1, by, t); CP_COMMIT(); }
        float4 x0[4];
        int kn = (q + 1) * 64 + kth;
        if (more) ldgRow4(grow, kn, x0);
        mma_chunk5(acc, Ah, Al, Bh, 0, rowbase, colbase, lane);
        mma_chunk5(acc, Ah, Al, Bh, 1, rowbase, colbase, lane);
        mma_chunk5(acc, Ah, Al, Bh, 2, rowbase, colbase, lane);
        mma_chunk5(acc, Ah, Al, Bh, 3, rowbase, colbase, lane);
        if (more) { stsRow4(nAh, nAl, r, kth, x0); CP_WAIT0(); }
        __syncthreads();
    }

    #pragma unroll
    for (int mi = 0; mi < 2; ++mi) {
        #pragma unroll
        for (int f = 0; f < 5; ++f) {
            int rr = rowbase + mi * 16 + g4;
            int col = by * 160 + colbase + f * 8 + 2 * tq;
            int n = n0 + rr;
            if (n < N)
                *(float2*)(d_AB + (size_t)n * ABS + col) = make_float2(acc[mi][f][0], acc[mi][f][1]);
            n = n0 + rr + 8;
            if (n < N)
                *(float2*)(d_AB + (size_t)n * ABS + col) = make_float2(acc[mi][f][2], acc[mi][f][3]);
        }
    }
}

// ===================== T2 fused: bilinear MMA + epilogue + layers 2-3 (64 pairs/CTA, 2 CTA/SM) =====================
#define F_W3   2560
#define F_A    4096
#define F_B    40960
#define F_STG  4096
#define F_WS   47104
#define F_SMEM 87040
#define SSTR   168

__device__ __forceinline__ void cpB_T2(uint32_t bh, int q, int t) {
    const uint4* sH = d_WcTh + (size_t)q * 1280;
    #pragma unroll
    for (int i = 0; i < 5; ++i) {
        int idx = t + 256 * i, n = idx >> 3, seg = idx & 7;
        cp16(bh + n * RS + seg * 16, sH + idx);
    }
}

__device__ __forceinline__ void ldgPair4(const float4* ir, const float4* jr, int kb0,
                                         float4 xi[4], float4 xj[4]) {
    #pragma unroll
    for (int u = 0; u < 4; ++u) {
        int kb = kb0 + 4 * u;
        if (kb < GI) { xi[u] = ir[kb >> 2]; xj[u] = jr[kb >> 2]; }
        else { xi[u] = make_float4(0.f, 0.f, 0.f, 0.f); xj[u] = make_float4(0.f, 0.f, 0.f, 0.f); }
    }
}
__device__ __forceinline__ void stsPair4(unsigned char* Ah, unsigned char* Al,
                                         int r, int koff, const float4 xi[4], const float4 xj[4]) {
    #pragma unroll
    for (int u = 0; u < 4; ++u) {
        float4 p4 = make_float4(xi[u].x * xj[u].x, xi[u].y * xj[u].y,
                                xi[u].z * xj[u].z, xi[u].w * xj[u].w);
        ull hu, lu; split4h(p4, hu, lu);
        uint32_t off = (uint32_t)(r * RS + (koff + 4 * u) * 2);
        *(ull*)(Ah + off) = hu;
        *(ull*)(Al + off) = lu;
    }
}

__global__ __launch_bounds__(256, 2) void bilinear_fused(
    const float* __restrict__ g,  const float* __restrict__ ms,
    const float* __restrict__ W2, const float* __restrict__ b2,
    const float* __restrict__ W3, const float* __restrict__ b3,
    const int* __restrict__ mid,  const int* __restrict__ aid,
    const int* __restrict__ did,  const int* __restrict__ gid,
    const int* __restrict__ sid,
    float* __restrict__ out, int P)
{
    extern __shared__ unsigned char sm[];
    uint32_t sb = smem_to_u32(sm);
    int t = threadIdx.x, wid = t >> 5, lane = t & 31;
    int g4 = lane >> 2, tq = lane & 3;
    int wr = wid & 1, wc = wid >> 1;              // 2 x 4 warp grid (32 x 40 tiles)
    int rowbase = wr * 32, colbase = wc * 40;
    int p0 = blockIdx.x * 64;
    int* sm_m = (int*)sm;
    int* sm_a = (int*)(sm + 512);
    int* sm_d = (int*)(sm + 1024);
    int* sm_g = (int*)(sm + 1536);
    int* sm_s = (int*)(sm + 2048);
    float* w3s = (float*)(sm + F_W3);

    if (t < 64) {
        int p = p0 + t; if (p >= P) p = P - 1;
        sm_m[t] = mid[p]; sm_a[t] = aid[p]; sm_d[t] = did[p]; sm_g[t] = gid[p]; sm_s[t] = sid[p];
    }
    if (t < CPAD) w3s[t] = (t < HID) ? W3[t] : 0.f;
    __syncthreads();

    int r = t >> 2, q4 = t & 3, kth = 16 * q4;    // A staging: 64 rows, 16 floats/thread
    const float4* ir = (const float4*)(g + (size_t)sm_m[r] * GI);
    const float4* jr = (const float4*)(g + (size_t)sm_a[r] * GI);

    float acc[2][5][4];
    #pragma unroll
    for (int mi = 0; mi < 2; ++mi)
        #pragma unroll
        for (int f = 0; f < 5; ++f)
            #pragma unroll
            for (int e = 0; e < 4; ++e) acc[mi][f][e] = 0.f;

    // prologue: stage chunk 0
    {
        float4 xi[4], xj[4];
        ldgPair4(ir, jr, kth, xi, xj);
        stsPair4(sm + F_A, sm + F_A + 9216, r, kth, xi, xj);
        cpB_T2(sb + F_B, 0, t);
        CP_COMMIT(); CP_WAIT0();
    }
    __syncthreads();

    for (int q = 0; q < NCH; ++q) {
        int cb = q & 1, nb = cb ^ 1;
        uint32_t Ah = sb + F_A + cb * 18432;
        uint32_t Al = Ah + 9216;
        uint32_t Bh = sb + F_B + cb * 23040;
        unsigned char* nAh = sm + F_A + nb * 18432;
        unsigned char* nAl = nAh + 9216;
        bool more = (q + 1 < NCH);
        if (more) { cpB_T2(sb + F_B + nb * 23040, q + 1, t); CP_COMMIT(); }
        float4 xi[4], xj[4];
        int kn = (q + 1) * 64 + kth;
        if (more) ldgPair4(ir, jr, kn, xi, xj);
        mma_chunk5(acc, Ah, Al, Bh, 0, rowbase, colbase, lane);
        mma_chunk5(acc, Ah, Al, Bh, 1, rowbase, colbase, lane);
        mma_chunk5(acc, Ah, Al, Bh, 2, rowbase, colbase, lane);
        mma_chunk5(acc, Ah, Al, Bh, 3, rowbase, colbase, lane);
        if (more) { stsPair4(nAh, nAl, r, kth, xi, xj); CP_WAIT0(); }
        __syncthreads();
    }

    // ---- stage acc -> smem [64 x 168] ----
    float* stg = (float*)(sm + F_STG);
    #pragma unroll
    for (int mi = 0; mi < 2; ++mi) {
        #pragma unroll
        for (int f = 0; f < 5; ++f) {
            int rr = rowbase + mi * 16 + g4;
            int col = colbase + f * 8 + 2 * tq;
            *(float2*)(stg + rr * SSTR + col) = make_float2(acc[mi][f][0], acc[mi][f][1]);
            *(float2*)(stg + (rr + 8) * SSTR + col) = make_float2(acc[mi][f][2], acc[mi][f][3]);
        }
    }
    __syncthreads();

    // ---- epilogue 1: h1 = relu(bil + AB[m] + AB[a]+160 + Dt + Gt + St), in place ----
    int tx = t & 15, ty = t >> 4;                 // ty 0..15: 4 rows each
    {
        const float2* AB2 = (const float2*)d_AB;   // row stride 160 float2
        const float2* Dt2 = (const float2*)d_Dt;
        const float2* Gt2 = (const float2*)d_Gt;
        const float2* St2 = (const float2*)d_St;
        #pragma unroll
        for (int j = 0; j < 4; ++j) {
            int rr = ty * 4 + j;
            const float2* am = AB2 + (size_t)sm_m[rr] * 160;
            const float2* bm = AB2 + (size_t)sm_a[rr] * 160 + 80;
            const float2* dp = Dt2 + sm_d[rr] * 80;
            const float2* gp = Gt2 + sm_g[rr] * 80;
            const float2* sp = St2 + sm_s[rr] * 80;
            #pragma unroll
            for (int c = 0; c < 5; ++c) {
                int cp = tx + 16 * c;
                float2 v  = *(float2*)(stg + rr * SSTR + 2 * cp);
                float2 t1 = am[cp], t2 = bm[cp], t3 = dp[cp], t4 = gp[cp], t5 = sp[cp];
                v.x = fmaxf(v.x + t1.x + t2.x + t3.x + t4.x + t5.x, 0.f);
                v.y = fmaxf(v.y + t1.y + t2.y + t3.y + t4.y + t5.y, 0.f);
                *(float2*)(stg + rr * SSTR + 2 * cp) = v;
            }
        }
    }

    // ---- layer 2: h2pre = h1 @ W2 (scalar f32x2) ----
    ull* Ws = (ull*)(sm + F_WS);
    ull acc2[4][5];
    #pragma unroll
    for (int j = 0; j < 4; ++j)
        #pragma unroll
        for (int c = 0; c < 5; ++c) acc2[j][c] = 0ull;

    for (int k0 = 0; k0 < CPAD; k0 += 16) {
        __syncthreads();
        for (int i = t; i < 1280; i += 256) {
            int k = i / 80, cp = i % 80, c0 = 2 * cp;
            int kk = k0 + k;
            ull w = 0ull;
            if (kk < HID) {
                float lo = (c0     < HID) ? W2[kk * HID + c0    ] : 0.f;
                float hi = (c0 + 1 < HID) ? W2[kk * HID + c0 + 1] : 0.f;
                w = pk(lo, hi);
            }
            Ws[k * 80 + cp] = w;
        }
        __syncthreads();
        #pragma unroll
        for (int kk = 0; kk < 16; ++kk) {
            ull qq[4];
            #pragma unroll
            for (int j = 0; j < 4; ++j) qq[j] = bcast2(stg[(ty * 4 + j) * SSTR + k0 + kk]);
            #pragma unroll
            for (int c = 0; c < 5; ++c) {
                ull w = Ws[kk * 80 + tx + 16 * c];
                #pragma unroll
                for (int j = 0; j < 4; ++j) fma2(acc2[j][c], qq[j], w);
            }
        }
    }

    // ---- epilogue 2: relu(h2pre + b2) @ W3 + b3 + ms[m] + ms[a] ----
    float b3v = b3[0];
    float part[4] = {0.f, 0.f, 0.f, 0.f};
    #pragma unroll
    for (int c = 0; c < 5; ++c) {
        int c0 = 2 * (tx + 16 * c);
        float w3a = w3s[c0], w3b = w3s[c0 + 1];
        float b2a = (c0     < HID) ? b2[c0    ] : 0.f;
        float b2b = (c0 + 1 < HID) ? b2[c0 + 1] : 0.f;
        #pragma unroll
        for (int j = 0; j < 4; ++j) {
            float2 v = unpk(acc2[j][c]);
            part[j] += fmaxf(v.x + b2a, 0.f) * w3a + fmaxf(v.y + b2b, 0.f) * w3b;
        }
    }
    #pragma unroll
    for (int j = 0; j < 4; ++j) {
        #pragma unroll
        for (int off = 8; off > 0; off >>= 1)
            part[j] += __shfl_xor_sync(0xffffffffu, part[j], off);
    }
    if (tx == 0) {
        #pragma unroll
        for (int j = 0; j < 4; ++j) {
            int rr = ty * 4 + j;
            int p = p0 + rr;
            if (p < P)
                out[p] = part[j] + b3v + ms[sm_m[rr]] + ms[sm_a[rr]];
        }
    }
}

// ===================== launch =====================

extern "C" void kernel_launch(void* const* d_in, const int* in_sizes, int n_in,
                              void* d_out, int out_size)
{
    const float* g_i = (const float*)d_in[0];
    const float* ms  = (const float*)d_in[1];
    const float* de  = (const float*)d_in[2];
    const float* ge  = (const float*)d_in[3];
    const float* se  = (const float*)d_in[4];
    const float* W1  = (const float*)d_in[5];
    const float* b1  = (const float*)d_in[6];
    const float* W2  = (const float*)d_in[7];
    const float* b2  = (const float*)d_in[8];
    const float* W3  = (const float*)d_in[9];
    const float* b3  = (const float*)d_in[10];
    const int*   mid = (const int*)d_in[11];
    const int*   aid = (const int*)d_in[12];
    const int*   did = (const int*)d_in[13];
    const int*   gid = (const int*)d_in[14];
    const int*   sid = (const int*)d_in[15];

    int N = in_sizes[0] / GI;
    if (N > NMAX) N = NMAX;
    int P = in_sizes[11];
    if (P > PMAX) P = PMAX;
    float* out = (float*)d_out;

    prep_wtiles<<<NCH, 256>>>(W1);
    prep_tabs<<<1, CPAD>>>(de, ge, se, W1, b1);

    cudaFuncSetAttribute(gemm_ab_pipe, cudaFuncAttributeMaxDynamicSharedMemorySize, T1_SMEM);
    dim3 g1((N + 63) / 64, 2);
    gemm_ab_pipe<<<g1, 256, T1_SMEM>>>(g_i, N);

    cudaFuncSetAttribute(bilinear_fused, cudaFuncAttributeMaxDynamicSharedMemorySize, F_SMEM);
    bilinear_fused<<<(P + 63) / 64, 256, F_SMEM>>>(g_i, ms, W2, b2, W3, b3,
                                                   mid, aid, did, gid, sid, out, P);
}

// round 12
// speedup vs baseline: 2.4678x; 1.0028x over previous
#include <cuda_runtime.h>
#include <cuda_fp16.h>
#include <cstdint>

typedef unsigned long long ull;

#define GI   1220
#define HID  150
#define NMAX 50000
#define PMAX 100000
#define CPAD 160
#define ABS  320
#define NCH2 39        // K chunks of 32 (1220 -> 39 chunks, padded)
#define RS2  80        // smem row stride (bytes) for fp16 chunk-32 tiles -> conflict-free LDSM

// ===================== device scratch (no allocations allowed) =====================
__device__ float d_AB[(size_t)NMAX * ABS];       // 64 MB: per-mention  g@[W1a|W1b]
__device__ uint4 d_WcTh[NCH2 * 10240 / 16];      // W1c^T fp16 tiles [160 x 32] per chunk
__device__ uint4 d_WabTh[NCH2 * 20480 / 16];     // [W1a|W1b]^T fp16 tiles [320 x 32] per chunk
__device__ float d_Dt[9 * CPAD];                 // dist table (+b1)
__device__ float d_Gt[8 * CPAD];
__device__ float d_St[3 * CPAD];

// ===================== helpers =====================
__device__ __forceinline__ uint32_t smem_to_u32(const void* p) {
    uint32_t a;
    asm("{ .reg .u64 t; cvta.to.shared.u64 t, %1; cvt.u32.u64 %0, t; }" : "=r"(a) : "l"(p));
    return a;
}

__device__ __forceinline__ void mma16816(float c[4],
                                         uint32_t a0, uint32_t a1, uint32_t a2, uint32_t a3,
                                         uint32_t b0, uint32_t b1) {
    asm volatile(
        "mma.sync.aligned.m16n8k16.row.col.f32.f16.f16.f32 "
        "{%0,%1,%2,%3}, {%4,%5,%6,%7}, {%8,%9}, {%0,%1,%2,%3};"
        : "+f"(c[0]), "+f"(c[1]), "+f"(c[2]), "+f"(c[3])
        : "r"(a0), "r"(a1), "r"(a2), "r"(a3), "r"(b0), "r"(b1));
}

__device__ __forceinline__ void ldsm4(uint32_t r[4], uint32_t addr) {
    asm volatile("ldmatrix.sync.aligned.m8n8.x4.shared.b16 {%0,%1,%2,%3}, [%4];"
        : "=r"(r[0]), "=r"(r[1]), "=r"(r[2]), "=r"(r[3]) : "r"(addr));
}
__device__ __forceinline__ void ldsm2(uint32_t r[2], uint32_t addr) {
    asm volatile("ldmatrix.sync.aligned.m8n8.x2.shared.b16 {%0,%1}, [%2];"
        : "=r"(r[0]), "=r"(r[1]) : "r"(addr));
}

__device__ __forceinline__ void cp16(uint32_t dst, const void* src) {
    asm volatile("cp.async.cg.shared.global [%0], [%1], 16;" :: "r"(dst), "l"(src));
}
#define CP_COMMIT() asm volatile("cp.async.commit_group;" ::: "memory")
#define CP_WAIT0()  asm volatile("cp.async.wait_group 0;" ::: "memory")

union HPack { __half v[4]; ull u; };
// fp16 hi/lo split: x = hi + lo with |x-hi-lo| <= 2^-22 |x|
__device__ __forceinline__ void split4h(float4 x, ull& hu, ull& lu) {
    HPack H, L;
    float p[4] = {x.x, x.y, x.z, x.w};
    #pragma unroll
    for (int i = 0; i < 4; ++i) {
        __half h = __float2half_rn(p[i]);
        H.v[i] = h;
        L.v[i] = __float2half_rn(p[i] - __half2float(h));
    }
    hu = H.u; lu = L.u;
}

// packed f32x2 helpers (scalar tail)
__device__ __forceinline__ void fma2(ull& d, ull a, ull b) {
    asm("fma.rn.f32x2 %0, %1, %2, %0;" : "+l"(d) : "l"(a), "l"(b));
}
__device__ __forceinline__ ull bcast2(float x) {
    ull r; asm("mov.b64 %0, {%1, %1};" : "=l"(r) : "f"(x)); return r;
}
__device__ __forceinline__ ull pk(float x, float y) {
    ull r; asm("mov.b64 %0, {%1, %2};" : "=l"(r) : "f"(x), "f"(y)); return r;
}
__device__ __forceinline__ float2 unpk(ull v) {
    float2 r; asm("mov.b64 {%0, %1}, %2;" : "=f"(r.x), "=f"(r.y) : "l"(v)); return r;
}

// MMA inner step (chunk-32 tiles, stride 80), 32x40 warp tile: 2 m-frags x 5 n-frags,
// 2 split passes (A hi+lo, B hi).  s in {0,1}.
__device__ __forceinline__ void mma_chunk5(float (*acc)[5][4],
        uint32_t Ah, uint32_t Al, uint32_t Bh,
        int s, int rowbase, int colbase, int lane) {
    int kb2 = s * 32;
    int l7 = lane & 7, g = lane >> 3;
    uint32_t aoff = (uint32_t)((rowbase + (g & 1) * 8 + l7) * RS2 + kb2 + (g >> 1) * 16);
    uint32_t ah[2][4], al[2][4];
    ldsm4(ah[0], Ah + aoff);
    ldsm4(ah[1], Ah + aoff + 16 * RS2);
    ldsm4(al[0], Al + aoff);
    ldsm4(al[1], Al + aoff + 16 * RS2);
    uint32_t boff = (uint32_t)((colbase + (g >> 1) * 8 + l7) * RS2 + kb2 + (g & 1) * 16);
    #pragma unroll
    for (int fp = 0; fp < 2; ++fp) {
        uint32_t bh[4];
        ldsm4(bh, Bh + boff + fp * 16 * RS2);
        #pragma unroll
        for (int half = 0; half < 2; ++half) {
            int f = fp * 2 + half;
            uint32_t b0h = bh[half * 2], b1h = bh[half * 2 + 1];
            #pragma unroll
            for (int mi = 0; mi < 2; ++mi) {
                mma16816(acc[mi][f], ah[mi][0], ah[mi][1], ah[mi][2], ah[mi][3], b0h, b1h);
                mma16816(acc[mi][f], al[mi][0], al[mi][1], al[mi][2], al[mi][3], b0h, b1h);
            }
        }
    }
    // n-frag 4 via ldmatrix.x2
    uint32_t boff2 = (uint32_t)((colbase + 32 + l7) * RS2 + kb2 + ((lane >> 3) & 1) * 16);
    uint32_t bh2[2];
    ldsm2(bh2, Bh + boff2);
    #pragma unroll
    for (int mi = 0; mi < 2; ++mi) {
        mma16816(acc[mi][4], ah[mi][0], ah[mi][1], ah[mi][2], ah[mi][3], bh2[0], bh2[1]);
        mma16816(acc[mi][4], al[mi][0], al[mi][1], al[mi][2], al[mi][3], bh2[0], bh2[1]);
    }
}

// ===================== weight prep: transpose + fp16, chunk-32 tiles =====================

__global__ void prep_wtiles(const float* __restrict__ W1) {
    int q = blockIdx.x;   // K-chunk of 32
    int t = threadIdx.x;
    __half* ch = (__half*)d_WcTh;
    for (int idx = t; idx < 160 * 32; idx += 256) {
        int n = idx >> 5, kk = idx & 31, k = q * 32 + kk;
        float v = (k < GI && n < HID) ? W1[(2 * GI + k) * HID + n] : 0.f;
        ch[(size_t)q * 5120 + (size_t)n * 32 + kk] = __float2half_rn(v);
    }
    __half* ah = (__half*)d_WabTh;
    for (int idx = t; idx < 320 * 32; idx += 256) {
        int n = idx >> 5, kk = idx & 31, k = q * 32 + kk;
        float v = 0.f;
        if (k < GI) {
            if (n < HID)                        v = W1[k * HID + n];
            else if (n >= 160 && n < 160 + HID) v = W1[(GI + k) * HID + (n - 160)];
        }
        ah[(size_t)q * 10240 + (size_t)n * 32 + kk] = __float2half_rn(v);
    }
}

__global__ void prep_tabs(const float* __restrict__ de, const float* __restrict__ ge,
                          const float* __restrict__ se, const float* __restrict__ W1,
                          const float* __restrict__ b1) {
    int c = threadIdx.x;     // 0..159
    for (int d = 0; d < 9; ++d) {
        float v = 0.f;
        if (c < HID) {
            v = b1[c];
            for (int t = 0; t < 20; ++t) v += de[d*20 + t] * W1[(3*GI + t) * HID + c];
        }
        d_Dt[d * CPAD + c] = v;
    }
    for (int g = 0; g < 8; ++g) {
        float v = 0.f;
        if (c < HID)
            for (int t = 0; t < 20; ++t) v += ge[g*20 + t] * W1[(3*GI + 20 + t) * HID + c];
        d_Gt[g * CPAD + c] = v;
    }
    for (int s = 0; s < 3; ++s) {
        float v = 0.f;
        if (c < HID)
            for (int t = 0; t < 20; ++t) v += se[s*20 + t] * W1[(3*GI + 40 + t) * HID + c];
        d_St[s * CPAD + c] = v;
    }
}

// ===================== T1: AB = g @ W1-half  (64 x 160 / CTA, 256 thr, 3 CTA/SM) =====================
// smem: A bufs @0 (2 x 10240: h 5120 + l 5120), B bufs @20480 (2 x 12800)
#define T1_B    20480
#define T1_SMEM 46080

__device__ __forceinline__ void cpB_T1(uint32_t bh, int q, int by, int t) {
    const uint4* sH = d_WabTh + (size_t)q * 1280 + (size_t)by * 640;
    #pragma unroll
    for (int i = 0; i < 3; ++i) {
        int idx = t + 256 * i;
        if (idx < 640) {
            int n = idx >> 2, seg = idx & 3;
            cp16(bh + n * RS2 + seg * 16, sH + idx);
        }
    }
}

__device__ __forceinline__ void ldgRow2(const float4* grow, int kb0, float4 x[2]) {
    #pragma unroll
    for (int u = 0; u < 2; ++u) {
        int kb = kb0 + 4 * u;
        x[u] = (kb < GI) ? grow[kb >> 2] : make_float4(0.f, 0.f, 0.f, 0.f);
    }
}
__device__ __forceinline__ void stsRow2(unsigned char* Ah, unsigned char* Al,
                                        int r, int koff, const float4 x[2]) {
    #pragma unroll
    for (int u = 0; u < 2; ++u) {
        ull hu, lu; split4h(x[u], hu, lu);
        uint32_t off = (uint32_t)(r * RS2 + (koff + 4 * u) * 2);
        *(ull*)(Ah + off) = hu;
        *(ull*)(Al + off) = lu;
    }
}

__global__ __launch_bounds__(256, 3) void gemm_ab_pipe(const float* __restrict__ g, int N) {
    extern __shared__ unsigned char sm[];
    uint32_t sb = smem_to_u32(sm);
    int t = threadIdx.x, wid = t >> 5, lane = t & 31;
    int g4 = lane >> 2, tq = lane & 3;
    int wr = wid & 1, wc = wid >> 1;              // 2 x 4 warp grid (32 x 40 tiles)
    int rowbase = wr * 32, colbase = wc * 40;
    int n0 = blockIdx.x * 64;
    int by = blockIdx.y;                          // which 160-col half of [W1a|W1b]
    int r = t >> 2, q4 = t & 3, kth = 8 * q4;     // A staging: 64 rows, 8 floats/thread
    int row = n0 + r; if (row >= N) row = N - 1;
    const float4* grow = (const float4*)(g + (size_t)row * GI);

    float acc[2][5][4];
    #pragma unroll
    for (int mi = 0; mi < 2; ++mi)
        #pragma unroll
        for (int f = 0; f < 5; ++f)
            #pragma unroll
            for (int e = 0; e < 4; ++e) acc[mi][f][e] = 0.f;

    // prologue: stage chunk 0
    {
        float4 x[2];
        ldgRow2(grow, kth, x);
        stsRow2(sm, sm + 5120, r, kth, x);
        cpB_T1(sb + T1_B, 0, by, t);
        CP_COMMIT(); CP_WAIT0();
    }
    __syncthreads();

    for (int q = 0; q < NCH2; ++q) {
        int cb = q & 1, nb = cb ^ 1;
        uint32_t Ah = sb + cb * 10240;
        uint32_t Al = Ah + 5120;
        uint32_t Bh = sb + T1_B + cb * 12800;
        unsigned char* nAh = sm + nb * 10240;
        unsigned char* nAl = nAh + 5120;
        bool more = (q + 1 < NCH2);
        if (more) { cpB_T1(sb + T1_B + nb * 12800, q + 1, by, t); CP_COMMIT(); }
        float4 x0[2];
        int kn = (q + 1) * 32 + kth;
        if (more) ldgRow2(grow, kn, x0);
        mma_chunk5(acc, Ah, Al, Bh, 0, rowbase, colbase, lane);
        mma_chunk5(acc, Ah, Al, Bh, 1, rowbase, colbase, lane);
        if (more) { stsRow2(nAh, nAl, r, kth, x0); CP_WAIT0(); }
        __syncthreads();
    }

    #pragma unroll
    for (int mi = 0; mi < 2; ++mi) {
        #pragma unroll
        for (int f = 0; f < 5; ++f) {
            int rr = rowbase + mi * 16 + g4;
            int col = by * 160 + colbase + f * 8 + 2 * tq;
            int n = n0 + rr;
            if (n < N)
                *(float2*)(d_AB + (size_t)n * ABS + col) = make_float2(acc[mi][f][0], acc[mi][f][1]);
            n = n0 + rr + 8;
            if (n < N)
                *(float2*)(d_AB + (size_t)n * ABS + col) = make_float2(acc[mi][f][2], acc[mi][f][3]);
        }
    }
}

// ===================== T2 fused: bilinear MMA + epilogue + layers 2-3 (64 pairs/CTA, 3 CTA/SM) =====================
// smem: idx/w3s @0..2048, A bufs @2048 (2 x 10240), B bufs @22528 (2 x 12800) -> 48128
// epilogue aliases: stage @2048 (64 x 168 floats = 43008) -> 45056, Ws @45056 (10240) -> 55296
#define F_A    2048
#define F_B    22528
#define F_STG  2048
#define F_WS   45056
#define F_SMEM 55296
#define SSTR   168

__device__ __forceinline__ void cpB_F(uint32_t bh, int q, int t) {
    const uint4* sH = d_WcTh + (size_t)q * 640;
    #pragma unroll
    for (int i = 0; i < 3; ++i) {
        int idx = t + 256 * i;
        if (idx < 640) {
            int n = idx >> 2, seg = idx & 3;
            cp16(bh + n * RS2 + seg * 16, sH + idx);
        }
    }
}

__device__ __forceinline__ void ldgPair2(const float4* ir, const float4* jr, int kb0,
                                         float4 xi[2], float4 xj[2]) {
    #pragma unroll
    for (int u = 0; u < 2; ++u) {
        int kb = kb0 + 4 * u;
        if (kb < GI) { xi[u] = ir[kb >> 2]; xj[u] = jr[kb >> 2]; }
        else { xi[u] = make_float4(0.f, 0.f, 0.f, 0.f); xj[u] = make_float4(0.f, 0.f, 0.f, 0.f); }
    }
}
__device__ __forceinline__ void stsPair2(unsigned char* Ah, unsigned char* Al,
                                         int r, int koff, const float4 xi[2], const float4 xj[2]) {
    #pragma unroll
    for (int u = 0; u < 2; ++u) {
        float4 p4 = make_float4(xi[u].x * xj[u].x, xi[u].y * xj[u].y,
                                xi[u].z * xj[u].z, xi[u].w * xj[u].w);
        ull hu, lu; split4h(p4, hu, lu);
        uint32_t off = (uint32_t)(r * RS2 + (koff + 4 * u) * 2);
        *(ull*)(Ah + off) = hu;
        *(ull*)(Al + off) = lu;
    }
}

__global__ __launch_bounds__(256, 3) void bilinear_fused(
    const float* __restrict__ g,  const float* __restrict__ ms,
    const float* __restrict__ W2, const float* __restrict__ b2,
    const float* __restrict__ W3, const float* __restrict__ b3,
    const int* __restrict__ mid,  const int* __restrict__ aid,
    const int* __restrict__ did,  const int* __restrict__ gid,
    const int* __restrict__ sid,
    float* __restrict__ out, int P)
{
    extern __shared__ unsigned char sm[];
    uint32_t sb = smem_to_u32(sm);
    int t = threadIdx.x, wid = t >> 5, lane = t & 31;
    int g4 = lane >> 2, tq = lane & 3;
    int wr = wid & 1, wc = wid >> 1;              // 2 x 4 warp grid (32 x 40 tiles)
    int rowbase = wr * 32, colbase = wc * 40;
    int p0 = blockIdx.x * 64;
    int* sm_m = (int*)sm;                          // 64 ints
    int* sm_a = (int*)(sm + 256);
    int* sm_d = (int*)(sm + 512);
    int* sm_g = (int*)(sm + 768);
    int* sm_s = (int*)(sm + 1024);
    float* w3s = (float*)(sm + 1280);              // 160 floats -> ends 1920

    if (t < 64) {
        int p = p0 + t; if (p >= P) p = P - 1;
        sm_m[t] = mid[p]; sm_a[t] = aid[p]; sm_d[t] = did[p]; sm_g[t] = gid[p]; sm_s[t] = sid[p];
    }
    if (t < CPAD) w3s[t] = (t < HID) ? W3[t] : 0.f;
    __syncthreads();

    int r = t >> 2, q4 = t & 3, kth = 8 * q4;     // A staging: 64 rows, 8 floats/thread
    const float4* ir = (const float4*)(g + (size_t)sm_m[r] * GI);
    const float4* jr = (const float4*)(g + (size_t)sm_a[r] * GI);

    float acc[2][5][4];
    #pragma unroll
    for (int mi = 0; mi < 2; ++mi)
        #pragma unroll
        for (int f = 0; f < 5; ++f)
            #pragma unroll
            for (int e = 0; e < 4; ++e) acc[mi][f][e] = 0.f;

    // prologue: stage chunk 0
    {
        float4 xi[2], xj[2];
        ldgPair2(ir, jr, kth, xi, xj);
        stsPair2(sm + F_A, sm + F_A + 5120, r, kth, xi, xj);
        cpB_F(sb + F_B, 0, t);
        CP_COMMIT(); CP_WAIT0();
    }
    __syncthreads();

    for (int q = 0; q < NCH2; ++q) {
        int cb = q & 1, nb = cb ^ 1;
        uint32_t Ah = sb + F_A + cb * 10240;
        uint32_t Al = Ah + 5120;
        uint32_t Bh = sb + F_B + cb * 12800;
        unsigned char* nAh = sm + F_A + nb * 10240;
        unsigned char* nAl = nAh + 5120;
        bool more = (q + 1 < NCH2);
        if (more) { cpB_F(sb + F_B + nb * 12800, q + 1, t); CP_COMMIT(); }
        float4 xi[2], xj[2];
        int kn = (q + 1) * 32 + kth;
        if (more) ldgPair2(ir, jr, kn, xi, xj);
        mma_chunk5(acc, Ah, Al, Bh, 0, rowbase, colbase, lane);
        mma_chunk5(acc, Ah, Al, Bh, 1, rowbase, colbase, lane);
        if (more) { stsPair2(nAh, nAl, r, kth, xi, xj); CP_WAIT0(); }
        __syncthreads();
    }

    // ---- stage acc -> smem [64 x 168] (aliases A/B buffers; loop is done) ----
    float* stg = (float*)(sm + F_STG);
    __syncthreads();
    #pragma unroll
    for (int mi = 0; mi < 2; ++mi) {
        #pragma unroll
        for (int f = 0; f < 5; ++f) {
            int rr = rowbase + mi * 16 + g4;
            int col = colbase + f * 8 + 2 * tq;
            *(float2*)(stg + rr * SSTR + col) = make_float2(acc[mi][f][0], acc[mi][f][1]);
            *(float2*)(stg + (rr + 8) * SSTR + col) = make_float2(acc[mi][f][2], acc[mi][f][3]);
        }
    }
    __syncthreads();

    // ---- epilogue 1: h1 = relu(bil + AB[m] + AB[a]+160 + Dt + Gt + St), in place ----
    int tx = t & 15, ty = t >> 4;                 // ty 0..15: 4 rows each
    {
        const float2* AB2 = (const float2*)d_AB;   // row stride 160 float2
        const float2* Dt2 = (const float2*)d_Dt;
        const float2* Gt2 = (const float2*)d_Gt;
        const float2* St2 = (const float2*)d_St;
        #pragma unroll
        for (int j = 0; j < 4; ++j) {
            int rr = ty * 4 + j;
            const float2* am = AB2 + (size_t)sm_m[rr] * 160;
            const float2* bm = AB2 + (size_t)sm_a[rr] * 160 + 80;
            const float2* dp = Dt2 + sm_d[rr] * 80;
            const float2* gp = Gt2 + sm_g[rr] * 80;
            const float2* sp = St2 + sm_s[rr] * 80;
            #pragma unroll
            for (int c = 0; c < 5; ++c) {
                int cp = tx + 16 * c;
                float2 v  = *(float2*)(stg + rr * SSTR + 2 * cp);
                float2 t1 = am[cp], t2 = bm[cp], t3 = dp[cp], t4 = gp[cp], t5 = sp[cp];
                v.x = fmaxf(v.x + t1.x + t2.x + t3.x + t4.x + t5.x, 0.f);
                v.y = fmaxf(v.y + t1.y + t2.y + t3.y + t4.y + t5.y, 0.f);
                *(float2*)(stg + rr * SSTR + 2 * cp) = v;
            }
        }
    }

    // ---- layer 2: h2pre = h1 @ W2 (scalar f32x2) ----
    ull* Ws = (ull*)(sm + F_WS);
    ull acc2[4][5];
    #pragma unroll
    for (int j = 0; j < 4; ++j)
        #pragma unroll
        for (int c = 0; c < 5; ++c) acc2[j][c] = 0ull;

    for (int k0 = 0; k0 < CPAD; k0 += 16) {
        __syncthreads();
        for (int i = t; i < 1280; i += 256) {
            int k = i / 80, cp = i % 80, c0 = 2 * cp;
            int kk = k0 + k;
            ull w = 0ull;
            if (kk < HID) {
                float lo = (c0     < HID) ? W2[kk * HID + c0    ] : 0.f;
                float hi = (c0 + 1 < HID) ? W2[kk * HID + c0 + 1] : 0.f;
                w = pk(lo, hi);
            }
            Ws[k * 80 + cp] = w;
        }
        __syncthreads();
        #pragma unroll
        for (int kk = 0; kk < 16; ++kk) {
            ull qq[4];
            #pragma unroll
            for (int j = 0; j < 4; ++j) qq[j] = bcast2(stg[(ty * 4 + j) * SSTR + k0 + kk]);
            #pragma unroll
            for (int c = 0; c < 5; ++c) {
                ull w = Ws[kk * 80 + tx + 16 * c];
                #pragma unroll
                for (int j = 0; j < 4; ++j) fma2(acc2[j][c], qq[j], w);
            }
        }
    }

    // ---- epilogue 2: relu(h2pre + b2) @ W3 + b3 + ms[m] + ms[a] ----
    float b3v = b3[0];
    float part[4] = {0.f, 0.f, 0.f, 0.f};
    #pragma unroll
    for (int c = 0; c < 5; ++c) {
        int c0 = 2 * (tx + 16 * c);
        float w3a = w3s[c0], w3b = w3s[c0 + 1];
        float b2a = (c0     < HID) ? b2[c0    ] : 0.f;
        float b2b = (c0 + 1 < HID) ? b2[c0 + 1] : 0.f;
        #pragma unroll
        for (int j = 0; j < 4; ++j) {
            float2 v = unpk(acc2[j][c]);
            part[j] += fmaxf(v.x + b2a, 0.f) * w3a + fmaxf(v.y + b2b, 0.f) * w3b;
        }
    }
    #pragma unroll
    for (int j = 0; j < 4; ++j) {
        #pragma unroll
        for (int off = 8; off > 0; off >>= 1)
            part[j] += __shfl_xor_sync(0xffffffffu, part[j], off);
    }
    if (tx == 0) {
        #pragma unroll
        for (int j = 0; j < 4; ++j) {
            int rr = ty * 4 + j;
            int p = p0 + rr;
            if (p < P)
                out[p] = part[j] + b3v + ms[sm_m[rr]] + ms[sm_a[rr]];
        }
    }
}

// ===================== launch =====================

extern "C" void kernel_launch(void* const* d_in, const int* in_sizes, int n_in,
                              void* d_out, int out_size)
{
    const float* g_i = (const float*)d_in[0];
    const float* ms  = (const float*)d_in[1];
    const float* de  = (const float*)d_in[2];
    const float* ge  = (const float*)d_in[3];
    const float* se  = (const float*)d_in[4];
    const float* W1  = (const float*)d_in[5];
    const float* b1  = (const float*)d_in[6];
    const float* W2  = (const float*)d_in[7];
    const float* b2  = (const float*)d_in[8];
    const float* W3  = (const float*)d_in[9];
    const float* b3  = (const float*)d_in[10];
    const int*   mid = (const int*)d_in[11];
    const int*   aid = (const int*)d_in[12];
    const int*   did = (const int*)d_in[13];
    const int*   gid = (const int*)d_in[14];
    const int*   sid = (const int*)d_in[15];

    int N = in_sizes[0] / GI;
    if (N > NMAX) N = NMAX;
    int P = in_sizes[11];
    if (P > PMAX) P = PMAX;
    float* out = (float*)d_out;

    prep_wtiles<<<NCH2, 256>>>(W1);
    prep_tabs<<<1, CPAD>>>(de, ge, se, W1, b1);

    cudaFuncSetAttribute(gemm_ab_pipe, cudaFuncAttributeMaxDynamicSharedMemorySize, T1_SMEM);
    dim3 g1((N + 63) / 64, 2);
    gemm_ab_pipe<<<g1, 256, T1_SMEM>>>(g_i, N);

    cudaFuncSetAttribute(bilinear_fused, cudaFuncAttributeMaxDynamicSharedMemorySize, F_SMEM);
    bilinear_fused<<<(P + 63) / 64, 256, F_SMEM>>>(g_i, ms, W2, b2, W3, b3,
                                                   mid, aid, did, gid, sid, out, P);
}

// round 13
// speedup vs baseline: 3.0154x; 1.2219x over previous
#include <cuda_runtime.h>
#include <cuda_fp16.h>
#include <cstdint>

typedef unsigned long long ull;

#define GI   1220
#define HID  150
#define NMAX 50000
#define PMAX 100000
#define CPAD 160
#define ABS  320
#define NCH2 39        // K chunks of 32
#define RS2  80        // smem row stride (bytes) for fp16 chunk-32 tiles -> conflict-free LDSM

// ===================== device scratch (no allocations allowed) =====================
__device__ float d_AB[(size_t)NMAX * ABS];       // 64 MB: per-mention  g@[W1a|W1b]
__device__ uint4 d_WcTh[NCH2 * 10240 / 16];      // W1c^T fp16 tiles [160 x 32] per chunk
__device__ uint4 d_WabTh[NCH2 * 20480 / 16];     // [W1a|W1b]^T fp16 tiles [320 x 32] per chunk
__device__ float d_Dt[9 * CPAD];                 // dist table (+b1)
__device__ float d_Gt[8 * CPAD];
__device__ float d_St[3 * CPAD];

// ===================== helpers =====================
__device__ __forceinline__ uint32_t smem_to_u32(const void* p) {
    uint32_t a;
    asm("{ .reg .u64 t; cvta.to.shared.u64 t, %1; cvt.u32.u64 %0, t; }" : "=r"(a) : "l"(p));
    return a;
}

__device__ __forceinline__ void mma16816(float c[4],
                                         uint32_t a0, uint32_t a1, uint32_t a2, uint32_t a3,
                                         uint32_t b0, uint32_t b1) {
    asm volatile(
        "mma.sync.aligned.m16n8k16.row.col.f32.f16.f16.f32 "
        "{%0,%1,%2,%3}, {%4,%5,%6,%7}, {%8,%9}, {%0,%1,%2,%3};"
        : "+f"(c[0]), "+f"(c[1]), "+f"(c[2]), "+f"(c[3])
        : "r"(a0), "r"(a1), "r"(a2), "r"(a3), "r"(b0), "r"(b1));
}

__device__ __forceinline__ void ldsm4(uint32_t r[4], uint32_t addr) {
    asm volatile("ldmatrix.sync.aligned.m8n8.x4.shared.b16 {%0,%1,%2,%3}, [%4];"
        : "=r"(r[0]), "=r"(r[1]), "=r"(r[2]), "=r"(r[3]) : "r"(addr));
}
__device__ __forceinline__ void ldsm2(uint32_t r[2], uint32_t addr) {
    asm volatile("ldmatrix.sync.aligned.m8n8.x2.shared.b16 {%0,%1}, [%2];"
        : "=r"(r[0]), "=r"(r[1]) : "r"(addr));
}

__device__ __forceinline__ void cp16(uint32_t dst, const void* src) {
    asm volatile("cp.async.cg.shared.global [%0], [%1], 16;" :: "r"(dst), "l"(src));
}
#define CP_COMMIT() asm volatile("cp.async.commit_group;" ::: "memory")
#define CP_WAIT0()  asm volatile("cp.async.wait_group 0;" ::: "memory")

union HPack { __half v[4]; ull u; };
// plain fp16 convert of 4 floats
__device__ __forceinline__ ull cvt4h(float4 x) {
    HPack H;
    H.v[0] = __float2half_rn(x.x);
    H.v[1] = __float2half_rn(x.y);
    H.v[2] = __float2half_rn(x.z);
    H.v[3] = __float2half_rn(x.w);
    return H.u;
}

// packed f32x2 helpers (scalar tail)
__device__ __forceinline__ void fma2(ull& d, ull a, ull b) {
    asm("fma.rn.f32x2 %0, %1, %2, %0;" : "+l"(d) : "l"(a), "l"(b));
}
__device__ __forceinline__ ull bcast2(float x) {
    ull r; asm("mov.b64 %0, {%1, %1};" : "=l"(r) : "f"(x)); return r;
}
__device__ __forceinline__ ull pk(float x, float y) {
    ull r; asm("mov.b64 %0, {%1, %2};" : "=l"(r) : "f"(x), "f"(y)); return r;
}
__device__ __forceinline__ float2 unpk(ull v) {
    float2 r; asm("mov.b64 {%0, %1}, %2;" : "=f"(r.x), "=f"(r.y) : "l"(v)); return r;
}

// MMA inner step (chunk-32 tiles, stride 80), 32x40 warp tile: 2 m-frags x 5 n-frags,
// SINGLE fp16 pass.  s in {0,1}.
__device__ __forceinline__ void mma_chunk5(float (*acc)[5][4],
        uint32_t Ah, uint32_t Bh,
        int s, int rowbase, int colbase, int lane) {
    int kb2 = s * 32;
    int l7 = lane & 7, g = lane >> 3;
    uint32_t aoff = (uint32_t)((rowbase + (g & 1) * 8 + l7) * RS2 + kb2 + (g >> 1) * 16);
    uint32_t ah[2][4];
    ldsm4(ah[0], Ah + aoff);
    ldsm4(ah[1], Ah + aoff + 16 * RS2);
    uint32_t boff = (uint32_t)((colbase + (g >> 1) * 8 + l7) * RS2 + kb2 + (g & 1) * 16);
    #pragma unroll
    for (int fp = 0; fp < 2; ++fp) {
        uint32_t bh[4];
        ldsm4(bh, Bh + boff + fp * 16 * RS2);
        #pragma unroll
        for (int half = 0; half < 2; ++half) {
            int f = fp * 2 + half;
            uint32_t b0h = bh[half * 2], b1h = bh[half * 2 + 1];
            #pragma unroll
            for (int mi = 0; mi < 2; ++mi)
                mma16816(acc[mi][f], ah[mi][0], ah[mi][1], ah[mi][2], ah[mi][3], b0h, b1h);
        }
    }
    // n-frag 4 via ldmatrix.x2
    uint32_t boff2 = (uint32_t)((colbase + 32 + l7) * RS2 + kb2 + ((lane >> 3) & 1) * 16);
    uint32_t bh2[2];
    ldsm2(bh2, Bh + boff2);
    #pragma unroll
    for (int mi = 0; mi < 2; ++mi)
        mma16816(acc[mi][4], ah[mi][0], ah[mi][1], ah[mi][2], ah[mi][3], bh2[0], bh2[1]);
}

// ===================== weight prep: transpose + fp16, chunk-32 tiles =====================

__global__ void prep_wtiles(const float* __restrict__ W1) {
    int q = blockIdx.x;   // K-chunk of 32
    int t = threadIdx.x;
    __half* ch = (__half*)d_WcTh;
    for (int idx = t; idx < 160 * 32; idx += 256) {
        int n = idx >> 5, kk = idx & 31, k = q * 32 + kk;
        float v = (k < GI && n < HID) ? W1[(2 * GI + k) * HID + n] : 0.f;
        ch[(size_t)q * 5120 + (size_t)n * 32 + kk] = __float2half_rn(v);
    }
    __half* ah = (__half*)d_WabTh;
    for (int idx = t; idx < 320 * 32; idx += 256) {
        int n = idx >> 5, kk = idx & 31, k = q * 32 + kk;
        float v = 0.f;
        if (k < GI) {
            if (n < HID)                        v = W1[k * HID + n];
            else if (n >= 160 && n < 160 + HID) v = W1[(GI + k) * HID + (n - 160)];
        }
        ah[(size_t)q * 10240 + (size_t)n * 32 + kk] = __float2half_rn(v);
    }
}

__global__ void prep_tabs(const float* __restrict__ de, const float* __restrict__ ge,
                          const float* __restrict__ se, const float* __restrict__ W1,
                          const float* __restrict__ b1) {
    int c = threadIdx.x;     // 0..159
    for (int d = 0; d < 9; ++d) {
        float v = 0.f;
        if (c < HID) {
            v = b1[c];
            for (int t = 0; t < 20; ++t) v += de[d*20 + t] * W1[(3*GI + t) * HID + c];
        }
        d_Dt[d * CPAD + c] = v;
    }
    for (int g = 0; g < 8; ++g) {
        float v = 0.f;
        if (c < HID)
            for (int t = 0; t < 20; ++t) v += ge[g*20 + t] * W1[(3*GI + 20 + t) * HID + c];
        d_Gt[g * CPAD + c] = v;
    }
    for (int s = 0; s < 3; ++s) {
        float v = 0.f;
        if (c < HID)
            for (int t = 0; t < 20; ++t) v += se[s*20 + t] * W1[(3*GI + 40 + t) * HID + c];
        d_St[s * CPAD + c] = v;
    }
}

// ===================== T1: AB = g @ W1-half  (64 x 160 / CTA, 256 thr, 3 CTA/SM) =====================
// smem: A bufs @0 (2 x 5120), B bufs @10240 (2 x 12800) -> 35840
#define T1_B    10240
#define T1_SMEM 35840

__device__ __forceinline__ void cpB_T1(uint32_t bh, int q, int by, int t) {
    const uint4* sH = d_WabTh + (size_t)q * 1280 + (size_t)by * 640;
    #pragma unroll
    for (int i = 0; i < 3; ++i) {
        int idx = t + 256 * i;
        if (idx < 640) {
            int n = idx >> 2, seg = idx & 3;
            cp16(bh + n * RS2 + seg * 16, sH + idx);
        }
    }
}

__device__ __forceinline__ void ldgRow2(const float4* grow, int kb0, float4 x[2]) {
    #pragma unroll
    for (int u = 0; u < 2; ++u) {
        int kb = kb0 + 4 * u;
        x[u] = (kb < GI) ? grow[kb >> 2] : make_float4(0.f, 0.f, 0.f, 0.f);
    }
}
__device__ __forceinline__ void stsRow2(unsigned char* Ah, int r, int koff, const float4 x[2]) {
    #pragma unroll
    for (int u = 0; u < 2; ++u) {
        uint32_t off = (uint32_t)(r * RS2 + (koff + 4 * u) * 2);
        *(ull*)(Ah + off) = cvt4h(x[u]);
    }
}

__global__ __launch_bounds__(256, 3) void gemm_ab_pipe(const float* __restrict__ g, int N) {
    extern __shared__ unsigned char sm[];
    uint32_t sb = smem_to_u32(sm);
    int t = threadIdx.x, wid = t >> 5, lane = t & 31;
    int g4 = lane >> 2, tq = lane & 3;
    int wr = wid & 1, wc = wid >> 1;              // 2 x 4 warp grid (32 x 40 tiles)
    int rowbase = wr * 32, colbase = wc * 40;
    int n0 = blockIdx.x * 64;
    int by = blockIdx.y;                          // which 160-col half of [W1a|W1b]
    int r = t >> 2, q4 = t & 3, kth = 8 * q4;     // A staging: 64 rows, 8 floats/thread
    int row = n0 + r; if (row >= N) row = N - 1;
    const float4* grow = (const float4*)(g + (size_t)row * GI);

    float acc[2][5][4];
    #pragma unroll
    for (int mi = 0; mi < 2; ++mi)
        #pragma unroll
        for (int f = 0; f < 5; ++f)
            #pragma unroll
            for (int e = 0; e < 4; ++e) acc[mi][f][e] = 0.f;

    // prologue: stage chunk 0
    {
        float4 x[2];
        ldgRow2(grow, kth, x);
        stsRow2(sm, r, kth, x);
        cpB_T1(sb + T1_B, 0, by, t);
        CP_COMMIT(); CP_WAIT0();
    }
    __syncthreads();

    for (int q = 0; q < NCH2; ++q) {
        int cb = q & 1, nb = cb ^ 1;
        uint32_t Ah = sb + cb * 5120;
        uint32_t Bh = sb + T1_B + cb * 12800;
        unsigned char* nAh = sm + nb * 5120;
        bool more = (q + 1 < NCH2);
        if (more) { cpB_T1(sb + T1_B + nb * 12800, q + 1, by, t); CP_COMMIT(); }
        float4 x0[2];
        int kn = (q + 1) * 32 + kth;
        if (more) ldgRow2(grow, kn, x0);
        mma_chunk5(acc, Ah, Bh, 0, rowbase, colbase, lane);
        mma_chunk5(acc, Ah, Bh, 1, rowbase, colbase, lane);
        if (more) { stsRow2(nAh, r, kth, x0); CP_WAIT0(); }
        __syncthreads();
    }

    #pragma unroll
    for (int mi = 0; mi < 2; ++mi) {
        #pragma unroll
        for (int f = 0; f < 5; ++f) {
            int rr = rowbase + mi * 16 + g4;
            int col = by * 160 + colbase + f * 8 + 2 * tq;
            int n = n0 + rr;
            if (n < N)
                *(float2*)(d_AB + (size_t)n * ABS + col) = make_float2(acc[mi][f][0], acc[mi][f][1]);
            n = n0 + rr + 8;
            if (n < N)
                *(float2*)(d_AB + (size_t)n * ABS + col) = make_float2(acc[mi][f][2], acc[mi][f][3]);
        }
    }
}

// ===================== T2 fused: bilinear MMA + epilogue + layers 2-3 (64 pairs/CTA, 3 CTA/SM) =====================
// smem: idx/w3s @0..2048, A bufs @2048 (2 x 5120) -> 12288, B bufs @12288 (2 x 12800) -> 37888
// epilogue aliases: stage @2048 (64 x 168 floats = 43008) -> 45056, Ws @45056 (10240) -> 55296
#define F_A    2048
#define F_B    12288
#define F_STG  2048
#define F_WS   45056
#define F_SMEM 55296
#define SSTR   168

__device__ __forceinline__ void cpB_F(uint32_t bh, int q, int t) {
    const uint4* sH = d_WcTh + (size_t)q * 640;
    #pragma unroll
    for (int i = 0; i < 3; ++i) {
        int idx = t + 256 * i;
        if (idx < 640) {
            int n = idx >> 2, seg = idx & 3;
            cp16(bh + n * RS2 + seg * 16, sH + idx);
        }
    }
}

__device__ __forceinline__ void ldgPair2(const float4* ir, const float4* jr, int kb0,
                                         float4 xi[2], float4 xj[2]) {
    #pragma unroll
    for (int u = 0; u < 2; ++u) {
        int kb = kb0 + 4 * u;
        if (kb < GI) { xi[u] = ir[kb >> 2]; xj[u] = jr[kb >> 2]; }
        else { xi[u] = make_float4(0.f, 0.f, 0.f, 0.f); xj[u] = make_float4(0.f, 0.f, 0.f, 0.f); }
    }
}
__device__ __forceinline__ void stsPair2(unsigned char* Ah, int r, int koff,
                                         const float4 xi[2], const float4 xj[2]) {
    #pragma unroll
    for (int u = 0; u < 2; ++u) {
        float4 p4 = make_float4(xi[u].x * xj[u].x, xi[u].y * xj[u].y,
                                xi[u].z * xj[u].z, xi[u].w * xj[u].w);
        uint32_t off = (uint32_t)(r * RS2 + (koff + 4 * u) * 2);
        *(ull*)(Ah + off) = cvt4h(p4);
    }
}

__global__ __launch_bounds__(256, 3) void bilinear_fused(
    const float* __restrict__ g,  const float* __restrict__ ms,
    const float* __restrict__ W2, const float* __restrict__ b2,
    const float* __restrict__ W3, const float* __restrict__ b3,
    const int* __restrict__ mid,  const int* __restrict__ aid,
    const int* __restrict__ did,  const int* __restrict__ gid,
    const int* __restrict__ sid,
    float* __restrict__ out, int P)
{
    extern __shared__ unsigned char sm[];
    uint32_t sb = smem_to_u32(sm);
    int t = threadIdx.x, wid = t >> 5, lane = t & 31;
    int g4 = lane >> 2, tq = lane & 3;
    int wr = wid & 1, wc = wid >> 1;              // 2 x 4 warp grid (32 x 40 tiles)
    int rowbase = wr * 32, colbase = wc * 40;
    int p0 = blockIdx.x * 64;
    int* sm_m = (int*)sm;                          // 64 ints
    int* sm_a = (int*)(sm + 256);
    int* sm_d = (int*)(sm + 512);
    int* sm_g = (int*)(sm + 768);
    int* sm_s = (int*)(sm + 1024);
    float* w3s = (float*)(sm + 1280);              // 160 floats -> ends 1920

    if (t < 64) {
        int p = p0 + t; if (p >= P) p = P - 1;
        sm_m[t] = mid[p]; sm_a[t] = aid[p]; sm_d[t] = did[p]; sm_g[t] = gid[p]; sm_s[t] = sid[p];
    }
    if (t < CPAD) w3s[t] = (t < HID) ? W3[t] : 0.f;
    __syncthreads();

    int r = t >> 2, q4 = t & 3, kth = 8 * q4;     // A staging: 64 rows, 8 floats/thread
    const float4* ir = (const float4*)(g + (size_t)sm_m[r] * GI);
    const float4* jr = (const float4*)(g + (size_t)sm_a[r] * GI);

    float acc[2][5][4];
    #pragma unroll
    for (int mi = 0; mi < 2; ++mi)
        #pragma unroll
        for (int f = 0; f < 5; ++f)
            #pragma unroll
            for (int e = 0; e < 4; ++e) acc[mi][f][e] = 0.f;

    // prologue: stage chunk 0
    {
        float4 xi[2], xj[2];
        ldgPair2(ir, jr, kth, xi, xj);
        stsPair2(sm + F_A, r, kth, xi, xj);
        cpB_F(sb + F_B, 0, t);
        CP_COMMIT(); CP_WAIT0();
    }
    __syncthreads();

    for (int q = 0; q < NCH2; ++q) {
        int cb = q & 1, nb = cb ^ 1;
        uint32_t Ah = sb + F_A + cb * 5120;
        uint32_t Bh = sb + F_B + cb * 12800;
        unsigned char* nAh = sm + F_A + nb * 5120;
        bool more = (q + 1 < NCH2);
        if (more) { cpB_F(sb + F_B + nb * 12800, q + 1, t); CP_COMMIT(); }
        float4 xi[2], xj[2];
        int kn = (q + 1) * 32 + kth;
        if (more) ldgPair2(ir, jr, kn, xi, xj);
        mma_chunk5(acc, Ah, Bh, 0, rowbase, colbase, lane);
        mma_chunk5(acc, Ah, Bh, 1, rowbase, colbase, lane);
        if (more) { stsPair2(nAh, r, kth, xi, xj); CP_WAIT0(); }
        __syncthreads();
    }

    // ---- stage acc -> smem [64 x 168] (aliases A/B buffers; loop is done) ----
    float* stg = (float*)(sm + F_STG);
    __syncthreads();
    #pragma unroll
    for (int mi = 0; mi < 2; ++mi) {
        #pragma unroll
        for (int f = 0; f < 5; ++f) {
            int rr = rowbase + mi * 16 + g4;
            int col = colbase + f * 8 + 2 * tq;
            *(float2*)(stg + rr * SSTR + col) = make_float2(acc[mi][f][0], acc[mi][f][1]);
            *(float2*)(stg + (rr + 8) * SSTR + col) = make_float2(acc[mi][f][2], acc[mi][f][3]);
        }
    }
    __syncthreads();

    // ---- epilogue 1: h1 = relu(bil + AB[m] + AB[a]+160 + Dt + Gt + St), in place ----
    int tx = t & 15, ty = t >> 4;                 // ty 0..15: 4 rows each
    {
        const float2* AB2 = (const float2*)d_AB;   // row stride 160 float2
        const float2* Dt2 = (const float2*)d_Dt;
        const float2* Gt2 = (const float2*)d_Gt;
        const float2* St2 = (const float2*)d_St;
        #pragma unroll
        for (int j = 0; j < 4; ++j) {
            int rr = ty * 4 + j;
            const float2* am = AB2 + (size_t)sm_m[rr] * 160;
            const float2* bm = AB2 + (size_t)sm_a[rr] * 160 + 80;
            const float2* dp = Dt2 + sm_d[rr] * 80;
            const float2* gp = Gt2 + sm_g[rr] * 80;
            const float2* sp = St2 + sm_s[rr] * 80;
            #pragma unroll
            for (int c = 0; c < 5; ++c) {
                int cp = tx + 16 * c;
                float2 v  = *(float2*)(stg + rr * SSTR + 2 * cp);
                float2 t1 = am[cp], t2 = bm[cp], t3 = dp[cp], t4 = gp[cp], t5 = sp[cp];
                v.x = fmaxf(v.x + t1.x + t2.x + t3.x + t4.x + t5.x, 0.f);
                v.y = fmaxf(v.y + t1.y + t2.y + t3.y + t4.y + t5.y, 0.f);
                *(float2*)(stg + rr * SSTR + 2 * cp) = v;
            }
        }
    }

    // ---- layer 2: h2pre = h1 @ W2 (scalar f32x2) ----
    ull* Ws = (ull*)(sm + F_WS);
    ull acc2[4][5];
    #pragma unroll
    for (int j = 0; j < 4; ++j)
        #pragma unroll
        for (int c = 0; c < 5; ++c) acc2[j][c] = 0ull;

    for (int k0 = 0; k0 < CPAD; k0 += 16) {
        __syncthreads();
        for (int i = t; i < 1280; i += 256) {
            int k = i / 80, cp = i % 80, c0 = 2 * cp;
            int kk = k0 + k;
            ull w = 0ull;
            if (kk < HID) {
                float lo = (c0     < HID) ? W2[kk * HID + c0    ] : 0.f;
                float hi = (c0 + 1 < HID) ? W2[kk * HID + c0 + 1] : 0.f;
                w = pk(lo, hi);
            }
            Ws[k * 80 + cp] = w;
        }
        __syncthreads();
        #pragma unroll
        for (int kk = 0; kk < 16; ++kk) {
            ull qq[4];
            #pragma unroll
            for (int j = 0; j < 4; ++j) qq[j] = bcast2(stg[(ty * 4 + j) * SSTR + k0 + kk]);
            #pragma unroll
            for (int c = 0; c < 5; ++c) {
                ull w = Ws[kk * 80 + tx + 16 * c];
                #pragma unroll
                for (int j = 0; j < 4; ++j) fma2(acc2[j][c], qq[j], w);
            }
        }
    }

    // ---- epilogue 2: relu(h2pre + b2) @ W3 + b3 + ms[m] + ms[a] ----
    float b3v = b3[0];
    float part[4] = {0.f, 0.f, 0.f, 0.f};
    #pragma unroll
    for (int c = 0; c < 5; ++c) {
        int c0 = 2 * (tx + 16 * c);
        float w3a = w3s[c0], w3b = w3s[c0 + 1];
        float b2a = (c0     < HID) ? b2[c0    ] : 0.f;
        float b2b = (c0 + 1 < HID) ? b2[c0 + 1] : 0.f;
        #pragma unroll
        for (int j = 0; j < 4; ++j) {
            float2 v = unpk(acc2[j][c]);
            part[j] += fmaxf(v.x + b2a, 0.f) * w3a + fmaxf(v.y + b2b, 0.f) * w3b;
        }
    }
    #pragma unroll
    for (int j = 0; j < 4; ++j) {
        #pragma unroll
        for (int off = 8; off > 0; off >>= 1)
            part[j] += __shfl_xor_sync(0xffffffffu, part[j], off);
    }
    if (tx == 0) {
        #pragma unroll
        for (int j = 0; j < 4; ++j) {
            int rr = ty * 4 + j;
            int p = p0 + rr;
            if (p < P)
                out[p] = part[j] + b3v + ms[sm_m[rr]] + ms[sm_a[rr]];
        }
    }
}

// ===================== launch =====================

extern "C" void kernel_launch(void* const* d_in, const int* in_sizes, int n_in,
                              void* d_out, int out_size)
{
    const float* g_i = (const float*)d_in[0];
    const float* ms  = (const float*)d_in[1];
    const float* de  = (const float*)d_in[2];
    const float* ge  = (const float*)d_in[3];
    const float* se  = (const float*)d_in[4];
    const float* W1  = (const float*)d_in[5];
    const float* b1  = (const float*)d_in[6];
    const float* W2  = (const float*)d_in[7];
    const float* b2  = (const float*)d_in[8];
    const float* W3  = (const float*)d_in[9];
    const float* b3  = (const float*)d_in[10];
    const int*   mid = (const int*)d_in[11];
    const int*   aid = (const int*)d_in[12];
    const int*   did = (const int*)d_in[13];
    const int*   gid = (const int*)d_in[14];
    const int*   sid = (const int*)d_in[15];

    int N = in_sizes[0] / GI;
    if (N > NMAX) N = NMAX;
    int P = in_sizes[11];
    if (P > PMAX) P = PMAX;
    float* out = (float*)d_out;

    prep_wtiles<<<NCH2, 256>>>(W1);
    prep_tabs<<<1, CPAD>>>(de, ge, se, W1, b1);

    cudaFuncSetAttribute(gemm_ab_pipe, cudaFuncAttributeMaxDynamicSharedMemorySize, T1_SMEM);
    dim3 g1((N + 63) / 64, 2);
    gemm_ab_pipe<<<g1, 256, T1_SMEM>>>(g_i, N);

    cudaFuncSetAttribute(bilinear_fused, cudaFuncAttributeMaxDynamicSharedMemorySize, F_SMEM);
    bilinear_fused<<<(P + 63) / 64, 256, F_SMEM>>>(g_i, ms, W2, b2, W3, b3,
                                                   mid, aid, did, gid, sid, out, P);
}

// round 14
// speedup vs baseline: 3.6522x; 1.2112x over previous
#include <cuda_runtime.h>
#include <cuda_fp16.h>
#include <cstdint>

typedef unsigned long long ull;

#define GI   1220
#define GHW  1232      // padded fp16 g row (16B-aligned)
#define HID  150
#define NMAX 50000
#define PMAX 100000
#define CPAD 160
#define ABS  320
#define NCH2 39        // K chunks of 32
#define RS2  80        // smem row stride (bytes) for fp16 chunk-32 tiles -> conflict-free LDSM
#define H1S  336       // h1 fp16 row stride bytes (168 halves) -> conflict-free LDSM (84r mod 32 distinct)

// ===================== device scratch (no allocations allowed) =====================
__device__ float  d_AB[(size_t)NMAX * ABS];      // 64 MB: per-mention  g@[W1a|W1b]
__device__ __half d_gh[(size_t)NMAX * GHW];      // 123 MB: fp16 image of g (zero-padded cols)
__device__ uint4  d_WcTh[NCH2 * 10240 / 16];     // W1c^T fp16 tiles [160 x 32] per chunk
__device__ uint4  d_WabTh[NCH2 * 20480 / 16];    // [W1a|W1b]^T fp16 tiles [320 x 32] per chunk
__device__ uint4  d_W2Th[5 * 10240 / 16];        // W2^T fp16 tiles [160 x 32] per k-chunk
__device__ float  d_Dt[9 * CPAD];                // dist table (+b1)
__device__ float  d_Gt[8 * CPAD];
__device__ float  d_St[3 * CPAD];

// ===================== helpers =====================
__device__ __forceinline__ uint32_t smem_to_u32(const void* p) {
    uint32_t a;
    asm("{ .reg .u64 t; cvta.to.shared.u64 t, %1; cvt.u32.u64 %0, t; }" : "=r"(a) : "l"(p));
    return a;
}

__device__ __forceinline__ void mma16816(float c[4],
                                         uint32_t a0, uint32_t a1, uint32_t a2, uint32_t a3,
                                         uint32_t b0, uint32_t b1) {
    asm volatile(
        "mma.sync.aligned.m16n8k16.row.col.f32.f16.f16.f32 "
        "{%0,%1,%2,%3}, {%4,%5,%6,%7}, {%8,%9}, {%0,%1,%2,%3};"
        : "+f"(c[0]), "+f"(c[1]), "+f"(c[2]), "+f"(c[3])
        : "r"(a0), "r"(a1), "r"(a2), "r"(a3), "r"(b0), "r"(b1));
}

__device__ __forceinline__ void ldsm4(uint32_t r[4], uint32_t addr) {
    asm volatile("ldmatrix.sync.aligned.m8n8.x4.shared.b16 {%0,%1,%2,%3}, [%4];"
        : "=r"(r[0]), "=r"(r[1]), "=r"(r[2]), "=r"(r[3]) : "r"(addr));
}
__device__ __forceinline__ void ldsm2(uint32_t r[2], uint32_t addr) {
    asm volatile("ldmatrix.sync.aligned.m8n8.x2.shared.b16 {%0,%1}, [%2];"
        : "=r"(r[0]), "=r"(r[1]) : "r"(addr));
}

__device__ __forceinline__ void cp16(uint32_t dst, const void* src) {
    asm volatile("cp.async.cg.shared.global [%0], [%1], 16;" :: "r"(dst), "l"(src));
}
#define CP_COMMIT() asm volatile("cp.async.commit_group;" ::: "memory")
#define CP_WAIT0()  asm volatile("cp.async.wait_group 0;" ::: "memory")

union HPack { __half v[4]; ull u; };
__device__ __forceinline__ ull cvt4h(float4 x) {
    HPack H;
    H.v[0] = __float2half_rn(x.x);
    H.v[1] = __float2half_rn(x.y);
    H.v[2] = __float2half_rn(x.z);
    H.v[3] = __float2half_rn(x.w);
    return H.u;
}

// generic MMA inner step: A from (Abase, astr, akoff), B chunk-32 stride 80.
// 32x40 warp tile: 2 m-frags x 5 n-frags, single fp16 pass.  s in {0,1}.
__device__ __forceinline__ void mma_chunk5g(float (*acc)[5][4],
        uint32_t Abase, uint32_t Bh, int s, int rowbase, int colbase, int lane,
        int astr, int akoff) {
    int kb2 = s * 32;
    int l7 = lane & 7, g = lane >> 3;
    uint32_t aoff = (uint32_t)((rowbase + (g & 1) * 8 + l7) * astr + akoff + kb2 + (g >> 1) * 16);
    uint32_t ah[2][4];
    ldsm4(ah[0], Abase + aoff);
    ldsm4(ah[1], Abase + aoff + 16 * astr);
    uint32_t boff = (uint32_t)((colbase + (g >> 1) * 8 + l7) * RS2 + kb2 + (g & 1) * 16);
    #pragma unroll
    for (int fp = 0; fp < 2; ++fp) {
        uint32_t bh[4];
        ldsm4(bh, Bh + boff + fp * 16 * RS2);
        #pragma unroll
        for (int half = 0; half < 2; ++half) {
            int f = fp * 2 + half;
            uint32_t b0h = bh[half * 2], b1h = bh[half * 2 + 1];
            #pragma unroll
            for (int mi = 0; mi < 2; ++mi)
                mma16816(acc[mi][f], ah[mi][0], ah[mi][1], ah[mi][2], ah[mi][3], b0h, b1h);
        }
    }
    uint32_t boff2 = (uint32_t)((colbase + 32 + l7) * RS2 + kb2 + ((lane >> 3) & 1) * 16);
    uint32_t bh2[2];
    ldsm2(bh2, Bh + boff2);
    #pragma unroll
    for (int mi = 0; mi < 2; ++mi)
        mma16816(acc[mi][4], ah[mi][0], ah[mi][1], ah[mi][2], ah[mi][3], bh2[0], bh2[1]);
}

// ===================== weight prep =====================

__global__ void prep_wtiles(const float* __restrict__ W1) {
    int q = blockIdx.x;   // K-chunk of 32
    int t = threadIdx.x;
    __half* ch = (__half*)d_WcTh;
    for (int idx = t; idx < 160 * 32; idx += 256) {
        int n = idx >> 5, kk = idx & 31, k = q * 32 + kk;
        float v = (k < GI && n < HID) ? W1[(2 * GI + k) * HID + n] : 0.f;
        ch[(size_t)q * 5120 + (size_t)n * 32 + kk] = __float2half_rn(v);
    }
    __half* ah = (__half*)d_WabTh;
    for (int idx = t; idx < 320 * 32; idx += 256) {
        int n = idx >> 5, kk = idx & 31, k = q * 32 + kk;
        float v = 0.f;
        if (k < GI) {
            if (n < HID)                        v = W1[k * HID + n];
            else if (n >= 160 && n < 160 + HID) v = W1[(GI + k) * HID + (n - 160)];
        }
        ah[(size_t)q * 10240 + (size_t)n * 32 + kk] = __float2half_rn(v);
    }
}

__global__ void prep_w2(const float* __restrict__ W2) {
    int q = blockIdx.x;   // 0..4
    int t = threadIdx.x;
    __half* wh = (__half*)d_W2Th;
    for (int idx = t; idx < 160 * 32; idx += 256) {
        int n = idx >> 5, kk = idx & 31, k = q * 32 + kk;
        float v = (k < HID && n < HID) ? W2[k * HID + n] : 0.f;
        wh[(size_t)q * 5120 + (size_t)n * 32 + kk] = __float2half_rn(v);
    }
}

__global__ void prep_tabs(const float* __restrict__ de, const float* __restrict__ ge,
                          const float* __restrict__ se, const float* __restrict__ W1,
                          const float* __restrict__ b1) {
    int c = threadIdx.x;     // 0..159
    for (int d = 0; d < 9; ++d) {
        float v = 0.f;
        if (c < HID) {
            v = b1[c];
            for (int t = 0; t < 20; ++t) v += de[d*20 + t] * W1[(3*GI + t) * HID + c];
        }
        d_Dt[d * CPAD + c] = v;
    }
    for (int g = 0; g < 8; ++g) {
        float v = 0.f;
        if (c < HID)
            for (int t = 0; t < 20; ++t) v += ge[g*20 + t] * W1[(3*GI + 20 + t) * HID + c];
        d_Gt[g * CPAD + c] = v;
    }
    for (int s = 0; s < 3; ++s) {
        float v = 0.f;
        if (c < HID)
            for (int t = 0; t < 20; ++t) v += se[s*20 + t] * W1[(3*GI + 40 + t) * HID + c];
        d_St[s * CPAD + c] = v;
    }
}

// ===================== T1: AB = g @ W1-half; also emits d_gh (by==0) =====================
// smem: A bufs @0 (2 x 5120), B bufs @10240 (2 x 12800) -> 35840
#define T1_B    10240
#define T1_SMEM 35840

__device__ __forceinline__ void cpB_T1(uint32_t bh, int q, int by, int t) {
    const uint4* sH = d_WabTh + (size_t)q * 1280 + (size_t)by * 640;
    #pragma unroll
    for (int i = 0; i < 3; ++i) {
        int idx = t + 256 * i;
        if (idx < 640) {
            int n = idx >> 2, seg = idx & 3;
            cp16(bh + n * RS2 + seg * 16, sH + idx);
        }
    }
}

__device__ __forceinline__ void ldgRow2(const float4* grow, int kb0, float4 x[2]) {
    #pragma unroll
    for (int u = 0; u < 2; ++u) {
        int kb = kb0 + 4 * u;
        x[u] = (kb < GI) ? grow[kb >> 2] : make_float4(0.f, 0.f, 0.f, 0.f);
    }
}
__device__ __forceinline__ void stsRow2(unsigned char* Ah, int r, int koff, const float4 x[2],
                                        __half* ghrow, int kb0, bool dowrite) {
    ull h0 = cvt4h(x[0]);
    ull h1v = cvt4h(x[1]);
    uint32_t off = (uint32_t)(r * RS2 + koff * 2);
    *(ull*)(Ah + off)     = h0;
    *(ull*)(Ah + off + 8) = h1v;
    if (dowrite && kb0 + 8 <= GHW) {
        uint4 v;
        v.x = (uint32_t)h0;  v.y = (uint32_t)(h0 >> 32);
        v.z = (uint32_t)h1v; v.w = (uint32_t)(h1v >> 32);
        *(uint4*)(ghrow + kb0) = v;
    }
}

__global__ __launch_bounds__(256, 3) void gemm_ab_pipe(const float* __restrict__ g, int N) {
    extern __shared__ unsigned char sm[];
    uint32_t sb = smem_to_u32(sm);
    int t = threadIdx.x, wid = t >> 5, lane = t & 31;
    int g4 = lane >> 2, tq = lane & 3;
    int wr = wid & 1, wc = wid >> 1;              // 2 x 4 warp grid (32 x 40 tiles)
    int rowbase = wr * 32, colbase = wc * 40;
    int n0 = blockIdx.x * 64;
    int by = blockIdx.y;                          // which 160-col half of [W1a|W1b]
    bool ghw = (by == 0);
    int r = t >> 2, q4 = t & 3, kth = 8 * q4;     // A staging: 64 rows, 8 floats/thread
    int row = n0 + r; if (row >= N) row = N - 1;
    const float4* grow = (const float4*)(g + (size_t)row * GI);
    __half* ghrow = d_gh + (size_t)row * GHW;

    float acc[2][5][4];
    #pragma unroll
    for (int mi = 0; mi < 2; ++mi)
        #pragma unroll
        for (int f = 0; f < 5; ++f)
            #pragma unroll
            for (int e = 0; e < 4; ++e) acc[mi][f][e] = 0.f;

    // prologue: stage chunk 0
    {
        float4 x[2];
        ldgRow2(grow, kth, x);
        stsRow2(sm, r, kth, x, ghrow, kth, ghw);
        cpB_T1(sb + T1_B, 0, by, t);
        CP_COMMIT(); CP_WAIT0();
    }
    __syncthreads();

    for (int q = 0; q < NCH2; ++q) {
        int cb = q & 1, nb = cb ^ 1;
        uint32_t Ah = sb + cb * 5120;
        uint32_t Bh = sb + T1_B + cb * 12800;
        unsigned char* nAh = sm + nb * 5120;
        bool more = (q + 1 < NCH2);
        if (more) { cpB_T1(sb + T1_B + nb * 12800, q + 1, by, t); CP_COMMIT(); }
        float4 x0[2];
        int kn = (q + 1) * 32 + kth;
        if (more) ldgRow2(grow, kn, x0);
        mma_chunk5g(acc, Ah, Bh, 0, rowbase, colbase, lane, RS2, 0);
        mma_chunk5g(acc, Ah, Bh, 1, rowbase, colbase, lane, RS2, 0);
        if (more) { stsRow2(nAh, r, kth, x0, ghrow, kn, ghw); CP_WAIT0(); }
        __syncthreads();
    }

    #pragma unroll
    for (int mi = 0; mi < 2; ++mi) {
        #pragma unroll
        for (int f = 0; f < 5; ++f) {
            int rr = rowbase + mi * 16 + g4;
            int col = by * 160 + colbase + f * 8 + 2 * tq;
            int n = n0 + rr;
            if (n < N)
                *(float2*)(d_AB + (size_t)n * ABS + col) = make_float2(acc[mi][f][0], acc[mi][f][1]);
            n = n0 + rr + 8;
            if (n < N)
                *(float2*)(d_AB + (size_t)n * ABS + col) = make_float2(acc[mi][f][2], acc[mi][f][3]);
        }
    }
}

// ===================== T2 fused: bilinear MMA (fp16 gather) + epilogue + layer2 MMA + out =====================
// smem map:
//  0..1280    indices m/a/d/g/s (5 x 256B)
//  1280..1920 w3s (160 f)     1920..2560 b2s (160 f)
//  2560..12800   A bufs (2 x 5120)     [main loop]
//  12800..38400  B bufs (2 x 12800)    [main loop]
//  2560..45568   stg fp32 [64 x 168]   [epilogue1, aliases A+B]
//  2560..15360   W2T buf (12800)       [layer2, aliases stg after reads done]
//  45568..67072  h1h fp16 [64 x 168h, stride 336B]
//  67072..68096  rowpart [4][64] f
#define F_A    2560
#define F_B    12800
#define F_STG  2560
#define F_W2B  2560
#define F_H1H  45568
#define F_RP   67072
#define F_SMEM 68096
#define SSTR   168

__device__ __forceinline__ void cpB_tiles(uint32_t bh, const uint4* srcBase, int q, int t) {
    const uint4* sH = srcBase + (size_t)q * 640;
    #pragma unroll
    for (int i = 0; i < 3; ++i) {
        int idx = t + 256 * i;
        if (idx < 640) {
            int n = idx >> 2, seg = idx & 3;
            cp16(bh + n * RS2 + seg * 16, sH + idx);
        }
    }
}

__device__ __forceinline__ void ldgPair2h(const uint4* ir, const uint4* jr, int kb0,
                                          uint4& xi, uint4& xj) {
    if (kb0 + 8 <= GHW) { xi = ir[kb0 >> 3]; xj = jr[kb0 >> 3]; }
    else { xi = make_uint4(0, 0, 0, 0); xj = xi; }
}
__device__ __forceinline__ void stsPair2h(unsigned char* Ah, int r, int koff,
                                          uint4 xi, uint4 xj) {
    uint4 p;
    *(__half2*)&p.x = __hmul2(*(__half2*)&xi.x, *(__half2*)&xj.x);
    *(__half2*)&p.y = __hmul2(*(__half2*)&xi.y, *(__half2*)&xj.y);
    *(__half2*)&p.z = __hmul2(*(__half2*)&xi.z, *(__half2*)&xj.z);
    *(__half2*)&p.w = __hmul2(*(__half2*)&xi.w, *(__half2*)&xj.w);
    *(uint4*)(Ah + r * RS2 + koff * 2) = p;
}

__global__ __launch_bounds__(256, 3) void bilinear_fused(
    const float* __restrict__ ms,
    const float* __restrict__ b2, const float* __restrict__ W3,
    const float* __restrict__ b3,
    const int* __restrict__ mid,  const int* __restrict__ aid,
    const int* __restrict__ did,  const int* __restrict__ gid,
    const int* __restrict__ sid,
    float* __restrict__ out, int P)
{
    extern __shared__ unsigned char sm[];
    uint32_t sb = smem_to_u32(sm);
    int t = threadIdx.x, wid = t >> 5, lane = t & 31;
    int g4 = lane >> 2, tq = lane & 3;
    int wr = wid & 1, wc = wid >> 1;              // 2 x 4 warp grid (32 x 40 tiles)
    int rowbase = wr * 32, colbase = wc * 40;
    int p0 = blockIdx.x * 64;
    int* sm_m = (int*)sm;
    int* sm_a = (int*)(sm + 256);
    int* sm_d = (int*)(sm + 512);
    int* sm_g = (int*)(sm + 768);
    int* sm_s = (int*)(sm + 1024);
    float* w3s = (float*)(sm + 1280);
    float* b2s = (float*)(sm + 1920);

    if (t < 64) {
        int p = p0 + t; if (p >= P) p = P - 1;
        sm_m[t] = mid[p]; sm_a[t] = aid[p]; sm_d[t] = did[p]; sm_g[t] = gid[p]; sm_s[t] = sid[p];
    }
    if (t < CPAD) {
        w3s[t] = (t < HID) ? W3[t] : 0.f;
        b2s[t] = (t < HID) ? b2[t] : 0.f;
    }
    __syncthreads();

    int r = t >> 2, q4 = t & 3, kth = 8 * q4;     // A staging: 64 rows, 8 halves/thread
    const uint4* ir = (const uint4*)(d_gh + (size_t)sm_m[r] * GHW);
    const uint4* jr = (const uint4*)(d_gh + (size_t)sm_a[r] * GHW);

    float acc[2][5][4];
    #pragma unroll
    for (int mi = 0; mi < 2; ++mi)
        #pragma unroll
        for (int f = 0; f < 5; ++f)
            #pragma unroll
            for (int e = 0; e < 4; ++e) acc[mi][f][e] = 0.f;

    // prologue: stage chunk 0
    {
        uint4 xi, xj;
        ldgPair2h(ir, jr, kth, xi, xj);
        stsPair2h(sm + F_A, r, kth, xi, xj);
        cpB_tiles(sb + F_B, d_WcTh, 0, t);
        CP_COMMIT(); CP_WAIT0();
    }
    __syncthreads();

    for (int q = 0; q < NCH2; ++q) {
        int cb = q & 1, nb = cb ^ 1;
        uint32_t Ah = sb + F_A + cb * 5120;
        uint32_t Bh = sb + F_B + cb * 12800;
        unsigned char* nAh = sm + F_A + nb * 5120;
        bool more = (q + 1 < NCH2);
        if (more) { cpB_tiles(sb + F_B + nb * 12800, d_WcTh, q + 1, t); CP_COMMIT(); }
        uint4 xi, xj;
        int kn = (q + 1) * 32 + kth;
        if (more) ldgPair2h(ir, jr, kn, xi, xj);
        mma_chunk5g(acc, Ah, Bh, 0, rowbase, colbase, lane, RS2, 0);
        mma_chunk5g(acc, Ah, Bh, 1, rowbase, colbase, lane, RS2, 0);
        if (more) { stsPair2h(nAh, r, kth, xi, xj); CP_WAIT0(); }
        __syncthreads();
    }

    // ---- stage acc -> smem fp32 [64 x 168] (aliases A/B bufs; loop done) ----
    float* stg = (float*)(sm + F_STG);
    __syncthreads();
    #pragma unroll
    for (int mi = 0; mi < 2; ++mi) {
        #pragma unroll
        for (int f = 0; f < 5; ++f) {
            int rr = rowbase + mi * 16 + g4;
            int col = colbase + f * 8 + 2 * tq;
            *(float2*)(stg + rr * SSTR + col) = make_float2(acc[mi][f][0], acc[mi][f][1]);
            *(float2*)(stg + (rr + 8) * SSTR + col) = make_float2(acc[mi][f][2], acc[mi][f][3]);
        }
    }
    __syncthreads();

    // ---- epilogue 1: h1 = relu(bil + AB[m] + AB[a]+160 + tabs) -> fp16 h1h ----
    int tx = t & 15, ty = t >> 4;                 // ty 0..15: 4 rows each
    __half* h1h = (__half*)(sm + F_H1H);          // stride 168 halves (336 B)
    {
        const float2* AB2 = (const float2*)d_AB;
        const float2* Dt2 = (const float2*)d_Dt;
        const float2* Gt2 = (const float2*)d_Gt;
        const float2* St2 = (const float2*)d_St;
        #pragma unroll
        for (int j = 0; j < 4; ++j) {
            int rr = ty * 4 + j;
            const float2* am = AB2 + (size_t)sm_m[rr] * 160;
            const float2* bm = AB2 + (size_t)sm_a[rr] * 160 + 80;
            const float2* dp = Dt2 + sm_d[rr] * 80;
            const float2* gp = Gt2 + sm_g[rr] * 80;
            const float2* sp = St2 + sm_s[rr] * 80;
            #pragma unroll
            for (int c = 0; c < 5; ++c) {
                int cp = tx + 16 * c;
                float2 v  = *(float2*)(stg + rr * SSTR + 2 * cp);
                float2 t1 = am[cp], t2 = bm[cp], t3 = dp[cp], t4 = gp[cp], t5 = sp[cp];
                float hx = fmaxf(v.x + t1.x + t2.x + t3.x + t4.x + t5.x, 0.f);
                float hy = fmaxf(v.y + t1.y + t2.y + t3.y + t4.y + t5.y, 0.f);
                *(__half2*)(h1h + rr * SSTR + 2 * cp) = __floats2half2_rn(hx, hy);
            }
        }
    }

    // ---- layer 2 via MMA: h2 = h1h @ W2 (5 k-chunks of 32, single-buffered W2T) ----
    float acc2[2][5][4];
    #pragma unroll
    for (int mi = 0; mi < 2; ++mi)
        #pragma unroll
        for (int f = 0; f < 5; ++f)
            #pragma unroll
            for (int e = 0; e < 4; ++e) acc2[mi][f][e] = 0.f;

    for (int q2 = 0; q2 < 5; ++q2) {
        __syncthreads();                            // stg reads / prev MMA done
        cpB_tiles(sb + F_W2B, d_W2Th, q2, t);
        CP_COMMIT(); CP_WAIT0();
        __syncthreads();                            // W2T + h1h visible
        mma_chunk5g(acc2, sb + F_H1H, sb + F_W2B, 0, rowbase, colbase, lane, H1S, q2 * 64);
        mma_chunk5g(acc2, sb + F_H1H, sb + F_W2B, 1, rowbase, colbase, lane, H1S, q2 * 64);
    }

    // ---- epilogue 2: out = relu(h2 + b2) . W3 + b3 + ms terms ----
    float pr[4] = {0.f, 0.f, 0.f, 0.f};
    #pragma unroll
    for (int f = 0; f < 5; ++f) {
        int c0 = colbase + f * 8 + 2 * tq;
        float w3a = w3s[c0], w3b = w3s[c0 + 1];
        float b2a = b2s[c0], b2b = b2s[c0 + 1];
        #pragma unroll
        for (int mi = 0; mi < 2; ++mi) {
            pr[mi * 2 + 0] += fmaxf(acc2[mi][f][0] + b2a, 0.f) * w3a
                            + fmaxf(acc2[mi][f][1] + b2b, 0.f) * w3b;
            pr[mi * 2 + 1] += fmaxf(acc2[mi][f][2] + b2a, 0.f) * w3a
                            + fmaxf(acc2[mi][f][3] + b2b, 0.f) * w3b;
        }
    }
    #pragma unroll
    for (int k = 0; k < 4; ++k) {
        pr[k] += __shfl_xor_sync(0xffffffffu, pr[k], 1);
        pr[k] += __shfl_xor_sync(0xffffffffu, pr[k], 2);
    }
    float* rowpart = (float*)(sm + F_RP);
    if (tq == 0) {
        #pragma unroll
        for (int mi = 0; mi < 2; ++mi) {
            int rr = rowbase + mi * 16 + g4;
            rowpart[wc * 64 + rr]     = pr[mi * 2 + 0];
            rowpart[wc * 64 + rr + 8] = pr[mi * 2 + 1];
        }
    }
    __syncthreads();
    if (t < 64) {
        float v = rowpart[t] + rowpart[64 + t] + rowpart[128 + t] + rowpart[192 + t];
        int p = p0 + t;
        if (p < P)
            out[p] = v + b3[0] + ms[sm_m[t]] + ms[sm_a[t]];
    }
}

// ===================== launch =====================

extern "C" void kernel_launch(void* const* d_in, const int* in_sizes, int n_in,
                              void* d_out, int out_size)
{
    const float* g_i = (const float*)d_in[0];
    const float* ms  = (const float*)d_in[1];
    const float* de  = (const float*)d_in[2];
    const float* ge  = (const float*)d_in[3];
    const float* se  = (const float*)d_in[4];
    const float* W1  = (const float*)d_in[5];
    const float* b1  = (const float*)d_in[6];
    const float* W2  = (const float*)d_in[7];
    const float* b2  = (const float*)d_in[8];
    const float* W3  = (const float*)d_in[9];
    const float* b3  = (const float*)d_in[10];
    const int*   mid = (const int*)d_in[11];
    const int*   aid = (const int*)d_in[12];
    const int*   did = (const int*)d_in[13];
    const int*   gid = (const int*)d_in[14];
    const int*   sid = (const int*)d_in[15];

    int N = in_sizes[0] / GI;
    if (N > NMAX) N = NMAX;
    int P = in_sizes[11];
    if (P > PMAX) P = PMAX;
    float* out = (float*)d_out;

    prep_wtiles<<<NCH2, 256>>>(W1);
    prep_w2<<<5, 256>>>(W2);
    prep_tabs<<<1, CPAD>>>(de, ge, se, W1, b1);

    cudaFuncSetAttribute(gemm_ab_pipe, cudaFuncAttributeMaxDynamicSharedMemorySize, T1_SMEM);
    dim3 g1((N + 63) / 64, 2);
    gemm_ab_pipe<<<g1, 256, T1_SMEM>>>(g_i, N);

    cudaFuncSetAttribute(bilinear_fused, cudaFuncAttributeMaxDynamicSharedMemorySize, F_SMEM);
    bilinear_fused<<<(P + 63) / 64, 256, F_SMEM>>>(ms, b2, W3, b3,
                                                   mid, aid, did, gid, sid, out, P);
}

// round 15
// speedup vs baseline: 3.8930x; 1.0659x over previous
#include <cuda_runtime.h>
#include <cuda_fp16.h>
#include <cstdint>

typedef unsigned long long ull;

#define GI   1220
#define GHW  1232      // padded fp16 g row (16B-aligned)
#define HID  150
#define NMAX 50000
#define PMAX 100000
#define CPAD 160
#define ABS  320
#define NCH2 39        // K chunks of 32
#define RS2  80        // smem row stride (bytes) for fp16 chunk-32 tiles -> conflict-free LDSM
#define H1S  336       // h1 fp16 row stride bytes

// ===================== device scratch (no allocations allowed) =====================
__device__ float  d_AB[(size_t)NMAX * ABS];      // 64 MB: per-mention  g@[W1a|W1b]
__device__ __half d_gh[(size_t)NMAX * GHW];      // 123 MB: fp16 image of g (zero-padded cols)
__device__ uint4  d_WcTh[NCH2 * 10240 / 16];     // W1c^T fp16 tiles [160 x 32] per chunk
__device__ uint4  d_WabTh[NCH2 * 20480 / 16];    // [W1a|W1b]^T fp16 tiles [320 x 32] per chunk
__device__ uint4  d_W2Th[5 * 10240 / 16];        // W2^T fp16 tiles [160 x 32] per k-chunk
__device__ float  d_Dt[9 * CPAD];                // dist table (+b1)
__device__ float  d_Gt[8 * CPAD];
__device__ float  d_St[3 * CPAD];

// ===================== helpers =====================
__device__ __forceinline__ uint32_t smem_to_u32(const void* p) {
    uint32_t a;
    asm("{ .reg .u64 t; cvta.to.shared.u64 t, %1; cvt.u32.u64 %0, t; }" : "=r"(a) : "l"(p));
    return a;
}

__device__ __forceinline__ void mma16816(float c[4],
                                         uint32_t a0, uint32_t a1, uint32_t a2, uint32_t a3,
                                         uint32_t b0, uint32_t b1) {
    asm volatile(
        "mma.sync.aligned.m16n8k16.row.col.f32.f16.f16.f32 "
        "{%0,%1,%2,%3}, {%4,%5,%6,%7}, {%8,%9}, {%0,%1,%2,%3};"
        : "+f"(c[0]), "+f"(c[1]), "+f"(c[2]), "+f"(c[3])
        : "r"(a0), "r"(a1), "r"(a2), "r"(a3), "r"(b0), "r"(b1));
}

__device__ __forceinline__ void ldsm4(uint32_t r[4], uint32_t addr) {
    asm volatile("ldmatrix.sync.aligned.m8n8.x4.shared.b16 {%0,%1,%2,%3}, [%4];"
        : "=r"(r[0]), "=r"(r[1]), "=r"(r[2]), "=r"(r[3]) : "r"(addr));
}
__device__ __forceinline__ void ldsm2(uint32_t r[2], uint32_t addr) {
    asm volatile("ldmatrix.sync.aligned.m8n8.x2.shared.b16 {%0,%1}, [%2];"
        : "=r"(r[0]), "=r"(r[1]) : "r"(addr));
}

__device__ __forceinline__ void cp16(uint32_t dst, const void* src) {
    asm volatile("cp.async.cg.shared.global [%0], [%1], 16;" :: "r"(dst), "l"(src));
}
#define CP_COMMIT() asm volatile("cp.async.commit_group;" ::: "memory")
#define CP_WAIT0()  asm volatile("cp.async.wait_group 0;" ::: "memory")

union HPack { __half v[4]; ull u; };
__device__ __forceinline__ ull cvt4h(float4 x) {
    HPack H;
    H.v[0] = __float2half_rn(x.x);
    H.v[1] = __float2half_rn(x.y);
    H.v[2] = __float2half_rn(x.z);
    H.v[3] = __float2half_rn(x.w);
    return H.u;
}

// generic MMA inner step: A from (Abase, astr, akoff), B chunk-32 stride 80.
// 32x40 warp tile: 2 m-frags x 5 n-frags, single fp16 pass.  s in {0,1}.
__device__ __forceinline__ void mma_chunk5g(float (*acc)[5][4],
        uint32_t Abase, uint32_t Bh, int s, int rowbase, int colbase, int lane,
        int astr, int akoff) {
    int kb2 = s * 32;
    int l7 = lane & 7, g = lane >> 3;
    uint32_t aoff = (uint32_t)((rowbase + (g & 1) * 8 + l7) * astr + akoff + kb2 + (g >> 1) * 16);
    uint32_t ah[2][4];
    ldsm4(ah[0], Abase + aoff);
    ldsm4(ah[1], Abase + aoff + 16 * astr);
    uint32_t boff = (uint32_t)((colbase + (g >> 1) * 8 + l7) * RS2 + kb2 + (g & 1) * 16);
    #pragma unroll
    for (int fp = 0; fp < 2; ++fp) {
        uint32_t bh[4];
        ldsm4(bh, Bh + boff + fp * 16 * RS2);
        #pragma unroll
        for (int half = 0; half < 2; ++half) {
            int f = fp * 2 + half;
            uint32_t b0h = bh[half * 2], b1h = bh[half * 2 + 1];
            #pragma unroll
            for (int mi = 0; mi < 2; ++mi)
                mma16816(acc[mi][f], ah[mi][0], ah[mi][1], ah[mi][2], ah[mi][3], b0h, b1h);
        }
    }
    uint32_t boff2 = (uint32_t)((colbase + 32 + l7) * RS2 + kb2 + ((lane >> 3) & 1) * 16);
    uint32_t bh2[2];
    ldsm2(bh2, Bh + boff2);
    #pragma unroll
    for (int mi = 0; mi < 2; ++mi)
        mma16816(acc[mi][4], ah[mi][0], ah[mi][1], ah[mi][2], ah[mi][3], bh2[0], bh2[1]);
}

// wide MMA inner step for T1: 32x80 warp tile, 2 m-frags x 10 n-frags.
__device__ __forceinline__ void mma_chunk10(float (*acc)[10][4],
        uint32_t Abase, uint32_t Bh, int s, int rowbase, int colbase, int lane) {
    int kb2 = s * 32;
    int l7 = lane & 7, g = lane >> 3;
    uint32_t aoff = (uint32_t)((rowbase + (g & 1) * 8 + l7) * RS2 + kb2 + (g >> 1) * 16);
    uint32_t ah[2][4];
    ldsm4(ah[0], Abase + aoff);
    ldsm4(ah[1], Abase + aoff + 16 * RS2);
    uint32_t boff = (uint32_t)((colbase + (g >> 1) * 8 + l7) * RS2 + kb2 + (g & 1) * 16);
    #pragma unroll
    for (int fp = 0; fp < 5; ++fp) {
        uint32_t bh[4];
        ldsm4(bh, Bh + boff + fp * 16 * RS2);
        #pragma unroll
        for (int half = 0; half < 2; ++half) {
            int f = fp * 2 + half;
            uint32_t b0h = bh[half * 2], b1h = bh[half * 2 + 1];
            #pragma unroll
            for (int mi = 0; mi < 2; ++mi)
                mma16816(acc[mi][f], ah[mi][0], ah[mi][1], ah[mi][2], ah[mi][3], b0h, b1h);
        }
    }
}

// ===================== weight prep =====================

__global__ void prep_wtiles(const float* __restrict__ W1) {
    int q = blockIdx.x;   // K-chunk of 32
    int t = threadIdx.x;
    __half* ch = (__half*)d_WcTh;
    for (int idx = t; idx < 160 * 32; idx += 256) {
        int n = idx >> 5, kk = idx & 31, k = q * 32 + kk;
        float v = (k < GI && n < HID) ? W1[(2 * GI + k) * HID + n] : 0.f;
        ch[(size_t)q * 5120 + (size_t)n * 32 + kk] = __float2half_rn(v);
    }
    __half* ah = (__half*)d_WabTh;
    for (int idx = t; idx < 320 * 32; idx += 256) {
        int n = idx >> 5, kk = idx & 31, k = q * 32 + kk;
        float v = 0.f;
        if (k < GI) {
            if (n < HID)                        v = W1[k * HID + n];
            else if (n >= 160 && n < 160 + HID) v = W1[(GI + k) * HID + (n - 160)];
        }
        ah[(size_t)q * 10240 + (size_t)n * 32 + kk] = __float2half_rn(v);
    }
}

__global__ void prep_w2(const float* __restrict__ W2) {
    int q = blockIdx.x;   // 0..4
    int t = threadIdx.x;
    __half* wh = (__half*)d_W2Th;
    for (int idx = t; idx < 160 * 32; idx += 256) {
        int n = idx >> 5, kk = idx & 31, k = q * 32 + kk;
        float v = (k < HID && n < HID) ? W2[k * HID + n] : 0.f;
        wh[(size_t)q * 5120 + (size_t)n * 32 + kk] = __float2half_rn(v);
    }
}

__global__ void prep_tabs(const float* __restrict__ de, const float* __restrict__ ge,
                          const float* __restrict__ se, const float* __restrict__ W1,
                          const float* __restrict__ b1) {
    int c = threadIdx.x;     // 0..159
    for (int d = 0; d < 9; ++d) {
        float v = 0.f;
        if (c < HID) {
            v = b1[c];
            for (int t = 0; t < 20; ++t) v += de[d*20 + t] * W1[(3*GI + t) * HID + c];
        }
        d_Dt[d * CPAD + c] = v;
    }
    for (int g = 0; g < 8; ++g) {
        float v = 0.f;
        if (c < HID)
            for (int t = 0; t < 20; ++t) v += ge[g*20 + t] * W1[(3*GI + 20 + t) * HID + c];
        d_Gt[g * CPAD + c] = v;
    }
    for (int s = 0; s < 3; ++s) {
        float v = 0.f;
        if (c < HID)
            for (int t = 0; t < 20; ++t) v += se[s*20 + t] * W1[(3*GI + 40 + t) * HID + c];
        d_St[s * CPAD + c] = v;
    }
}

// ===================== T1: AB = g @ [W1a|W1b] full 320 cols; emits d_gh; g read ONCE =====================
// smem: A bufs @0 (2 x 5120) -> 10240, B bufs @10240 (2 x 25600) -> 61440
#define T1_B    10240
#define T1_SMEM 61440

__device__ __forceinline__ void cpB_T1(uint32_t bh, int q, int t) {
    const uint4* sH = d_WabTh + (size_t)q * 1280;
    #pragma unroll
    for (int i = 0; i < 5; ++i) {
        int idx = t + 256 * i;              // 0..1279
        int n = idx >> 2, seg = idx & 3;
        cp16(bh + n * RS2 + seg * 16, sH + idx);
    }
}

__device__ __forceinline__ void ldgRow2(const float4* grow, int kb0, float4 x[2]) {
    #pragma unroll
    for (int u = 0; u < 2; ++u) {
        int kb = kb0 + 4 * u;
        x[u] = (kb < GI) ? grow[kb >> 2] : make_float4(0.f, 0.f, 0.f, 0.f);
    }
}
__device__ __forceinline__ void stsRow2(unsigned char* Ah, int r, int koff, const float4 x[2],
                                        __half* ghrow, int kb0) {
    ull h0 = cvt4h(x[0]);
    ull h1v = cvt4h(x[1]);
    uint32_t off = (uint32_t)(r * RS2 + koff * 2);
    *(ull*)(Ah + off)     = h0;
    *(ull*)(Ah + off + 8) = h1v;
    if (kb0 + 8 <= GHW) {
        uint4 v;
        v.x = (uint32_t)h0;  v.y = (uint32_t)(h0 >> 32);
        v.z = (uint32_t)h1v; v.w = (uint32_t)(h1v >> 32);
        *(uint4*)(ghrow + kb0) = v;
    }
}

__global__ __launch_bounds__(256, 2) void gemm_ab_pipe(const float* __restrict__ g, int N) {
    extern __shared__ unsigned char sm[];
    uint32_t sb = smem_to_u32(sm);
    int t = threadIdx.x, wid = t >> 5, lane = t & 31;
    int g4 = lane >> 2, tq = lane & 3;
    int wr = wid & 1, wc = wid >> 1;              // 2 x 4 warp grid (32 x 80 tiles)
    int rowbase = wr * 32, colbase = wc * 80;
    int n0 = blockIdx.x * 64;
    int r = t >> 2, q4 = t & 3, kth = 8 * q4;     // A staging: 64 rows, 8 floats/thread
    int row = n0 + r; if (row >= N) row = N - 1;
    const float4* grow = (const float4*)(g + (size_t)row * GI);
    __half* ghrow = d_gh + (size_t)row * GHW;

    float acc[2][10][4];
    #pragma unroll
    for (int mi = 0; mi < 2; ++mi)
        #pragma unroll
        for (int f = 0; f < 10; ++f)
            #pragma unroll
            for (int e = 0; e < 4; ++e) acc[mi][f][e] = 0.f;

    // prologue: stage chunk 0
    {
        float4 x[2];
        ldgRow2(grow, kth, x);
        stsRow2(sm, r, kth, x, ghrow, kth);
        cpB_T1(sb + T1_B, 0, t);
        CP_COMMIT(); CP_WAIT0();
    }
    __syncthreads();

    for (int q = 0; q < NCH2; ++q) {
        int cb = q & 1, nb = cb ^ 1;
        uint32_t Ah = sb + cb * 5120;
        uint32_t Bh = sb + T1_B + cb * 25600;
        unsigned char* nAh = sm + nb * 5120;
        bool more = (q + 1 < NCH2);
        if (more) { cpB_T1(sb + T1_B + nb * 25600, q + 1, t); CP_COMMIT(); }
        float4 x0[2];
        int kn = (q + 1) * 32 + kth;
        if (more) ldgRow2(grow, kn, x0);
        mma_chunk10(acc, Ah, Bh, 0, rowbase, colbase, lane);
        mma_chunk10(acc, Ah, Bh, 1, rowbase, colbase, lane);
        if (more) { stsRow2(nAh, r, kth, x0, ghrow, kn); CP_WAIT0(); }
        __syncthreads();
    }

    #pragma unroll
    for (int mi = 0; mi < 2; ++mi) {
        #pragma unroll
        for (int f = 0; f < 10; ++f) {
            int rr = rowbase + mi * 16 + g4;
            int col = colbase + f * 8 + 2 * tq;
            int n = n0 + rr;
            if (n < N)
                *(float2*)(d_AB + (size_t)n * ABS + col) = make_float2(acc[mi][f][0], acc[mi][f][1]);
            n = n0 + rr + 8;
            if (n < N)
                *(float2*)(d_AB + (size_t)n * ABS + col) = make_float2(acc[mi][f][2], acc[mi][f][3]);
        }
    }
}

// ===================== T2 fused: bilinear MMA (fp16 gather) + epilogue + layer2 MMA + out =====================
#define F_A    2560
#define F_B    12800
#define F_STG  2560
#define F_W2B  2560
#define F_H1H  45568
#define F_RP   67072
#define F_SMEM 68096
#define SSTR   168

__device__ __forceinline__ void cpB_tiles(uint32_t bh, const uint4* srcBase, int q, int t) {
    const uint4* sH = srcBase + (size_t)q * 640;
    #pragma unroll
    for (int i = 0; i < 3; ++i) {
        int idx = t + 256 * i;
        if (idx < 640) {
            int n = idx >> 2, seg = idx & 3;
            cp16(bh + n * RS2 + seg * 16, sH + idx);
        }
    }
}

__device__ __forceinline__ void ldgPair2h(const uint4* ir, const uint4* jr, int kb0,
                                          uint4& xi, uint4& xj) {
    if (kb0 + 8 <= GHW) { xi = ir[kb0 >> 3]; xj = jr[kb0 >> 3]; }
    else { xi = make_uint4(0, 0, 0, 0); xj = xi; }
}
__device__ __forceinline__ void stsPair2h(unsigned char* Ah, int r, int koff,
                                          uint4 xi, uint4 xj) {
    uint4 p;
    *(__half2*)&p.x = __hmul2(*(__half2*)&xi.x, *(__half2*)&xj.x);
    *(__half2*)&p.y = __hmul2(*(__half2*)&xi.y, *(__half2*)&xj.y);
    *(__half2*)&p.z = __hmul2(*(__half2*)&xi.z, *(__half2*)&xj.z);
    *(__half2*)&p.w = __hmul2(*(__half2*)&xi.w, *(__half2*)&xj.w);
    *(uint4*)(Ah + r * RS2 + koff * 2) = p;
}

__global__ __launch_bounds__(256, 3) void bilinear_fused(
    const float* __restrict__ ms,
    const float* __restrict__ b2, const float* __restrict__ W3,
    const float* __restrict__ b3,
    const int* __restrict__ mid,  const int* __restrict__ aid,
    const int* __restrict__ did,  const int* __restrict__ gid,
    const int* __restrict__ sid,
    float* __restrict__ out, int P)
{
    extern __shared__ unsigned char sm[];
    uint32_t sb = smem_to_u32(sm);
    int t = threadIdx.x, wid = t >> 5, lane = t & 31;
    int g4 = lane >> 2, tq = lane & 3;
    int wr = wid & 1, wc = wid >> 1;              // 2 x 4 warp grid (32 x 40 tiles)
    int rowbase = wr * 32, colbase = wc * 40;
    int p0 = blockIdx.x * 64;
    int* sm_m = (int*)sm;
    int* sm_a = (int*)(sm + 256);
    int* sm_d = (int*)(sm + 512);
    int* sm_g = (int*)(sm + 768);
    int* sm_s = (int*)(sm + 1024);
    float* w3s = (float*)(sm + 1280);
    float* b2s = (float*)(sm + 1920);

    if (t < 64) {
        int p = p0 + t; if (p >= P) p = P - 1;
        sm_m[t] = mid[p]; sm_a[t] = aid[p]; sm_d[t] = did[p]; sm_g[t] = gid[p]; sm_s[t] = sid[p];
    }
    if (t < CPAD) {
        w3s[t] = (t < HID) ? W3[t] : 0.f;
        b2s[t] = (t < HID) ? b2[t] : 0.f;
    }
    __syncthreads();

    int r = t >> 2, q4 = t & 3, kth = 8 * q4;     // A staging: 64 rows, 8 halves/thread
    const uint4* ir = (const uint4*)(d_gh + (size_t)sm_m[r] * GHW);
    const uint4* jr = (const uint4*)(d_gh + (size_t)sm_a[r] * GHW);

    float acc[2][5][4];
    #pragma unroll
    for (int mi = 0; mi < 2; ++mi)
        #pragma unroll
        for (int f = 0; f < 5; ++f)
            #pragma unroll
            for (int e = 0; e < 4; ++e) acc[mi][f][e] = 0.f;

    // prologue: stage chunk 0
    {
        uint4 xi, xj;
        ldgPair2h(ir, jr, kth, xi, xj);
        stsPair2h(sm + F_A, r, kth, xi, xj);
        cpB_tiles(sb + F_B, d_WcTh, 0, t);
        CP_COMMIT(); CP_WAIT0();
    }
    __syncthreads();

    for (int q = 0; q < NCH2; ++q) {
        int cb = q & 1, nb = cb ^ 1;
        uint32_t Ah = sb + F_A + cb * 5120;
        uint32_t Bh = sb + F_B + cb * 12800;
        unsigned char* nAh = sm + F_A + nb * 5120;
        bool more = (q + 1 < NCH2);
        if (more) { cpB_tiles(sb + F_B + nb * 12800, d_WcTh, q + 1, t); CP_COMMIT(); }
        uint4 xi, xj;
        int kn = (q + 1) * 32 + kth;
        if (more) ldgPair2h(ir, jr, kn, xi, xj);
        mma_chunk5g(acc, Ah, Bh, 0, rowbase, colbase, lane, RS2, 0);
        mma_chunk5g(acc, Ah, Bh, 1, rowbase, colbase, lane, RS2, 0);
        if (more) { stsPair2h(nAh, r, kth, xi, xj); CP_WAIT0(); }
        __syncthreads();
    }

    // ---- stage acc -> smem fp32 [64 x 168] (aliases A/B bufs; loop done) ----
    float* stg = (float*)(sm + F_STG);
    __syncthreads();
    #pragma unroll
    for (int mi = 0; mi < 2; ++mi) {
        #pragma unroll
        for (int f = 0; f < 5; ++f) {
            int rr = rowbase + mi * 16 + g4;
            int col = colbase + f * 8 + 2 * tq;
            *(float2*)(stg + rr * SSTR + col) = make_float2(acc[mi][f][0], acc[mi][f][1]);
            *(float2*)(stg + (rr + 8) * SSTR + col) = make_float2(acc[mi][f][2], acc[mi][f][3]);
        }
    }
    __syncthreads();

    // ---- epilogue 1: h1 = relu(bil + AB[m] + AB[a]+160 + tabs) -> fp16 h1h ----
    int tx = t & 15, ty = t >> 4;                 // ty 0..15: 4 rows each
    __half* h1h = (__half*)(sm + F_H1H);          // stride 168 halves (336 B)
    {
        const float2* AB2 = (const float2*)d_AB;
        const float2* Dt2 = (const float2*)d_Dt;
        const float2* Gt2 = (const float2*)d_Gt;
        const float2* St2 = (const float2*)d_St;
        #pragma unroll
        for (int j = 0; j < 4; ++j) {
            int rr = ty * 4 + j;
            const float2* am = AB2 + (size_t)sm_m[rr] * 160;
            const float2* bm = AB2 + (size_t)sm_a[rr] * 160 + 80;
            const float2* dp = Dt2 + sm_d[rr] * 80;
            const float2* gp = Gt2 + sm_g[rr] * 80;
            const float2* sp = St2 + sm_s[rr] * 80;
            #pragma unroll
            for (int c = 0; c < 5; ++c) {
                int cp = tx + 16 * c;
                float2 v  = *(float2*)(stg + rr * SSTR + 2 * cp);
                float2 t1 = am[cp], t2 = bm[cp], t3 = dp[cp], t4 = gp[cp], t5 = sp[cp];
                float hx = fmaxf(v.x + t1.x + t2.x + t3.x + t4.x + t5.x, 0.f);
                float hy = fmaxf(v.y + t1.y + t2.y + t3.y + t4.y + t5.y, 0.f);
                *(__half2*)(h1h + rr * SSTR + 2 * cp) = __floats2half2_rn(hx, hy);
            }
        }
    }

    // ---- layer 2 via MMA: h2 = h1h @ W2 (5 k-chunks of 32, single-buffered W2T) ----
    float acc2[2][5][4];
    #pragma unroll
    for (int mi = 0; mi < 2; ++mi)
        #pragma unroll
        for (int f = 0; f < 5; ++f)
            #pragma unroll
            for (int e = 0; e < 4; ++e) acc2[mi][f][e] = 0.f;

    for (int q2 = 0; q2 < 5; ++q2) {
        __syncthreads();                            // stg reads / prev MMA done
        cpB_tiles(sb + F_W2B, d_W2Th, q2, t);
        CP_COMMIT(); CP_WAIT0();
        __syncthreads();                            // W2T + h1h visible
        mma_chunk5g(acc2, sb + F_H1H, sb + F_W2B, 0, rowbase, colbase, lane, H1S, q2 * 64);
        mma_chunk5g(acc2, sb + F_H1H, sb + F_W2B, 1, rowbase, colbase, lane, H1S, q2 * 64);
    }

    // ---- epilogue 2: out = relu(h2 + b2) . W3 + b3 + ms terms ----
    float pr[4] = {0.f, 0.f, 0.f, 0.f};
    #pragma unroll
    for (int f = 0; f < 5; ++f) {
        int c0 = colbase + f * 8 + 2 * tq;
        float w3a = w3s[c0], w3b = w3s[c0 + 1];
        float b2a = b2s[c0], b2b = b2s[c0 + 1];
        #pragma unroll
        for (int mi = 0; mi < 2; ++mi) {
            pr[mi * 2 + 0] += fmaxf(acc2[mi][f][0] + b2a, 0.f) * w3a
                            + fmaxf(acc2[mi][f][1] + b2b, 0.f) * w3b;
            pr[mi * 2 + 1] += fmaxf(acc2[mi][f][2] + b2a, 0.f) * w3a
                            + fmaxf(acc2[mi][f][3] + b2b, 0.f) * w3b;
        }
    }
    #pragma unroll
    for (int k = 0; k < 4; ++k) {
        pr[k] += __shfl_xor_sync(0xffffffffu, pr[k], 1);
        pr[k] += __shfl_xor_sync(0xffffffffu, pr[k], 2);
    }
    float* rowpart = (float*)(sm + F_RP);
    if (tq == 0) {
        #pragma unroll
        for (int mi = 0; mi < 2; ++mi) {
            int rr = rowbase + mi * 16 + g4;
            rowpart[wc * 64 + rr]     = pr[mi * 2 + 0];
            rowpart[wc * 64 + rr + 8] = pr[mi * 2 + 1];
        }
    }
    __syncthreads();
    if (t < 64) {
        float v = rowpart[t] + rowpart[64 + t] + rowpart[128 + t] + rowpart[192 + t];
        int p = p0 + t;
        if (p < P)
            out[p] = v + b3[0] + ms[sm_m[t]] + ms[sm_a[t]];
    }
}

// ===================== launch =====================

extern "C" void kernel_launch(void* const* d_in, const int* in_sizes, int n_in,
                              void* d_out, int out_size)
{
    const float* g_i = (const float*)d_in[0];
    const float* ms  = (const float*)d_in[1];
    const float* de  = (const float*)d_in[2];
    const float* ge  = (const float*)d_in[3];
    const float* se  = (const float*)d_in[4];
    const float* W1  = (const float*)d_in[5];
    const float* b1  = (const float*)d_in[6];
    const float* W2  = (const float*)d_in[7];
    const float* b2  = (const float*)d_in[8];
    const float* W3  = (const float*)d_in[9];
    const float* b3  = (const float*)d_in[10];
    const int*   mid = (const int*)d_in[11];
    const int*   aid = (const int*)d_in[12];
    const int*   did = (const int*)d_in[13];
    const int*   gid = (const int*)d_in[14];
    const int*   sid = (const int*)d_in[15];

    int N = in_sizes[0] / GI;
    if (N > NMAX) N = NMAX;
    int P = in_sizes[11];
    if (P > PMAX) P = PMAX;
    float* out = (float*)d_out;

    prep_wtiles<<<NCH2, 256>>>(W1);
    prep_w2<<<5, 256>>>(W2);
    prep_tabs<<<1, CPAD>>>(de, ge, se, W1, b1);

    cudaFuncSetAttribute(gemm_ab_pipe, cudaFuncAttributeMaxDynamicSharedMemorySize, T1_SMEM);
    gemm_ab_pipe<<<(N + 63) / 64, 256, T1_SMEM>>>(g_i, N);

    cudaFuncSetAttribute(bilinear_fused, cudaFuncAttributeMaxDynamicSharedMemorySize, F_SMEM);
    bilinear_fused<<<(P + 63) / 64, 256, F_SMEM>>>(ms, b2, W3, b3,
                                                   mid, aid, did, gid, sid, out, P);
}

// round 16
// speedup vs baseline: 4.2618x; 1.0947x over previous
#include <cuda_runtime.h>
#include <cuda_fp16.h>
#include <cstdint>

typedef unsigned long long ull;

#define GI   1220
#define GHW  1232      // padded fp16 g row (16B-aligned)
#define HID  150
#define NMAX 50000
#define PMAX 100000
#define CPAD 160
#define ABS  320
#define NCH2 39        // K chunks of 32
#define RS2  80        // smem row stride (bytes) for fp16 chunk-32 tiles -> conflict-free LDSM
#define H1S  336       // h1 fp16 row stride bytes (84r mod 32 distinct -> conflict-free)

// ===================== device scratch (no allocations allowed) =====================
__device__ float  d_AB[(size_t)NMAX * ABS];      // 64 MB: per-mention  g@[W1a|W1b]
__device__ __half d_gh[(size_t)NMAX * GHW];      // 123 MB: fp16 image of g (zero-padded cols)
__device__ uint4  d_WcTh[NCH2 * 10240 / 16];     // W1c^T fp16 tiles [160 x 32] per chunk
__device__ uint4  d_WabTh[NCH2 * 20480 / 16];    // [W1a|W1b]^T fp16 tiles [320 x 32] per chunk
__device__ uint4  d_W2Th[5 * 10240 / 16];        // W2^T fp16 tiles [160 x 32] per k-chunk
__device__ float  d_Dt[9 * CPAD];                // dist table (+b1)
__device__ float  d_Gt[8 * CPAD];
__device__ float  d_St[3 * CPAD];

// ===================== helpers =====================
__device__ __forceinline__ uint32_t smem_to_u32(const void* p) {
    uint32_t a;
    asm("{ .reg .u64 t; cvta.to.shared.u64 t, %1; cvt.u32.u64 %0, t; }" : "=r"(a) : "l"(p));
    return a;
}

__device__ __forceinline__ void mma16816(float c[4],
                                         uint32_t a0, uint32_t a1, uint32_t a2, uint32_t a3,
                                         uint32_t b0, uint32_t b1) {
    asm volatile(
        "mma.sync.aligned.m16n8k16.row.col.f32.f16.f16.f32 "
        "{%0,%1,%2,%3}, {%4,%5,%6,%7}, {%8,%9}, {%0,%1,%2,%3};"
        : "+f"(c[0]), "+f"(c[1]), "+f"(c[2]), "+f"(c[3])
        : "r"(a0), "r"(a1), "r"(a2), "r"(a3), "r"(b0), "r"(b1));
}

__device__ __forceinline__ void ldsm4(uint32_t r[4], uint32_t addr) {
    asm volatile("ldmatrix.sync.aligned.m8n8.x4.shared.b16 {%0,%1,%2,%3}, [%4];"
        : "=r"(r[0]), "=r"(r[1]), "=r"(r[2]), "=r"(r[3]) : "r"(addr));
}

__device__ __forceinline__ void cp16(uint32_t dst, const void* src) {
    asm volatile("cp.async.cg.shared.global [%0], [%1], 16;" :: "r"(dst), "l"(src));
}
#define CP_COMMIT() asm volatile("cp.async.commit_group;" ::: "memory")
#define CP_WAIT0()  asm volatile("cp.async.wait_group 0;" ::: "memory")

union HPack { __half v[4]; ull u; };
__device__ __forceinline__ ull cvt4h(float4 x) {
    HPack H;
    H.v[0] = __float2half_rn(x.x);
    H.v[1] = __float2half_rn(x.y);
    H.v[2] = __float2half_rn(x.z);
    H.v[3] = __float2half_rn(x.w);
    return H.u;
}

// wide MMA inner step: 32x80 warp tile, 2 m-frags x 10 n-frags, single fp16 pass.
// A from (Abase, astr bytes, akoff bytes); B chunk-32, stride RS2.  s in {0,1}.
__device__ __forceinline__ void mma_chunk10(float (*acc)[10][4],
        uint32_t Abase, uint32_t Bh, int s, int rowbase, int colbase, int lane,
        int astr, int akoff) {
    int kb2 = s * 32;
    int l7 = lane & 7, g = lane >> 3;
    uint32_t aoff = (uint32_t)((rowbase + (g & 1) * 8 + l7) * astr + akoff + kb2 + (g >> 1) * 16);
    uint32_t ah[2][4];
    ldsm4(ah[0], Abase + aoff);
    ldsm4(ah[1], Abase + aoff + 16 * astr);
    uint32_t boff = (uint32_t)((colbase + (g >> 1) * 8 + l7) * RS2 + kb2 + (g & 1) * 16);
    #pragma unroll
    for (int fp = 0; fp < 5; ++fp) {
        uint32_t bh[4];
        ldsm4(bh, Bh + boff + fp * 16 * RS2);
        #pragma unroll
        for (int half = 0; half < 2; ++half) {
            int f = fp * 2 + half;
            uint32_t b0h = bh[half * 2], b1h = bh[half * 2 + 1];
            #pragma unroll
            for (int mi = 0; mi < 2; ++mi)
                mma16816(acc[mi][f], ah[mi][0], ah[mi][1], ah[mi][2], ah[mi][3], b0h, b1h);
        }
    }
}

// ===================== weight prep =====================

__global__ void prep_wtiles(const float* __restrict__ W1) {
    int q = blockIdx.x;   // K-chunk of 32
    int t = threadIdx.x;
    __half* ch = (__half*)d_WcTh;
    for (int idx = t; idx < 160 * 32; idx += 256) {
        int n = idx >> 5, kk = idx & 31, k = q * 32 + kk;
        float v = (k < GI && n < HID) ? W1[(2 * GI + k) * HID + n] : 0.f;
        ch[(size_t)q * 5120 + (size_t)n * 32 + kk] = __float2half_rn(v);
    }
    __half* ah = (__half*)d_WabTh;
    for (int idx = t; idx < 320 * 32; idx += 256) {
        int n = idx >> 5, kk = idx & 31, k = q * 32 + kk;
        float v = 0.f;
        if (k < GI) {
            if (n < HID)                        v = W1[k * HID + n];
            else if (n >= 160 && n < 160 + HID) v = W1[(GI + k) * HID + (n - 160)];
        }
        ah[(size_t)q * 10240 + (size_t)n * 32 + kk] = __float2half_rn(v);
    }
}

__global__ void prep_w2(const float* __restrict__ W2) {
    int q = blockIdx.x;   // 0..4
    int t = threadIdx.x;
    __half* wh = (__half*)d_W2Th;
    for (int idx = t; idx < 160 * 32; idx += 256) {
        int n = idx >> 5, kk = idx & 31, k = q * 32 + kk;
        float v = (k < HID && n < HID) ? W2[k * HID + n] : 0.f;
        wh[(size_t)q * 5120 + (size_t)n * 32 + kk] = __float2half_rn(v);
    }
}

__global__ void prep_tabs(const float* __restrict__ de, const float* __restrict__ ge,
                          const float* __restrict__ se, const float* __restrict__ W1,
                          const float* __restrict__ b1) {
    int c = threadIdx.x;     // 0..159
    for (int d = 0; d < 9; ++d) {
        float v = 0.f;
        if (c < HID) {
            v = b1[c];
            for (int t = 0; t < 20; ++t) v += de[d*20 + t] * W1[(3*GI + t) * HID + c];
        }
        d_Dt[d * CPAD + c] = v;
    }
    for (int g = 0; g < 8; ++g) {
        float v = 0.f;
        if (c < HID)
            for (int t = 0; t < 20; ++t) v += ge[g*20 + t] * W1[(3*GI + 20 + t) * HID + c];
        d_Gt[g * CPAD + c] = v;
    }
    for (int s = 0; s < 3; ++s) {
        float v = 0.f;
        if (c < HID)
            for (int t = 0; t < 20; ++t) v += se[s*20 + t] * W1[(3*GI + 40 + t) * HID + c];
        d_St[s * CPAD + c] = v;
    }
}

// ===================== T1: AB = g @ [W1a|W1b] full 320 cols; emits d_gh; g read ONCE =====================
// smem: A bufs @0 (2 x 5120) -> 10240, B bufs @10240 (2 x 25600) -> 61440
#define T1_B    10240
#define T1_SMEM 61440

__device__ __forceinline__ void cpB_T1(uint32_t bh, int q, int t) {
    const uint4* sH = d_WabTh + (size_t)q * 1280;
    #pragma unroll
    for (int i = 0; i < 5; ++i) {
        int idx = t + 256 * i;              // 0..1279
        int n = idx >> 2, seg = idx & 3;
        cp16(bh + n * RS2 + seg * 16, sH + idx);
    }
}

__device__ __forceinline__ void ldgRow2(const float4* grow, int kb0, float4 x[2]) {
    #pragma unroll
    for (int u = 0; u < 2; ++u) {
        int kb = kb0 + 4 * u;
        x[u] = (kb < GI) ? grow[kb >> 2] : make_float4(0.f, 0.f, 0.f, 0.f);
    }
}
__device__ __forceinline__ void stsRow2(unsigned char* Ah, int r, int koff, const float4 x[2],
                                        __half* ghrow, int kb0) {
    ull h0 = cvt4h(x[0]);
    ull h1v = cvt4h(x[1]);
    uint32_t off = (uint32_t)(r * RS2 + koff * 2);
    *(ull*)(Ah + off)     = h0;
    *(ull*)(Ah + off + 8) = h1v;
    if (kb0 + 8 <= GHW) {
        uint4 v;
        v.x = (uint32_t)h0;  v.y = (uint32_t)(h0 >> 32);
        v.z = (uint32_t)h1v; v.w = (uint32_t)(h1v >> 32);
        *(uint4*)(ghrow + kb0) = v;
    }
}

__global__ __launch_bounds__(256, 2) void gemm_ab_pipe(const float* __restrict__ g, int N) {
    extern __shared__ unsigned char sm[];
    uint32_t sb = smem_to_u32(sm);
    int t = threadIdx.x, wid = t >> 5, lane = t & 31;
    int g4 = lane >> 2, tq = lane & 3;
    int wr = wid & 1, wc = wid >> 1;              // 2 x 4 warp grid (32 x 80 tiles)
    int rowbase = wr * 32, colbase = wc * 80;
    int n0 = blockIdx.x * 64;
    int r = t >> 2, q4 = t & 3, kth = 8 * q4;     // A staging: 64 rows, 8 floats/thread
    int row = n0 + r; if (row >= N) row = N - 1;
    const float4* grow = (const float4*)(g + (size_t)row * GI);
    __half* ghrow = d_gh + (size_t)row * GHW;

    float acc[2][10][4];
    #pragma unroll
    for (int mi = 0; mi < 2; ++mi)
        #pragma unroll
        for (int f = 0; f < 10; ++f)
            #pragma unroll
            for (int e = 0; e < 4; ++e) acc[mi][f][e] = 0.f;

    // prologue: stage chunk 0
    {
        float4 x[2];
        ldgRow2(grow, kth, x);
        stsRow2(sm, r, kth, x, ghrow, kth);
        cpB_T1(sb + T1_B, 0, t);
        CP_COMMIT(); CP_WAIT0();
    }
    __syncthreads();

    for (int q = 0; q < NCH2; ++q) {
        int cb = q & 1, nb = cb ^ 1;
        uint32_t Ah = sb + cb * 5120;
        uint32_t Bh = sb + T1_B + cb * 25600;
        unsigned char* nAh = sm + nb * 5120;
        bool more = (q + 1 < NCH2);
        if (more) { cpB_T1(sb + T1_B + nb * 25600, q + 1, t); CP_COMMIT(); }
        float4 x0[2];
        int kn = (q + 1) * 32 + kth;
        if (more) ldgRow2(grow, kn, x0);
        mma_chunk10(acc, Ah, Bh, 0, rowbase, colbase, lane, RS2, 0);
        mma_chunk10(acc, Ah, Bh, 1, rowbase, colbase, lane, RS2, 0);
        if (more) { stsRow2(nAh, r, kth, x0, ghrow, kn); CP_WAIT0(); }
        __syncthreads();
    }

    #pragma unroll
    for (int mi = 0; mi < 2; ++mi) {
        #pragma unroll
        for (int f = 0; f < 10; ++f) {
            int rr = rowbase + mi * 16 + g4;
            int col = colbase + f * 8 + 2 * tq;
            int n = n0 + rr;
            if (n < N)
                *(float2*)(d_AB + (size_t)n * ABS + col) = make_float2(acc[mi][f][0], acc[mi][f][1]);
            n = n0 + rr + 8;
            if (n < N)
                *(float2*)(d_AB + (size_t)n * ABS + col) = make_float2(acc[mi][f][2], acc[mi][f][3]);
        }
    }
}

// ===================== T2 fused (128 pairs/CTA): bilinear MMA + reg epilogue + layer2 MMA =====================
// smem map:
//  0..2560      indices m/a/d/g/s (5 x 512B)
//  2560..3200   w3s (160 f)    3200..3840  b2s (160 f)
//  3840..24320  A bufs (2 x 10240)   [main loop]
//  24320..49920 B bufs (2 x 12800)   [main loop]
//  3840..46848  h1h fp16 [128 x 168h, stride 336B]   (aliases A/B after loop)
//  49920..62720 W2T buf (12800)
//  62720..63744 rowpart [2][128] f
#define F_A    3840
#define F_B    24320
#define F_H1H  3840
#define F_W2B  49920
#define F_RP   62720
#define F_SMEM 63744

__device__ __forceinline__ void cpB_tiles(uint32_t bh, const uint4* srcBase, int q, int t) {
    const uint4* sH = srcBase + (size_t)q * 640;
    #pragma unroll
    for (int i = 0; i < 3; ++i) {
        int idx = t + 256 * i;
        if (idx < 640) {
            int n = idx >> 2, seg = idx & 3;
            cp16(bh + n * RS2 + seg * 16, sH + idx);
        }
    }
}

__device__ __forceinline__ void ldgPair128(const uint4* ir, const uint4* jr, int kb0,
                                           uint4 xi[2], uint4 xj[2]) {
    #pragma unroll
    for (int u = 0; u < 2; ++u) {
        int kb = kb0 + 8 * u;
        if (kb + 8 <= GHW) { xi[u] = ir[kb >> 3]; xj[u] = jr[kb >> 3]; }
        else { xi[u] = make_uint4(0, 0, 0, 0); xj[u] = xi[u]; }
    }
}
__device__ __forceinline__ void stsPair128(unsigned char* Ah, int r, int koff,
                                           const uint4 xi[2], const uint4 xj[2]) {
    #pragma unroll
    for (int u = 0; u < 2; ++u) {
        uint4 p;
        *(__half2*)&p.x = __hmul2(*(__half2*)&xi[u].x, *(__half2*)&xj[u].x);
        *(__half2*)&p.y = __hmul2(*(__half2*)&xi[u].y, *(__half2*)&xj[u].y);
        *(__half2*)&p.z = __hmul2(*(__half2*)&xi[u].z, *(__half2*)&xj[u].z);
        *(__half2*)&p.w = __hmul2(*(__half2*)&xi[u].w, *(__half2*)&xj[u].w);
        *(uint4*)(Ah + r * RS2 + (koff + 8 * u) * 2) = p;
    }
}

__global__ __launch_bounds__(256, 2) void bilinear_fused(
    const float* __restrict__ ms,
    const float* __restrict__ b2, const float* __restrict__ W3,
    const float* __restrict__ b3,
    const int* __restrict__ mid,  const int* __restrict__ aid,
    const int* __restrict__ did,  const int* __restrict__ gid,
    const int* __restrict__ sid,
    float* __restrict__ out, int P)
{
    extern __shared__ unsigned char sm[];
    uint32_t sb = smem_to_u32(sm);
    int t = threadIdx.x, wid = t >> 5, lane = t & 31;
    int g4 = lane >> 2, tq = lane & 3;
    int wr = wid >> 1, wc = wid & 1;              // 4 x 2 warp grid (32 x 80 tiles)
    int rowbase = wr * 32, colbase = wc * 80;
    int p0 = blockIdx.x * 128;
    int* sm_m = (int*)sm;
    int* sm_a = (int*)(sm + 512);
    int* sm_d = (int*)(sm + 1024);
    int* sm_g = (int*)(sm + 1536);
    int* sm_s = (int*)(sm + 2048);
    float* w3s = (float*)(sm + 2560);
    float* b2s = (float*)(sm + 3200);

    if (t < 128) {
        int p = p0 + t; if (p >= P) p = P - 1;
        sm_m[t] = mid[p]; sm_a[t] = aid[p]; sm_d[t] = did[p]; sm_g[t] = gid[p]; sm_s[t] = sid[p];
    }
    if (t < CPAD) {
        w3s[t] = (t < HID) ? W3[t] : 0.f;
        b2s[t] = (t < HID) ? b2[t] : 0.f;
    }
    __syncthreads();

    int r = t >> 1, kth = 16 * (t & 1);           // A staging: 128 rows, 16 halves/thread
    const uint4* ir = (const uint4*)(d_gh + (size_t)sm_m[r] * GHW);
    const uint4* jr = (const uint4*)(d_gh + (size_t)sm_a[r] * GHW);

    float acc[2][10][4];
    #pragma unroll
    for (int mi = 0; mi < 2; ++mi)
        #pragma unroll
        for (int f = 0; f < 10; ++f)
            #pragma unroll
            for (int e = 0; e < 4; ++e) acc[mi][f][e] = 0.f;

    // prologue: stage chunk 0
    {
        uint4 xi[2], xj[2];
        ldgPair128(ir, jr, kth, xi, xj);
        stsPair128(sm + F_A, r, kth, xi, xj);
        cpB_tiles(sb + F_B, d_WcTh, 0, t);
        CP_COMMIT(); CP_WAIT0();
    }
    __syncthreads();

    for (int q = 0; q < NCH2; ++q) {
        int cb = q & 1, nb = cb ^ 1;
        uint32_t Ah = sb + F_A + cb * 10240;
        uint32_t Bh = sb + F_B + cb * 12800;
        unsigned char* nAh = sm + F_A + nb * 10240;
        bool more = (q + 1 < NCH2);
        if (more) { cpB_tiles(sb + F_B + nb * 12800, d_WcTh, q + 1, t); CP_COMMIT(); }
        uint4 xi[2], xj[2];
        int kn = (q + 1) * 32 + kth;
        if (more) ldgPair128(ir, jr, kn, xi, xj);
        mma_chunk10(acc, Ah, Bh, 0, rowbase, colbase, lane, RS2, 0);
        mma_chunk10(acc, Ah, Bh, 1, rowbase, colbase, lane, RS2, 0);
        if (more) { stsPair128(nAh, r, kth, xi, xj); CP_WAIT0(); }
        __syncthreads();
    }

    // ---- epilogue 1 (register-direct): h1 = relu(bil + AB[m] + AB[a]+160 + tabs) -> fp16 h1h ----
    __half* h1h = (__half*)(sm + F_H1H);          // stride 168 halves (336 B); aliases A/B bufs
    {
        const float2* AB2 = (const float2*)d_AB;
        const float2* Dt2 = (const float2*)d_Dt;
        const float2* Gt2 = (const float2*)d_Gt;
        const float2* St2 = (const float2*)d_St;
        #pragma unroll
        for (int mi = 0; mi < 2; ++mi) {
            #pragma unroll
            for (int rh = 0; rh < 2; ++rh) {
                int rr = rowbase + mi * 16 + rh * 8 + g4;
                const float2* am = AB2 + (size_t)sm_m[rr] * 160;
                const float2* bm = AB2 + (size_t)sm_a[rr] * 160 + 80;
                const float2* dp = Dt2 + sm_d[rr] * 80;
                const float2* gp = Gt2 + sm_g[rr] * 80;
                const float2* sp = St2 + sm_s[rr] * 80;
                #pragma unroll
                for (int f = 0; f < 10; ++f) {
                    int cp = colbase / 2 + f * 4 + tq;
                    float2 t1 = am[cp], t2 = bm[cp], t3 = dp[cp], t4 = gp[cp], t5 = sp[cp];
                    float hx = fmaxf(acc[mi][f][rh * 2 + 0] + t1.x + t2.x + t3.x + t4.x + t5.x, 0.f);
                    float hy = fmaxf(acc[mi][f][rh * 2 + 1] + t1.y + t2.y + t3.y + t4.y + t5.y, 0.f);
                    *(__half2*)(h1h + rr * 168 + 2 * cp) = __floats2half2_rn(hx, hy);
                }
            }
        }
    }
    __syncthreads();

    // ---- layer 2 via MMA: h2 = h1h @ W2 (5 k-chunks of 32, single-buffered W2T) ----
    float acc2[2][10][4];
    #pragma unroll
    for (int mi = 0; mi < 2; ++mi)
        #pragma unroll
        for (int f = 0; f < 10; ++f)
            #pragma unroll
            for (int e = 0; e < 4; ++e) acc2[mi][f][e] = 0.f;

    for (int q2 = 0; q2 < 5; ++q2) {
        if (q2) __syncthreads();                    // prev MMA reads of W2 buf done
        cpB_tiles(sb + F_W2B, d_W2Th, q2, t);
        CP_COMMIT(); CP_WAIT0();
        __syncthreads();                            // W2T visible
        mma_chunk10(acc2, sb + F_H1H, sb + F_W2B, 0, rowbase, colbase, lane, H1S, q2 * 64);
        mma_chunk10(acc2, sb + F_H1H, sb + F_W2B, 1, rowbase, colbase, lane, H1S, q2 * 64);
    }

    // ---- epilogue 2: out = relu(h2 + b2) . W3 + b3 + ms terms ----
    float pr[4] = {0.f, 0.f, 0.f, 0.f};
    #pragma unroll
    for (int f = 0; f < 10; ++f) {
        int c0 = colbase + f * 8 + 2 * tq;
        float w3a = w3s[c0], w3b = w3s[c0 + 1];
        float b2a = b2s[c0], b2b = b2s[c0 + 1];
        #pragma unroll
        for (int mi = 0; mi < 2; ++mi) {
            pr[mi * 2 + 0] += fmaxf(acc2[mi][f][0] + b2a, 0.f) * w3a
                            + fmaxf(acc2[mi][f][1] + b2b, 0.f) * w3b;
            pr[mi * 2 + 1] += fmaxf(acc2[mi][f][2] + b2a, 0.f) * w3a
                            + fmaxf(acc2[mi][f][3] + b2b, 0.f) * w3b;
        }
    }
    #pragma unroll
    for (int k = 0; k < 4; ++k) {
        pr[k] += __shfl_xor_sync(0xffffffffu, pr[k], 1);
        pr[k] += __shfl_xor_sync(0xffffffffu, pr[k], 2);
    }
    float* rowpart = (float*)(sm + F_RP);          // [2][128]
    if (tq == 0) {
        #pragma unroll
        for (int mi = 0; mi < 2; ++mi) {
            int rr = rowbase + mi * 16 + g4;
            rowpart[wc * 128 + rr]     = pr[mi * 2 + 0];
            rowpart[wc * 128 + rr + 8] = pr[mi * 2 + 1];
        }
    }
    __syncthreads();
    if (t < 128) {
        float v = rowpart[t] + rowpart[128 + t];
        int p = p0 + t;
        if (p < P)
            out[p] = v + b3[0] + ms[sm_m[t]] + ms[sm_a[t]];
    }
}

// ===================== launch =====================

extern "C" void kernel_launch(void* const* d_in, const int* in_sizes, int n_in,
                              void* d_out, int out_size)
{
    const float* g_i = (const float*)d_in[0];
    const float* ms  = (const float*)d_in[1];
    const float* de  = (const float*)d_in[2];
    const float* ge  = (const float*)d_in[3];
    const float* se  = (const float*)d_in[4];
    const float* W1  = (const float*)d_in[5];
    const float* b1  = (const float*)d_in[6];
    const float* W2  = (const float*)d_in[7];
    const float* b2  = (const float*)d_in[8];
    const float* W3  = (const float*)d_in[9];
    const float* b3  = (const float*)d_in[10];
    const int*   mid = (const int*)d_in[11];
    const int*   aid = (const int*)d_in[12];
    const int*   did = (const int*)d_in[13];
    const int*   gid = (const int*)d_in[14];
    const int*   sid = (const int*)d_in[15];

    int N = in_sizes[0] / GI;
    if (N > NMAX) N = NMAX;
    int P = in_sizes[11];
    if (P > PMAX) P = PMAX;
    float* out = (float*)d_out;

    prep_wtiles<<<NCH2, 256>>>(W1);
    prep_w2<<<5, 256>>>(W2);
    prep_tabs<<<1, CPAD>>>(de, ge, se, W1, b1);

    cudaFuncSetAttribute(gemm_ab_pipe, cudaFuncAttributeMaxDynamicSharedMemorySize, T1_SMEM);
    gemm_ab_pipe<<<(N + 63) / 64, 256, T1_SMEM>>>(g_i, N);

    cudaFuncSetAttribute(bilinear_fused, cudaFuncAttributeMaxDynamicSharedMemorySize, F_SMEM);
    bilinear_fused<<<(P + 127) / 128, 256, F_SMEM>>>(ms, b2, W3, b3,
                                                     mid, aid, did, gid, sid, out, P);
}